// round 1
// baseline (speedup 1.0000x reference)
#include <cuda_runtime.h>
#include <math.h>

// Problem dims
#define Bb   16
#define Ss   512
#define Dd   768
#define Hh   8
#define Vv   100
#define Ff   2048
#define Ll   6
#define DHd  96
#define Mm   (Bb*Ss)   // 8192

// ---------------- device scratch (no allocs allowed) ----------------
__device__ float g_x   [Mm * Dd];        // activations [8192,768]
__device__ float g_buf [Mm * 3 * Dd];    // qkv [8192,2304] / ffn hidden [8192,2048]
__device__ float g_attn[Mm * Dd];        // attention output (pre O-proj)
__device__ float g_y   [Mm * Dd];        // branch output for residual
__device__ float g_cat [Bb * Dd];        // cross-attn v_const
__device__ float g_ca  [Bb * Dd];        // cross-attn final per-batch vector

// ---------------- embed: x = tok_emb[target] + pos_emb ----------------
__global__ __launch_bounds__(256) void embed_kernel(
    const int* __restrict__ target, const float* __restrict__ tok,
    const float* __restrict__ pos, float* __restrict__ x)
{
    int row = blockIdx.x;          // b*S + s
    int s   = row & (Ss - 1);
    int t   = target[row];
    const float* tp = tok + (size_t)t * Dd;
    const float* pp = pos + (size_t)s * Dd;
    float* xp = x + (size_t)row * Dd;
    for (int c = threadIdx.x; c < Dd; c += 256)
        xp[c] = tp[c] + pp[c];
}

// ---------------- GEMM: C[M,N] = A[M,K] @ W[N,K]^T + bias, opt ReLU ----------------
// 128x128 tile, BK=16, 256 threads, 8x8 per-thread microtile.
__global__ __launch_bounds__(256) void gemm128(
    const float* __restrict__ A, const float* __restrict__ W,
    const float* __restrict__ bias, float* __restrict__ C,
    int M, int N, int K, int relu)
{
    __shared__ float As[16][128];
    __shared__ float Ws[16][128];
    const int tid = threadIdx.x;
    const int bm  = blockIdx.y * 128;
    const int bn  = blockIdx.x * 128;
    const int lk  = (tid & 3) * 4;   // k offset (float4)
    const int lr  = tid >> 2;        // 0..63
    const int tx  = tid & 15;
    const int ty  = tid >> 4;

    float acc[8][8];
    #pragma unroll
    for (int i = 0; i < 8; ++i)
        #pragma unroll
        for (int j = 0; j < 8; ++j) acc[i][j] = 0.f;

    for (int k0 = 0; k0 < K; k0 += 16) {
        #pragma unroll
        for (int p = 0; p < 2; ++p) {
            int r = lr + p * 64;
            float4 va = *(const float4*)&A[(size_t)(bm + r) * K + k0 + lk];
            As[lk + 0][r] = va.x; As[lk + 1][r] = va.y;
            As[lk + 2][r] = va.z; As[lk + 3][r] = va.w;
            int rn = bn + r;
            float4 vw = make_float4(0.f, 0.f, 0.f, 0.f);
            if (rn < N) vw = *(const float4*)&W[(size_t)rn * K + k0 + lk];
            Ws[lk + 0][r] = vw.x; Ws[lk + 1][r] = vw.y;
            Ws[lk + 2][r] = vw.z; Ws[lk + 3][r] = vw.w;
        }
        __syncthreads();
        #pragma unroll
        for (int kk = 0; kk < 16; ++kk) {
            float a[8], w[8];
            *(float4*)&a[0] = *(const float4*)&As[kk][ty * 8];
            *(float4*)&a[4] = *(const float4*)&As[kk][ty * 8 + 4];
            *(float4*)&w[0] = *(const float4*)&Ws[kk][tx * 8];
            *(float4*)&w[4] = *(const float4*)&Ws[kk][tx * 8 + 4];
            #pragma unroll
            for (int i = 0; i < 8; ++i)
                #pragma unroll
                for (int j = 0; j < 8; ++j)
                    acc[i][j] = fmaf(a[i], w[j], acc[i][j]);
        }
        __syncthreads();
    }

    float bs[8];
    #pragma unroll
    for (int j = 0; j < 8; ++j) {
        int n = bn + tx * 8 + j;
        bs[j] = (n < N) ? bias[n] : 0.f;
    }
    #pragma unroll
    for (int i = 0; i < 8; ++i) {
        size_t base = (size_t)(bm + ty * 8 + i) * N;
        #pragma unroll
        for (int j = 0; j < 8; ++j) {
            int n = bn + tx * 8 + j;
            if (n < N) {
                float t = acc[i][j] + bs[j];
                if (relu) t = fmaxf(t, 0.f);
                C[base + n] = t;
            }
        }
    }
}

// ---------------- tiny GEMM for cross-attn shortcut: warp per output ----------------
__global__ __launch_bounds__(256) void small_gemm(
    const float* __restrict__ A, const float* __restrict__ W,
    const float* __restrict__ bias, float* __restrict__ C,
    int Bq, int N, int K)
{
    int wg   = (blockIdx.x * blockDim.x + threadIdx.x) >> 5;
    int lane = threadIdx.x & 31;
    if (wg >= Bq * N) return;
    int bq = wg / N, n = wg - bq * N;
    const float* a = A + (size_t)bq * K;
    const float* w = W + (size_t)n * K;
    float s = 0.f;
    for (int k = lane; k < K; k += 32) s = fmaf(a[k], w[k], s);
    #pragma unroll
    for (int o = 16; o; o >>= 1) s += __shfl_xor_sync(0xffffffffu, s, o);
    if (lane == 0) C[wg] = s + bias[n];
}

// ---------------- fused residual-add + LayerNorm (in-place on x) ----------------
__global__ __launch_bounds__(256) void add_ln_kernel(
    float* __restrict__ x, const float* __restrict__ br,
    const float* __restrict__ g, const float* __restrict__ b, int bcast)
{
    int row = blockIdx.x;
    const float* brp = br + (size_t)(bcast ? (row >> 9) : row) * Dd;
    float* xp = x + (size_t)row * Dd;
    int tid = threadIdx.x;

    float v[3];
    float sum = 0.f, sq = 0.f;
    #pragma unroll
    for (int i = 0; i < 3; ++i) {
        int c = tid + i * 256;
        float t = xp[c] + brp[c];
        v[i] = t; sum += t; sq = fmaf(t, t, sq);
    }
    // block reduce (8 warps)
    #pragma unroll
    for (int o = 16; o; o >>= 1) {
        sum += __shfl_xor_sync(0xffffffffu, sum, o);
        sq  += __shfl_xor_sync(0xffffffffu, sq,  o);
    }
    __shared__ float sh1[8], sh2[8];
    int warp = tid >> 5, lane = tid & 31;
    if (lane == 0) { sh1[warp] = sum; sh2[warp] = sq; }
    __syncthreads();
    if (tid == 0) {
        float a = 0.f, c2 = 0.f;
        #pragma unroll
        for (int i = 0; i < 8; ++i) { a += sh1[i]; c2 += sh2[i]; }
        sh1[0] = a; sh2[0] = c2;
    }
    __syncthreads();
    float mu  = sh1[0] * (1.f / Dd);
    float var = sh2[0] * (1.f / Dd) - mu * mu;
    float rs  = rsqrtf(var + 1e-5f);
    #pragma unroll
    for (int i = 0; i < 3; ++i) {
        int c = tid + i * 256;
        xp[c] = (v[i] - mu) * rs * g[c] + b[c];
    }
}

// ---------------- causal self-attention, block = (b, h, 16 q rows) ----------------
__global__ __launch_bounds__(256) void attn_kernel(
    const float* __restrict__ qkv, float* __restrict__ out)
{
    __shared__ float sQ[16][97];
    __shared__ float sK[16][97];
    __shared__ float sS[16][Ss];
    const int qb  = blockIdx.x * 16;
    const int h   = blockIdx.y;
    const int b   = blockIdx.z;
    const int tid = threadIdx.x;
    const float scale = rsqrtf((float)DHd);

    for (int e = tid; e < 16 * DHd; e += 256) {
        int r = e / DHd, d = e - r * DHd;
        sQ[r][d] = qkv[(size_t)(b * Ss + qb + r) * (3 * Dd) + h * DHd + d];
    }
    __syncthreads();

    const int r = tid >> 4, c = tid & 15;
    for (int jt = 0; jt < Ss; jt += 16) {
        for (int e = tid; e < 16 * DHd; e += 256) {
            int rr = e / DHd, d = e - rr * DHd;
            sK[rr][d] = qkv[(size_t)(b * Ss + jt + rr) * (3 * Dd) + Dd + h * DHd + d];
        }
        __syncthreads();
        float a0 = 0.f, a1 = 0.f;
        #pragma unroll
        for (int d = 0; d < DHd; d += 2) {
            a0 = fmaf(sQ[r][d],     sK[c][d],     a0);
            a1 = fmaf(sQ[r][d + 1], sK[c][d + 1], a1);
        }
        int j = jt + c;
        sS[r][j] = (j <= qb + r) ? (a0 + a1) * scale : -1e9f;
        __syncthreads();
    }

    // softmax per row: warp handles rows {warp, warp+8}
    const int warp = tid >> 5, lane = tid & 31;
    for (int rr = warp; rr < 16; rr += 8) {
        float mx = -1e30f;
        for (int j = lane; j < Ss; j += 32) mx = fmaxf(mx, sS[rr][j]);
        #pragma unroll
        for (int o = 16; o; o >>= 1) mx = fmaxf(mx, __shfl_xor_sync(0xffffffffu, mx, o));
        float sum = 0.f;
        for (int j = lane; j < Ss; j += 32) {
            float e = __expf(sS[rr][j] - mx);
            sS[rr][j] = e; sum += e;
        }
        #pragma unroll
        for (int o = 16; o; o >>= 1) sum += __shfl_xor_sync(0xffffffffu, sum, o);
        float inv = 1.f / sum;
        for (int j = lane; j < Ss; j += 32) sS[rr][j] *= inv;
    }
    __syncthreads();

    // out = P @ V
    for (int e = tid; e < 16 * DHd; e += 256) {
        int rr = e / DHd, d = e - rr * DHd;
        const float* vp = qkv + (size_t)(b * Ss) * (3 * Dd) + 2 * Dd + h * DHd + d;
        float a0 = 0.f, a1 = 0.f, a2 = 0.f, a3 = 0.f;
        #pragma unroll 2
        for (int j = 0; j < Ss; j += 4) {
            a0 = fmaf(sS[rr][j],     vp[(size_t)(j)     * (3 * Dd)], a0);
            a1 = fmaf(sS[rr][j + 1], vp[(size_t)(j + 1) * (3 * Dd)], a1);
            a2 = fmaf(sS[rr][j + 2], vp[(size_t)(j + 2) * (3 * Dd)], a2);
            a3 = fmaf(sS[rr][j + 3], vp[(size_t)(j + 3) * (3 * Dd)], a3);
        }
        out[(size_t)(b * Ss + qb + rr) * Dd + h * DHd + d] = (a0 + a1) + (a2 + a3);
    }
}

// ---------------- launcher ----------------
extern "C" void kernel_launch(void* const* d_in, const int* in_sizes, int n_in,
                              void* d_out, int out_size)
{
    (void)in_sizes; (void)n_in; (void)out_size;
    const float* latent   = (const float*)d_in[0];
    const int*   target   = (const int*)  d_in[1];
    const float* tok_emb  = (const float*)d_in[2];
    const float* pos_emb  = (const float*)d_in[3];
    const float* sa_w_qkv = (const float*)d_in[4];
    const float* sa_b_qkv = (const float*)d_in[5];
    const float* sa_w_o   = (const float*)d_in[6];
    const float* sa_b_o   = (const float*)d_in[7];
    const float* ca_w_qkv = (const float*)d_in[8];
    const float* ca_b_qkv = (const float*)d_in[9];
    const float* ca_w_o   = (const float*)d_in[10];
    const float* ca_b_o   = (const float*)d_in[11];
    const float* ffn_w1   = (const float*)d_in[12];
    const float* ffn_b1   = (const float*)d_in[13];
    const float* ffn_w2   = (const float*)d_in[14];
    const float* ffn_b2   = (const float*)d_in[15];
    const float* ln1_g    = (const float*)d_in[16];
    const float* ln1_b    = (const float*)d_in[17];
    const float* ln2_g    = (const float*)d_in[18];
    const float* ln2_b    = (const float*)d_in[19];
    const float* ln3_g    = (const float*)d_in[20];
    const float* ln3_b    = (const float*)d_in[21];
    const float* out_w    = (const float*)d_in[22];
    const float* out_b    = (const float*)d_in[23];

    float *x, *buf, *attn, *y, *cat, *ca;
    cudaGetSymbolAddress((void**)&x,    g_x);
    cudaGetSymbolAddress((void**)&buf,  g_buf);
    cudaGetSymbolAddress((void**)&attn, g_attn);
    cudaGetSymbolAddress((void**)&y,    g_y);
    cudaGetSymbolAddress((void**)&cat,  g_cat);
    cudaGetSymbolAddress((void**)&ca,   g_ca);

    embed_kernel<<<Mm, 256>>>(target, tok_emb, pos_emb, x);

    for (int l = 0; l < Ll; ++l) {
        // ---- self-attention ----
        gemm128<<<dim3(18, 64), 256>>>(x, sa_w_qkv + (size_t)l * 3 * Dd * Dd,
                                       sa_b_qkv + (size_t)l * 3 * Dd, buf,
                                       Mm, 3 * Dd, Dd, 0);
        attn_kernel<<<dim3(Ss / 16, Hh, Bb), 256>>>(buf, attn);
        gemm128<<<dim3(6, 64), 256>>>(attn, sa_w_o + (size_t)l * Dd * Dd,
                                      sa_b_o + (size_t)l * Dd, y,
                                      Mm, Dd, Dd, 0);
        add_ln_kernel<<<Mm, 256>>>(x, y, ln1_g + (size_t)l * Dd, ln1_b + (size_t)l * Dd, 0);

        // ---- cross-attention (analytic: uniform softmax over identical keys) ----
        small_gemm<<<(Bb * Dd * 32 + 255) / 256, 256>>>(
            latent, ca_w_qkv + (size_t)l * 3 * Dd * Dd + (size_t)2 * Dd * Dd,
            ca_b_qkv + (size_t)l * 3 * Dd + 2 * Dd, cat, Bb, Dd, Dd);
        small_gemm<<<(Bb * Dd * 32 + 255) / 256, 256>>>(
            cat, ca_w_o + (size_t)l * Dd * Dd,
            ca_b_o + (size_t)l * Dd, ca, Bb, Dd, Dd);
        add_ln_kernel<<<Mm, 256>>>(x, ca, ln2_g + (size_t)l * Dd, ln2_b + (size_t)l * Dd, 1);

        // ---- FFN ----
        gemm128<<<dim3(16, 64), 256>>>(x, ffn_w1 + (size_t)l * Ff * Dd,
                                       ffn_b1 + (size_t)l * Ff, buf,
                                       Mm, Ff, Dd, 1);
        gemm128<<<dim3(6, 64), 256>>>(buf, ffn_w2 + (size_t)l * Dd * Ff,
                                      ffn_b2 + (size_t)l * Dd, y,
                                      Mm, Dd, Ff, 0);
        add_ln_kernel<<<Mm, 256>>>(x, y, ln3_g + (size_t)l * Dd, ln3_b + (size_t)l * Dd, 0);
    }

    // ---- output projection ----
    gemm128<<<dim3(1, 64), 256>>>(x, out_w, out_b, (float*)d_out, Mm, Vv, Dd, 0);
}

// round 3
// speedup vs baseline: 2.0053x; 2.0053x over previous
#include <cuda_runtime.h>
#include <cuda_bf16.h>
#include <stdint.h>
#include <math.h>

// Problem dims
#define Bb   16
#define Ss   512
#define Dd   768
#define Hh   8
#define Vv   100
#define Ff   2048
#define Ll   6
#define DHd  96
#define Mm   (Bb*Ss)   // 8192

// ================= low-level helpers (plain sm_103-safe PTX only) =================
__device__ __forceinline__ uint32_t smem_u32(const void* p) {
    return (uint32_t)__cvta_generic_to_shared(p);
}
__device__ __forceinline__ void cp_async16(uint32_t dst, const void* src, int szvalid) {
    asm volatile("cp.async.cg.shared.global [%0], [%1], 16, %2;"
                 :: "r"(dst), "l"(src), "r"(szvalid) : "memory");
}
#define CP_COMMIT() asm volatile("cp.async.commit_group;" ::: "memory")
#define CP_WAIT(n)  asm volatile("cp.async.wait_group %0;" :: "n"(n) : "memory")

__device__ __forceinline__ void ldm_x4(uint32_t* r, uint32_t addr) {
    asm volatile("ldmatrix.sync.aligned.m8n8.x4.shared.b16 {%0,%1,%2,%3}, [%4];"
                 : "=r"(r[0]), "=r"(r[1]), "=r"(r[2]), "=r"(r[3]) : "r"(addr));
}
__device__ __forceinline__ void mma16816(float* d, const uint32_t* a, const uint32_t* b) {
    asm volatile("mma.sync.aligned.m16n8k16.row.col.f32.bf16.bf16.f32 "
                 "{%0,%1,%2,%3}, {%4,%5,%6,%7}, {%8,%9}, {%0,%1,%2,%3};"
                 : "+f"(d[0]), "+f"(d[1]), "+f"(d[2]), "+f"(d[3])
                 : "r"(a[0]), "r"(a[1]), "r"(a[2]), "r"(a[3]), "r"(b[0]), "r"(b[1]));
}

// ================= device scratch (no allocs allowed) =================
__device__ float g_x   [Mm * Dd];
__device__ float g_buf [Mm * 3 * Dd];    // qkv output (fp32 for attention)
__device__ float g_y   [Mm * Dd];        // branch output for residual
__device__ float g_cat [Bb * Dd];
__device__ float g_ca  [Bb * Dd];

// activation splits (16B aligned for cp.async / vector loads)
__device__ __align__(16) __nv_bfloat16 g_xh[Mm * Dd],  g_xl[Mm * Dd];
__device__ __align__(16) __nv_bfloat16 g_oh[Mm * Dd],  g_ol[Mm * Dd];
__device__ __align__(16) __nv_bfloat16 g_hh[Mm * Ff],  g_hl[Mm * Ff];

// weight splits
__device__ __align__(16) __nv_bfloat16 g_wqkvh[Ll*3*Dd*Dd], g_wqkvl[Ll*3*Dd*Dd];
__device__ __align__(16) __nv_bfloat16 g_woh  [Ll*Dd*Dd],   g_wol  [Ll*Dd*Dd];
__device__ __align__(16) __nv_bfloat16 g_w1h  [Ll*Ff*Dd],   g_w1l  [Ll*Ff*Dd];
__device__ __align__(16) __nv_bfloat16 g_w2h  [Ll*Dd*Ff],   g_w2l  [Ll*Dd*Ff];
__device__ __align__(16) __nv_bfloat16 g_wouth[Vv*Dd],      g_woutl[Vv*Dd];

__device__ __forceinline__ void split1(float v, __nv_bfloat16& h, __nv_bfloat16& l) {
    h = __float2bfloat16(v);
    l = __float2bfloat16(v - __bfloat162float(h));
}

// ================= weight split kernel =================
__global__ __launch_bounds__(256) void split_kernel(
    const float* __restrict__ in, __nv_bfloat16* __restrict__ hi,
    __nv_bfloat16* __restrict__ lo, int n)
{
    int i = (blockIdx.x * 256 + threadIdx.x) * 4;
    if (i >= n) return;
    float4 v = *(const float4*)&in[i];
    __nv_bfloat16 h0, l0, h1, l1, h2, l2, h3, l3;
    split1(v.x, h0, l0); split1(v.y, h1, l1);
    split1(v.z, h2, l2); split1(v.w, h3, l3);
    hi[i] = h0; hi[i+1] = h1; hi[i+2] = h2; hi[i+3] = h3;
    lo[i] = l0; lo[i+1] = l1; lo[i+2] = l2; lo[i+3] = l3;
}

// ================= embed (+split) =================
__global__ __launch_bounds__(256) void embed_kernel(
    const int* __restrict__ target, const float* __restrict__ tok,
    const float* __restrict__ pos, float* __restrict__ x,
    __nv_bfloat16* __restrict__ xh, __nv_bfloat16* __restrict__ xl)
{
    int row = blockIdx.x;
    int s   = row & (Ss - 1);
    int t   = target[row];
    const float* tp = tok + (size_t)t * Dd;
    const float* pp = pos + (size_t)s * Dd;
    size_t base = (size_t)row * Dd;
    for (int c = threadIdx.x; c < Dd; c += 256) {
        float v = tp[c] + pp[c];
        x[base + c] = v;
        __nv_bfloat16 h, l; split1(v, h, l);
        xh[base + c] = h; xl[base + c] = l;
    }
}

// ================= mma.sync GEMM: C[M,N] = A[M,K] @ W[N,K]^T + bias =================
// split-bf16: C = Ah.Wh + Ah.Wl + Al.Wh, fp32 accumulation in registers.
// 128x128 CTA tile, BK=32, cp.async double buffer.
// mode 0: fp32 out + bias.  mode 1: relu + bf16 split out (Ch/Cl).
#define BKc 32
#define SA_ELEM 40                       // padded row stride (elems)
#define SA_B    (SA_ELEM*2)              // 80 bytes
#define TILE_B  (128*SA_B)               // 10240 B per tile
#define STAGE_B (4*TILE_B)               // 40960 B per stage
#define GEMM_SMEM (2*STAGE_B)            // 81920 B

__global__ void __launch_bounds__(256) gemm_mma(
    const __nv_bfloat16* __restrict__ Ah, const __nv_bfloat16* __restrict__ Al,
    const __nv_bfloat16* __restrict__ Wh, const __nv_bfloat16* __restrict__ Wl,
    const float* __restrict__ bias, float* __restrict__ C,
    __nv_bfloat16* __restrict__ Ch, __nv_bfloat16* __restrict__ Cl,
    int M, int N, int K, int mode)
{
    extern __shared__ char sm[];
    const uint32_t smU = smem_u32(sm);
    const int tid  = threadIdx.x;
    const int lane = tid & 31;
    const int wid  = tid >> 5;
    const int bm   = blockIdx.y * 128;
    const int bn   = blockIdx.x * 128;
    const int wm   = (wid >> 2) * 64;       // warp row base within tile
    const int wn   = (wid & 3) * 32;        // warp col base within tile

    float acc[4][4][4];
    #pragma unroll
    for (int i = 0; i < 4; ++i)
        #pragma unroll
        for (int j = 0; j < 4; ++j)
            #pragma unroll
            for (int r = 0; r < 4; ++r) acc[i][j][r] = 0.f;

    const int NC = K / BKc;

    // ---- async load of one BK chunk into stage s ----
    auto issue = [&](int chunk, int s) {
        const int k0 = chunk * BKc;
        #pragma unroll
        for (int t = 0; t < 4; ++t) {
            const __nv_bfloat16* src = (t == 0) ? Ah : (t == 1) ? Al : (t == 2) ? Wh : Wl;
            const uint32_t base = smU + s * STAGE_B + t * TILE_B;
            #pragma unroll
            for (int i = 0; i < 2; ++i) {
                int id  = tid * 2 + i;          // 0..511
                int row = id >> 2;
                int c16 = id & 3;
                uint32_t dst = base + row * SA_B + c16 * 16;
                int sz = 16;
                const char* g;
                if (t < 2) {
                    g = (const char*)(src + (size_t)(bm + row) * K + k0) + c16 * 16;
                } else {
                    int rn = bn + row;
                    g = (const char*)(src + (size_t)rn * K + k0) + c16 * 16;
                    if (rn >= N) { sz = 0; g = (const char*)src; }
                }
                cp_async16(dst, g, sz);
            }
        }
        CP_COMMIT();
    };

    // per-lane ldmatrix offsets
    const int wrow_off = ((lane >> 4) << 3) + (lane & 7);  // W: n offset within 16
    const int wcol_off = ((lane >> 3) & 1) * 8;            // W: k offset within 16
    const int arow_off = lane & 15;                         // A: m offset within 16
    const int acol_off = (lane >> 4) << 3;                  // A: k offset within 16

    auto compute = [&](int s) {
        const uint32_t aBh = smU + s * STAGE_B;
        const uint32_t aBl = aBh + TILE_B;
        const uint32_t wBh = aBh + 2 * TILE_B;
        const uint32_t wBl = aBh + 3 * TILE_B;
        #pragma unroll
        for (int ks = 0; ks < BKc; ks += 16) {
            uint32_t wh[8], wl[8];
            #pragma unroll
            for (int nb = 0; nb < 2; ++nb) {
                int nrow = wn + nb * 16 + wrow_off;
                uint32_t off = nrow * SA_B + (ks + wcol_off) * 2;
                ldm_x4(&wh[nb * 4], wBh + off);
                ldm_x4(&wl[nb * 4], wBl + off);
            }
            #pragma unroll
            for (int mi = 0; mi < 4; ++mi) {
                int arow = wm + mi * 16 + arow_off;
                uint32_t off = arow * SA_B + (ks + acol_off) * 2;
                uint32_t ah[4], al[4];
                ldm_x4(ah, aBh + off);
                ldm_x4(al, aBl + off);
                #pragma unroll
                for (int nj = 0; nj < 4; ++nj) {
                    float* d = &acc[mi][nj][0];
                    mma16816(d, ah, &wh[nj * 2]);
                    mma16816(d, ah, &wl[nj * 2]);
                    mma16816(d, al, &wh[nj * 2]);
                }
            }
        }
    };

    issue(0, 0);
    for (int c = 0; c < NC; ++c) {
        if (c + 1 < NC) {
            issue(c + 1, (c + 1) & 1);
            CP_WAIT(1);
        } else {
            CP_WAIT(0);
        }
        __syncthreads();
        compute(c & 1);
        __syncthreads();
    }

    // ---- epilogue ----
    #pragma unroll
    for (int mi = 0; mi < 4; ++mi) {
        #pragma unroll
        for (int nj = 0; nj < 4; ++nj) {
            int row0 = bm + wm + mi * 16 + (lane >> 2);
            int col0 = bn + wn + nj * 8 + (lane & 3) * 2;
            #pragma unroll
            for (int r = 0; r < 4; ++r) {
                int row = row0 + ((r >> 1) ? 8 : 0);
                int col = col0 + (r & 1);
                if (col < N) {
                    float t = acc[mi][nj][r] + bias[col];
                    if (mode == 0) {
                        C[(size_t)row * N + col] = t;
                    } else {
                        t = fmaxf(t, 0.f);
                        __nv_bfloat16 h, l; split1(t, h, l);
                        Ch[(size_t)row * N + col] = h;
                        Cl[(size_t)row * N + col] = l;
                    }
                }
            }
        }
    }
}

// ================= tiny GEMM for cross-attn shortcut =================
__global__ __launch_bounds__(256) void small_gemm(
    const float* __restrict__ A, const float* __restrict__ W,
    const float* __restrict__ bias, float* __restrict__ C,
    int Bq, int N, int K)
{
    int wg   = (blockIdx.x * blockDim.x + threadIdx.x) >> 5;
    int lane = threadIdx.x & 31;
    if (wg >= Bq * N) return;
    int bq = wg / N, n = wg - bq * N;
    const float* a = A + (size_t)bq * K;
    const float* w = W + (size_t)n * K;
    float s = 0.f;
    for (int k = lane; k < K; k += 32) s = fmaf(a[k], w[k], s);
    #pragma unroll
    for (int o = 16; o; o >>= 1) s += __shfl_xor_sync(0xffffffffu, s, o);
    if (lane == 0) C[wg] = s + bias[n];
}

// ================= fused residual-add + LayerNorm (+opt split) =================
__global__ __launch_bounds__(256) void add_ln_kernel(
    float* __restrict__ x, const float* __restrict__ br,
    const float* __restrict__ g, const float* __restrict__ b, int bcast,
    __nv_bfloat16* __restrict__ xh, __nv_bfloat16* __restrict__ xl)
{
    int row = blockIdx.x;
    const float* brp = br + (size_t)(bcast ? (row >> 9) : row) * Dd;
    float* xp = x + (size_t)row * Dd;
    int tid = threadIdx.x;

    float v[3];
    float sum = 0.f, sq = 0.f;
    #pragma unroll
    for (int i = 0; i < 3; ++i) {
        int c = tid + i * 256;
        float t = xp[c] + brp[c];
        v[i] = t; sum += t; sq = fmaf(t, t, sq);
    }
    #pragma unroll
    for (int o = 16; o; o >>= 1) {
        sum += __shfl_xor_sync(0xffffffffu, sum, o);
        sq  += __shfl_xor_sync(0xffffffffu, sq,  o);
    }
    __shared__ float sh1[8], sh2[8];
    int warp = tid >> 5, lane = tid & 31;
    if (lane == 0) { sh1[warp] = sum; sh2[warp] = sq; }
    __syncthreads();
    if (tid == 0) {
        float a = 0.f, c2 = 0.f;
        #pragma unroll
        for (int i = 0; i < 8; ++i) { a += sh1[i]; c2 += sh2[i]; }
        sh1[0] = a; sh2[0] = c2;
    }
    __syncthreads();
    float mu  = sh1[0] * (1.f / Dd);
    float var = sh2[0] * (1.f / Dd) - mu * mu;
    float rs  = rsqrtf(var + 1e-5f);
    #pragma unroll
    for (int i = 0; i < 3; ++i) {
        int c = tid + i * 256;
        float o = (v[i] - mu) * rs * g[c] + b[c];
        xp[c] = o;
        if (xh) {
            __nv_bfloat16 h, l; split1(o, h, l);
            xh[(size_t)row * Dd + c] = h;
            xl[(size_t)row * Dd + c] = l;
        }
    }
}

// ================= causal self-attention (smem V tiles + causal skip) =================
__global__ __launch_bounds__(256) void attn_kernel(
    const float* __restrict__ qkv,
    __nv_bfloat16* __restrict__ oh, __nv_bfloat16* __restrict__ ol)
{
    __shared__ float sQ[16][97];
    __shared__ float sK[16][97];       // reused as V tile in PV phase
    __shared__ float sS[16][Ss];
    const int qb  = blockIdx.x * 16;
    const int h   = blockIdx.y;
    const int b   = blockIdx.z;
    const int tid = threadIdx.x;
    const float scale = rsqrtf((float)DHd);
    const int jmax = qb + 16;          // causal: keys beyond qb+15 are masked for all rows

    for (int e = tid; e < 16 * DHd; e += 256) {
        int r = e / DHd, d = e - r * DHd;
        sQ[r][d] = qkv[(size_t)(b * Ss + qb + r) * (3 * Dd) + h * DHd + d];
    }
    __syncthreads();

    // ---- scores for tiles jt < jmax ----
    const int r = tid >> 4, c = tid & 15;
    for (int jt = 0; jt < jmax; jt += 16) {
        for (int e = tid; e < 16 * DHd; e += 256) {
            int rr = e / DHd, d = e - rr * DHd;
            sK[rr][d] = qkv[(size_t)(b * Ss + jt + rr) * (3 * Dd) + Dd + h * DHd + d];
        }
        __syncthreads();
        float a0 = 0.f, a1 = 0.f;
        #pragma unroll
        for (int d = 0; d < DHd; d += 2) {
            a0 = fmaf(sQ[r][d],     sK[c][d],     a0);
            a1 = fmaf(sQ[r][d + 1], sK[c][d + 1], a1);
        }
        int j = jt + c;
        sS[r][j] = (j <= qb + r) ? (a0 + a1) * scale : -1e9f;
        __syncthreads();
    }

    // ---- softmax over j < jmax ----
    const int warp = tid >> 5, lane = tid & 31;
    for (int rr = warp; rr < 16; rr += 8) {
        float mx = -1e30f;
        for (int j = lane; j < jmax; j += 32) mx = fmaxf(mx, sS[rr][j]);
        #pragma unroll
        for (int o = 16; o; o >>= 1) mx = fmaxf(mx, __shfl_xor_sync(0xffffffffu, mx, o));
        float sum = 0.f;
        for (int j = lane; j < jmax; j += 32) {
            float e = __expf(sS[rr][j] - mx);
            sS[rr][j] = e; sum += e;
        }
        #pragma unroll
        for (int o = 16; o; o >>= 1) sum += __shfl_xor_sync(0xffffffffu, sum, o);
        float inv = 1.f / sum;
        for (int j = lane; j < jmax; j += 32) sS[rr][j] *= inv;
    }
    __syncthreads();

    // ---- PV with V tiles staged in smem (reuse sK) ----
    const int rr2 = tid >> 4;          // q row 0..15
    const int dg  = (tid & 15) * 6;    // this thread's 6 d's
    float o6[6] = {0.f, 0.f, 0.f, 0.f, 0.f, 0.f};
    for (int jt = 0; jt < jmax; jt += 16) {
        for (int e = tid; e < 16 * DHd; e += 256) {
            int rr = e / DHd, d = e - rr * DHd;
            sK[rr][d] = qkv[(size_t)(b * Ss + jt + rr) * (3 * Dd) + 2 * Dd + h * DHd + d];
        }
        __syncthreads();
        #pragma unroll
        for (int j = 0; j < 16; ++j) {
            float p = sS[rr2][jt + j];
            #pragma unroll
            for (int q = 0; q < 6; ++q)
                o6[q] = fmaf(p, sK[j][dg + q], o6[q]);
        }
        __syncthreads();
    }

    size_t oi = (size_t)(b * Ss + qb + rr2) * Dd + h * DHd + dg;
    #pragma unroll
    for (int q = 0; q < 6; ++q) {
        __nv_bfloat16 hh, ll; split1(o6[q], hh, ll);
        oh[oi + q] = hh; ol[oi + q] = ll;
    }
}

// ================= launcher =================
extern "C" void kernel_launch(void* const* d_in, const int* in_sizes, int n_in,
                              void* d_out, int out_size)
{
    (void)in_sizes; (void)n_in; (void)out_size;
    const float* latent   = (const float*)d_in[0];
    const int*   target   = (const int*)  d_in[1];
    const float* tok_emb  = (const float*)d_in[2];
    const float* pos_emb  = (const float*)d_in[3];
    const float* sa_w_qkv = (const float*)d_in[4];
    const float* sa_b_qkv = (const float*)d_in[5];
    const float* sa_w_o   = (const float*)d_in[6];
    const float* sa_b_o   = (const float*)d_in[7];
    const float* ca_w_qkv = (const float*)d_in[8];
    const float* ca_b_qkv = (const float*)d_in[9];
    const float* ca_w_o   = (const float*)d_in[10];
    const float* ca_b_o   = (const float*)d_in[11];
    const float* ffn_w1   = (const float*)d_in[12];
    const float* ffn_b1   = (const float*)d_in[13];
    const float* ffn_w2   = (const float*)d_in[14];
    const float* ffn_b2   = (const float*)d_in[15];
    const float* ln1_g    = (const float*)d_in[16];
    const float* ln1_b    = (const float*)d_in[17];
    const float* ln2_g    = (const float*)d_in[18];
    const float* ln2_b    = (const float*)d_in[19];
    const float* ln3_g    = (const float*)d_in[20];
    const float* ln3_b    = (const float*)d_in[21];
    const float* out_w    = (const float*)d_in[22];
    const float* out_b    = (const float*)d_in[23];

    float *x, *buf, *y, *cat, *ca;
    __nv_bfloat16 *xh, *xl, *oh, *ol, *hh, *hl;
    __nv_bfloat16 *wqkvh, *wqkvl, *woh, *wol, *w1h, *w1l, *w2h, *w2l, *wouth, *woutl;
    cudaGetSymbolAddress((void**)&x,   g_x);
    cudaGetSymbolAddress((void**)&buf, g_buf);
    cudaGetSymbolAddress((void**)&y,   g_y);
    cudaGetSymbolAddress((void**)&cat, g_cat);
    cudaGetSymbolAddress((void**)&ca,  g_ca);
    cudaGetSymbolAddress((void**)&xh,  g_xh);  cudaGetSymbolAddress((void**)&xl, g_xl);
    cudaGetSymbolAddress((void**)&oh,  g_oh);  cudaGetSymbolAddress((void**)&ol, g_ol);
    cudaGetSymbolAddress((void**)&hh,  g_hh);  cudaGetSymbolAddress((void**)&hl, g_hl);
    cudaGetSymbolAddress((void**)&wqkvh, g_wqkvh); cudaGetSymbolAddress((void**)&wqkvl, g_wqkvl);
    cudaGetSymbolAddress((void**)&woh,   g_woh);   cudaGetSymbolAddress((void**)&wol,   g_wol);
    cudaGetSymbolAddress((void**)&w1h,   g_w1h);   cudaGetSymbolAddress((void**)&w1l,   g_w1l);
    cudaGetSymbolAddress((void**)&w2h,   g_w2h);   cudaGetSymbolAddress((void**)&w2l,   g_w2l);
    cudaGetSymbolAddress((void**)&wouth, g_wouth); cudaGetSymbolAddress((void**)&woutl, g_woutl);

    cudaFuncSetAttribute(gemm_mma, cudaFuncAttributeMaxDynamicSharedMemorySize, GEMM_SMEM);

    // weight splits (part of the graph, deterministic)
    {
        int n;
        n = Ll*3*Dd*Dd; split_kernel<<<(n/4 + 255)/256, 256>>>(sa_w_qkv, wqkvh, wqkvl, n);
        n = Ll*Dd*Dd;   split_kernel<<<(n/4 + 255)/256, 256>>>(sa_w_o,   woh,   wol,   n);
        n = Ll*Ff*Dd;   split_kernel<<<(n/4 + 255)/256, 256>>>(ffn_w1,   w1h,   w1l,   n);
        n = Ll*Dd*Ff;   split_kernel<<<(n/4 + 255)/256, 256>>>(ffn_w2,   w2h,   w2l,   n);
        n = Vv*Dd;      split_kernel<<<(n/4 + 255)/256, 256>>>(out_w,    wouth, woutl, n);
    }

    embed_kernel<<<Mm, 256>>>(target, tok_emb, pos_emb, x, xh, xl);

    for (int l = 0; l < Ll; ++l) {
        // ---- self-attention ----
        gemm_mma<<<dim3(18, 64), 256, GEMM_SMEM>>>(
            xh, xl, wqkvh + (size_t)l*3*Dd*Dd, wqkvl + (size_t)l*3*Dd*Dd,
            sa_b_qkv + (size_t)l*3*Dd, buf, nullptr, nullptr, Mm, 3*Dd, Dd, 0);
        attn_kernel<<<dim3(Ss/16, Hh, Bb), 256>>>(buf, oh, ol);
        gemm_mma<<<dim3(6, 64), 256, GEMM_SMEM>>>(
            oh, ol, woh + (size_t)l*Dd*Dd, wol + (size_t)l*Dd*Dd,
            sa_b_o + (size_t)l*Dd, y, nullptr, nullptr, Mm, Dd, Dd, 0);
        add_ln_kernel<<<Mm, 256>>>(x, y, ln1_g + (size_t)l*Dd, ln1_b + (size_t)l*Dd, 0,
                                   nullptr, nullptr);

        // ---- cross-attention (analytic: uniform softmax over identical keys) ----
        small_gemm<<<(Bb * Dd * 32 + 255) / 256, 256>>>(
            latent, ca_w_qkv + (size_t)l*3*Dd*Dd + (size_t)2*Dd*Dd,
            ca_b_qkv + (size_t)l*3*Dd + 2*Dd, cat, Bb, Dd, Dd);
        small_gemm<<<(Bb * Dd * 32 + 255) / 256, 256>>>(
            cat, ca_w_o + (size_t)l*Dd*Dd, ca_b_o + (size_t)l*Dd, ca, Bb, Dd, Dd);
        add_ln_kernel<<<Mm, 256>>>(x, ca, ln2_g + (size_t)l*Dd, ln2_b + (size_t)l*Dd, 1,
                                   xh, xl);

        // ---- FFN ----
        gemm_mma<<<dim3(16, 64), 256, GEMM_SMEM>>>(
            xh, xl, w1h + (size_t)l*Ff*Dd, w1l + (size_t)l*Ff*Dd,
            ffn_b1 + (size_t)l*Ff, nullptr, hh, hl, Mm, Ff, Dd, 1);
        gemm_mma<<<dim3(6, 64), 256, GEMM_SMEM>>>(
            hh, hl, w2h + (size_t)l*Dd*Ff, w2l + (size_t)l*Dd*Ff,
            ffn_b2 + (size_t)l*Dd, y, nullptr, nullptr, Mm, Dd, Ff, 0);
        add_ln_kernel<<<Mm, 256>>>(x, y, ln3_g + (size_t)l*Dd, ln3_b + (size_t)l*Dd, 0,
                                   xh, xl);
    }

    // ---- output projection ----
    gemm_mma<<<dim3(1, 64), 256, GEMM_SMEM>>>(
        xh, xl, wouth, woutl, out_b, (float*)d_out, nullptr, nullptr, Mm, Vv, Dd, 0);
}

// round 4
// speedup vs baseline: 3.0317x; 1.5118x over previous
#include <cuda_runtime.h>
#include <cuda_fp16.h>
#include <stdint.h>
#include <math.h>

// Problem dims
#define Bb   16
#define Ss   512
#define Dd   768
#define Hh   8
#define Vv   100
#define Ff   2048
#define Ll   6
#define DHd  96
#define Mm   (Bb*Ss)   // 8192

// ================= low-level helpers (plain sm_103-safe PTX only) =================
__device__ __forceinline__ uint32_t smem_u32(const void* p) {
    return (uint32_t)__cvta_generic_to_shared(p);
}
__device__ __forceinline__ void cp_async16(uint32_t dst, const void* src, int szvalid) {
    asm volatile("cp.async.cg.shared.global [%0], [%1], 16, %2;"
                 :: "r"(dst), "l"(src), "r"(szvalid) : "memory");
}
#define CP_COMMIT() asm volatile("cp.async.commit_group;" ::: "memory")
#define CP_WAIT(n)  asm volatile("cp.async.wait_group %0;" :: "n"(n) : "memory")

__device__ __forceinline__ void ldm_x4(uint32_t* r, uint32_t addr) {
    asm volatile("ldmatrix.sync.aligned.m8n8.x4.shared.b16 {%0,%1,%2,%3}, [%4];"
                 : "=r"(r[0]), "=r"(r[1]), "=r"(r[2]), "=r"(r[3]) : "r"(addr));
}
__device__ __forceinline__ void mma16816(float* d, const uint32_t* a, const uint32_t* b) {
    asm volatile("mma.sync.aligned.m16n8k16.row.col.f32.f16.f16.f32 "
                 "{%0,%1,%2,%3}, {%4,%5,%6,%7}, {%8,%9}, {%0,%1,%2,%3};"
                 : "+f"(d[0]), "+f"(d[1]), "+f"(d[2]), "+f"(d[3])
                 : "r"(a[0]), "r"(a[1]), "r"(a[2]), "r"(a[3]), "r"(b[0]), "r"(b[1]));
}

// ================= device scratch (no allocs allowed) =================
__device__ float g_x   [Mm * Dd];
__device__ float g_buf [Mm * 3 * Dd];    // qkv output (fp32 for attention)
__device__ float g_y   [Mm * Dd];        // branch output for residual
__device__ float g_cat [Ll * Bb * Dd];   // per-layer cross-attn v_const
__device__ float g_ca  [Ll * Bb * Dd];   // per-layer cross-attn final vector

// fp16 activations
__device__ __align__(16) __half g_x16[Mm * Dd];
__device__ __align__(16) __half g_o16[Mm * Dd];
__device__ __align__(16) __half g_h16[Mm * Ff];

// fp16 weights
__device__ __align__(16) __half g_wqkv16[Ll*3*Dd*Dd];
__device__ __align__(16) __half g_wo16  [Ll*Dd*Dd];
__device__ __align__(16) __half g_w116  [Ll*Ff*Dd];
__device__ __align__(16) __half g_w216  [Ll*Dd*Ff];
__device__ __align__(16) __half g_wout16[Vv*Dd];

// ================= single convert kernel: fp32 -> fp16 for all 5 weight arrays ====
__global__ __launch_bounds__(256) void convert_all(
    const float* __restrict__ s0, __half* __restrict__ d0, int b0,
    const float* __restrict__ s1, __half* __restrict__ d1, int b1,
    const float* __restrict__ s2, __half* __restrict__ d2, int b2,
    const float* __restrict__ s3, __half* __restrict__ d3, int b3,
    const float* __restrict__ s4, __half* __restrict__ d4, int b4)
{
    int bid = blockIdx.x;
    const float* src; __half* dst; int nb;
    if      (bid < b0)                 { src = s0; dst = d0; nb = bid; }
    else if (bid < b0+b1)              { src = s1; dst = d1; nb = bid - b0; }
    else if (bid < b0+b1+b2)           { src = s2; dst = d2; nb = bid - b0 - b1; }
    else if (bid < b0+b1+b2+b3)        { src = s3; dst = d3; nb = bid - b0 - b1 - b2; }
    else                               { src = s4; dst = d4; nb = bid - b0 - b1 - b2 - b3; }
    int i = (nb * 256 + threadIdx.x) * 4;
    float4 v = *(const float4*)&src[i];
    __half2 lo = __floats2half2_rn(v.x, v.y);
    __half2 hi = __floats2half2_rn(v.z, v.w);
    *(__half2*)&dst[i]     = lo;
    *(__half2*)&dst[i + 2] = hi;
}

// ================= embed (+fp16 copy) =================
__global__ __launch_bounds__(256) void embed_kernel(
    const int* __restrict__ target, const float* __restrict__ tok,
    const float* __restrict__ pos, float* __restrict__ x,
    __half* __restrict__ x16)
{
    int row = blockIdx.x;
    int s   = row & (Ss - 1);
    int t   = target[row];
    const float* tp = tok + (size_t)t * Dd;
    const float* pp = pos + (size_t)s * Dd;
    size_t base = (size_t)row * Dd;
    for (int c = threadIdx.x; c < Dd; c += 256) {
        float v = tp[c] + pp[c];
        x[base + c] = v;
        x16[base + c] = __float2half(v);
    }
}

// ================= fp16 mma.sync GEMM: C[M,N] = A[M,K] @ W[N,K]^T + bias ==========
// Single-product fp16, fp32 register accumulation.
// 128x128 CTA tile, BK=32, cp.async double buffer.
// mode 0: fp32 out + bias.  mode 1: relu + fp16 out (Ch).
#define BKc 32
#define SA_ELEM 40                       // padded row stride (elems)
#define SA_B    (SA_ELEM*2)              // 80 bytes
#define TILE_B  (128*SA_B)               // 10240 B per tile
#define STAGE_B (2*TILE_B)               // 20480 B per stage (A + W)
#define GEMM_SMEM (2*STAGE_B)            // 40960 B

__global__ void __launch_bounds__(256, 2) gemm_fp16(
    const __half* __restrict__ A, const __half* __restrict__ W,
    const float* __restrict__ bias, float* __restrict__ C,
    __half* __restrict__ Ch,
    int M, int N, int K, int mode)
{
    extern __shared__ char sm[];
    const uint32_t smU = smem_u32(sm);
    const int tid  = threadIdx.x;
    const int lane = tid & 31;
    const int wid  = tid >> 5;
    const int bm   = blockIdx.y * 128;
    const int bn   = blockIdx.x * 128;
    const int wm   = (wid >> 2) * 64;       // warp row base within tile
    const int wn   = (wid & 3) * 32;        // warp col base within tile

    float acc[4][4][4];
    #pragma unroll
    for (int i = 0; i < 4; ++i)
        #pragma unroll
        for (int j = 0; j < 4; ++j)
            #pragma unroll
            for (int r = 0; r < 4; ++r) acc[i][j][r] = 0.f;

    const int NC = K / BKc;

    // ---- async load of one BK chunk into stage s ----
    auto issue = [&](int chunk, int s) {
        const int k0 = chunk * BKc;
        #pragma unroll
        for (int t = 0; t < 2; ++t) {
            const __half* src = (t == 0) ? A : W;
            const uint32_t base = smU + s * STAGE_B + t * TILE_B;
            #pragma unroll
            for (int i = 0; i < 2; ++i) {
                int id  = tid * 2 + i;          // 0..511
                int row = id >> 2;
                int c16 = id & 3;
                uint32_t dst = base + row * SA_B + c16 * 16;
                int sz = 16;
                const char* g;
                if (t == 0) {
                    g = (const char*)(src + (size_t)(bm + row) * K + k0) + c16 * 16;
                } else {
                    int rn = bn + row;
                    g = (const char*)(src + (size_t)rn * K + k0) + c16 * 16;
                    if (rn >= N) { sz = 0; g = (const char*)src; }
                }
                cp_async16(dst, g, sz);
            }
        }
        CP_COMMIT();
    };

    // per-lane ldmatrix offsets (identical pattern to verified round-3 kernel)
    const int wrow_off = ((lane >> 4) << 3) + (lane & 7);  // W: n offset within 16
    const int wcol_off = ((lane >> 3) & 1) * 8;            // W: k offset within 16
    const int arow_off = lane & 15;                         // A: m offset within 16
    const int acol_off = (lane >> 4) << 3;                  // A: k offset within 16

    auto compute = [&](int s) {
        const uint32_t aB = smU + s * STAGE_B;
        const uint32_t wB = aB + TILE_B;
        #pragma unroll
        for (int ks = 0; ks < BKc; ks += 16) {
            uint32_t wh[8];
            #pragma unroll
            for (int nb = 0; nb < 2; ++nb) {
                int nrow = wn + nb * 16 + wrow_off;
                uint32_t off = nrow * SA_B + (ks + wcol_off) * 2;
                ldm_x4(&wh[nb * 4], wB + off);
            }
            #pragma unroll
            for (int mi = 0; mi < 4; ++mi) {
                int arow = wm + mi * 16 + arow_off;
                uint32_t off = arow * SA_B + (ks + acol_off) * 2;
                uint32_t ah[4];
                ldm_x4(ah, aB + off);
                #pragma unroll
                for (int nj = 0; nj < 4; ++nj)
                    mma16816(&acc[mi][nj][0], ah, &wh[nj * 2]);
            }
        }
    };

    issue(0, 0);
    for (int c = 0; c < NC; ++c) {
        if (c + 1 < NC) {
            issue(c + 1, (c + 1) & 1);
            CP_WAIT(1);
        } else {
            CP_WAIT(0);
        }
        __syncthreads();
        compute(c & 1);
        __syncthreads();
    }

    // ---- epilogue ----
    #pragma unroll
    for (int mi = 0; mi < 4; ++mi) {
        #pragma unroll
        for (int nj = 0; nj < 4; ++nj) {
            int row0 = bm + wm + mi * 16 + (lane >> 2);
            int col0 = bn + wn + nj * 8 + (lane & 3) * 2;
            #pragma unroll
            for (int r = 0; r < 4; ++r) {
                int row = row0 + ((r >> 1) ? 8 : 0);
                int col = col0 + (r & 1);
                if (col < N) {
                    float t = acc[mi][nj][r] + bias[col];
                    if (mode == 0) {
                        C[(size_t)row * N + col] = t;
                    } else {
                        Ch[(size_t)row * N + col] = __float2half(fmaxf(t, 0.f));
                    }
                }
            }
        }
    }
}

// ================= tiny GEMM for cross-attn shortcut =================
__global__ __launch_bounds__(256) void small_gemm(
    const float* __restrict__ A, const float* __restrict__ W,
    const float* __restrict__ bias, float* __restrict__ C,
    int Bq, int N, int K)
{
    int wg   = (blockIdx.x * blockDim.x + threadIdx.x) >> 5;
    int lane = threadIdx.x & 31;
    if (wg >= Bq * N) return;
    int bq = wg / N, n = wg - bq * N;
    const float* a = A + (size_t)bq * K;
    const float* w = W + (size_t)n * K;
    float s = 0.f;
    for (int k = lane; k < K; k += 32) s = fmaf(a[k], w[k], s);
    #pragma unroll
    for (int o = 16; o; o >>= 1) s += __shfl_xor_sync(0xffffffffu, s, o);
    if (lane == 0) C[wg] = s + bias[n];
}

// ================= fused residual-add + LayerNorm (+opt fp16 copy) ===============
__global__ __launch_bounds__(256) void add_ln_kernel(
    float* __restrict__ x, const float* __restrict__ br,
    const float* __restrict__ g, const float* __restrict__ b, int bcast,
    __half* __restrict__ x16)
{
    int row = blockIdx.x;
    const float* brp = br + (size_t)(bcast ? (row >> 9) : row) * Dd;
    float* xp = x + (size_t)row * Dd;
    int tid = threadIdx.x;

    float v[3];
    float sum = 0.f, sq = 0.f;
    #pragma unroll
    for (int i = 0; i < 3; ++i) {
        int c = tid + i * 256;
        float t = xp[c] + brp[c];
        v[i] = t; sum += t; sq = fmaf(t, t, sq);
    }
    #pragma unroll
    for (int o = 16; o; o >>= 1) {
        sum += __shfl_xor_sync(0xffffffffu, sum, o);
        sq  += __shfl_xor_sync(0xffffffffu, sq,  o);
    }
    __shared__ float sh1[8], sh2[8];
    int warp = tid >> 5, lane = tid & 31;
    if (lane == 0) { sh1[warp] = sum; sh2[warp] = sq; }
    __syncthreads();
    if (tid == 0) {
        float a = 0.f, c2 = 0.f;
        #pragma unroll
        for (int i = 0; i < 8; ++i) { a += sh1[i]; c2 += sh2[i]; }
        sh1[0] = a; sh2[0] = c2;
    }
    __syncthreads();
    float mu  = sh1[0] * (1.f / Dd);
    float var = sh2[0] * (1.f / Dd) - mu * mu;
    float rs  = rsqrtf(var + 1e-5f);
    #pragma unroll
    for (int i = 0; i < 3; ++i) {
        int c = tid + i * 256;
        float o = (v[i] - mu) * rs * g[c] + b[c];
        xp[c] = o;
        if (x16) x16[(size_t)row * Dd + c] = __float2half(o);
    }
}

// ================= causal self-attention (smem V tiles + causal skip) ============
__global__ __launch_bounds__(256) void attn_kernel(
    const float* __restrict__ qkv, __half* __restrict__ o16)
{
    __shared__ float sQ[16][97];
    __shared__ float sK[16][97];       // reused as V tile in PV phase
    __shared__ float sS[16][Ss];
    const int qb  = blockIdx.x * 16;
    const int h   = blockIdx.y;
    const int b   = blockIdx.z;
    const int tid = threadIdx.x;
    const float scale = rsqrtf((float)DHd);
    const int jmax = qb + 16;          // causal skip

    for (int e = tid; e < 16 * DHd; e += 256) {
        int r = e / DHd, d = e - r * DHd;
        sQ[r][d] = qkv[(size_t)(b * Ss + qb + r) * (3 * Dd) + h * DHd + d];
    }
    __syncthreads();

    const int r = tid >> 4, c = tid & 15;
    for (int jt = 0; jt < jmax; jt += 16) {
        for (int e = tid; e < 16 * DHd; e += 256) {
            int rr = e / DHd, d = e - rr * DHd;
            sK[rr][d] = qkv[(size_t)(b * Ss + jt + rr) * (3 * Dd) + Dd + h * DHd + d];
        }
        __syncthreads();
        float a0 = 0.f, a1 = 0.f;
        #pragma unroll
        for (int d = 0; d < DHd; d += 2) {
            a0 = fmaf(sQ[r][d],     sK[c][d],     a0);
            a1 = fmaf(sQ[r][d + 1], sK[c][d + 1], a1);
        }
        int j = jt + c;
        sS[r][j] = (j <= qb + r) ? (a0 + a1) * scale : -1e9f;
        __syncthreads();
    }

    const int warp = tid >> 5, lane = tid & 31;
    for (int rr = warp; rr < 16; rr += 8) {
        float mx = -1e30f;
        for (int j = lane; j < jmax; j += 32) mx = fmaxf(mx, sS[rr][j]);
        #pragma unroll
        for (int o = 16; o; o >>= 1) mx = fmaxf(mx, __shfl_xor_sync(0xffffffffu, mx, o));
        float sum = 0.f;
        for (int j = lane; j < jmax; j += 32) {
            float e = __expf(sS[rr][j] - mx);
            sS[rr][j] = e; sum += e;
        }
        #pragma unroll
        for (int o = 16; o; o >>= 1) sum += __shfl_xor_sync(0xffffffffu, sum, o);
        float inv = 1.f / sum;
        for (int j = lane; j < jmax; j += 32) sS[rr][j] *= inv;
    }
    __syncthreads();

    const int rr2 = tid >> 4;          // q row 0..15
    const int dg  = (tid & 15) * 6;    // this thread's 6 d's
    float o6[6] = {0.f, 0.f, 0.f, 0.f, 0.f, 0.f};
    for (int jt = 0; jt < jmax; jt += 16) {
        for (int e = tid; e < 16 * DHd; e += 256) {
            int rr = e / DHd, d = e - rr * DHd;
            sK[rr][d] = qkv[(size_t)(b * Ss + jt + rr) * (3 * Dd) + 2 * Dd + h * DHd + d];
        }
        __syncthreads();
        #pragma unroll
        for (int j = 0; j < 16; ++j) {
            float p = sS[rr2][jt + j];
            #pragma unroll
            for (int q = 0; q < 6; ++q)
                o6[q] = fmaf(p, sK[j][dg + q], o6[q]);
        }
        __syncthreads();
    }

    size_t oi = (size_t)(b * Ss + qb + rr2) * Dd + h * DHd + dg;
    #pragma unroll
    for (int q = 0; q < 6; ++q)
        o16[oi + q] = __float2half(o6[q]);
}

// ================= launcher =================
extern "C" void kernel_launch(void* const* d_in, const int* in_sizes, int n_in,
                              void* d_out, int out_size)
{
    (void)in_sizes; (void)n_in; (void)out_size;
    const float* latent   = (const float*)d_in[0];
    const int*   target   = (const int*)  d_in[1];
    const float* tok_emb  = (const float*)d_in[2];
    const float* pos_emb  = (const float*)d_in[3];
    const float* sa_w_qkv = (const float*)d_in[4];
    const float* sa_b_qkv = (const float*)d_in[5];
    const float* sa_w_o   = (const float*)d_in[6];
    const float* sa_b_o   = (const float*)d_in[7];
    const float* ca_w_qkv = (const float*)d_in[8];
    const float* ca_b_qkv = (const float*)d_in[9];
    const float* ca_w_o   = (const float*)d_in[10];
    const float* ca_b_o   = (const float*)d_in[11];
    const float* ffn_w1   = (const float*)d_in[12];
    const float* ffn_b1   = (const float*)d_in[13];
    const float* ffn_w2   = (const float*)d_in[14];
    const float* ffn_b2   = (const float*)d_in[15];
    const float* ln1_g    = (const float*)d_in[16];
    const float* ln1_b    = (const float*)d_in[17];
    const float* ln2_g    = (const float*)d_in[18];
    const float* ln2_b    = (const float*)d_in[19];
    const float* ln3_g    = (const float*)d_in[20];
    const float* ln3_b    = (const float*)d_in[21];
    const float* out_w    = (const float*)d_in[22];
    const float* out_b    = (const float*)d_in[23];

    float *x, *buf, *y, *cat, *ca;
    __half *x16, *o16, *h16, *wqkv16, *wo16, *w116, *w216, *wout16;
    cudaGetSymbolAddress((void**)&x,   g_x);
    cudaGetSymbolAddress((void**)&buf, g_buf);
    cudaGetSymbolAddress((void**)&y,   g_y);
    cudaGetSymbolAddress((void**)&cat, g_cat);
    cudaGetSymbolAddress((void**)&ca,  g_ca);
    cudaGetSymbolAddress((void**)&x16, g_x16);
    cudaGetSymbolAddress((void**)&o16, g_o16);
    cudaGetSymbolAddress((void**)&h16, g_h16);
    cudaGetSymbolAddress((void**)&wqkv16, g_wqkv16);
    cudaGetSymbolAddress((void**)&wo16,   g_wo16);
    cudaGetSymbolAddress((void**)&w116,   g_w116);
    cudaGetSymbolAddress((void**)&w216,   g_w216);
    cudaGetSymbolAddress((void**)&wout16, g_wout16);

    cudaFuncSetAttribute(gemm_fp16, cudaFuncAttributeMaxDynamicSharedMemorySize, GEMM_SMEM);

    // launch 0: all weight conversions in one kernel
    const int nb0 = (Ll*3*Dd*Dd) / 1024, nb1 = (Ll*Dd*Dd) / 1024,
              nb2 = (Ll*Ff*Dd) / 1024,   nb3 = (Ll*Dd*Ff) / 1024,
              nb4 = (Vv*Dd) / 1024;
    convert_all<<<nb0 + nb1 + nb2 + nb3 + nb4, 256>>>(
        sa_w_qkv, wqkv16, nb0, sa_w_o, wo16, nb1,
        ffn_w1, w116, nb2, ffn_w2, w216, nb3, out_w, wout16, nb4);

    // launch 1: embed
    embed_kernel<<<Mm, 256>>>(target, tok_emb, pos_emb, x, x16);

    // launches 2-4: hoisted cross-attn small gemms (layer 0 pair + layer 1 first)
    const int SGG = (Bb * Dd * 32 + 255) / 256;
    small_gemm<<<SGG, 256>>>(latent, ca_w_qkv + (size_t)0*3*Dd*Dd + (size_t)2*Dd*Dd,
                             ca_b_qkv + (size_t)0*3*Dd + 2*Dd, cat + 0*Bb*Dd, Bb, Dd, Dd);
    small_gemm<<<SGG, 256>>>(cat + 0*Bb*Dd, ca_w_o + (size_t)0*Dd*Dd,
                             ca_b_o + (size_t)0*Dd, ca + 0*Bb*Dd, Bb, Dd, Dd);
    small_gemm<<<SGG, 256>>>(latent, ca_w_qkv + (size_t)1*3*Dd*Dd + (size_t)2*Dd*Dd,
                             ca_b_qkv + (size_t)1*3*Dd + 2*Dd, cat + 1*Bb*Dd, Bb, Dd, Dd);

    // launch 5: first big GEMM (QKV, layer 0) — ncu -s 5 -c 1 profiles THIS
    gemm_fp16<<<dim3(18, 64), 256, GEMM_SMEM>>>(
        x16, wqkv16, sa_b_qkv, buf, nullptr, Mm, 3*Dd, Dd, 0);

    // remaining hoisted cross-attn small gemms
    small_gemm<<<SGG, 256>>>(cat + 1*Bb*Dd, ca_w_o + (size_t)1*Dd*Dd,
                             ca_b_o + (size_t)1*Dd, ca + 1*Bb*Dd, Bb, Dd, Dd);
    for (int l = 2; l < Ll; ++l) {
        small_gemm<<<SGG, 256>>>(latent, ca_w_qkv + (size_t)l*3*Dd*Dd + (size_t)2*Dd*Dd,
                                 ca_b_qkv + (size_t)l*3*Dd + 2*Dd, cat + l*Bb*Dd, Bb, Dd, Dd);
        small_gemm<<<SGG, 256>>>(cat + l*Bb*Dd, ca_w_o + (size_t)l*Dd*Dd,
                                 ca_b_o + (size_t)l*Dd, ca + l*Bb*Dd, Bb, Dd, Dd);
    }

    for (int l = 0; l < Ll; ++l) {
        // ---- self-attention ----
        if (l > 0)
            gemm_fp16<<<dim3(18, 64), 256, GEMM_SMEM>>>(
                x16, wqkv16 + (size_t)l*3*Dd*Dd, sa_b_qkv + (size_t)l*3*Dd,
                buf, nullptr, Mm, 3*Dd, Dd, 0);
        attn_kernel<<<dim3(Ss/16, Hh, Bb), 256>>>(buf, o16);
        gemm_fp16<<<dim3(6, 64), 256, GEMM_SMEM>>>(
            o16, wo16 + (size_t)l*Dd*Dd, sa_b_o + (size_t)l*Dd,
            y, nullptr, Mm, Dd, Dd, 0);
        add_ln_kernel<<<Mm, 256>>>(x, y, ln1_g + (size_t)l*Dd, ln1_b + (size_t)l*Dd, 0,
                                   nullptr);

        // ---- cross-attention (analytic) residual + LN ----
        add_ln_kernel<<<Mm, 256>>>(x, ca + l*Bb*Dd, ln2_g + (size_t)l*Dd,
                                   ln2_b + (size_t)l*Dd, 1, x16);

        // ---- FFN ----
        gemm_fp16<<<dim3(16, 64), 256, GEMM_SMEM>>>(
            x16, w116 + (size_t)l*Ff*Dd, ffn_b1 + (size_t)l*Ff,
            nullptr, h16, Mm, Ff, Dd, 1);
        gemm_fp16<<<dim3(6, 64), 256, GEMM_SMEM>>>(
            h16, w216 + (size_t)l*Dd*Ff, ffn_b2 + (size_t)l*Dd,
            y, nullptr, Mm, Dd, Ff, 0);
        add_ln_kernel<<<Mm, 256>>>(x, y, ln3_g + (size_t)l*Dd, ln3_b + (size_t)l*Dd, 0,
                                   x16);
    }

    // ---- output projection ----
    gemm_fp16<<<dim3(1, 64), 256, GEMM_SMEM>>>(
        x16, wout16, out_b, (float*)d_out, nullptr, Mm, Vv, Dd, 0);
}

// round 5
// speedup vs baseline: 6.1342x; 2.0233x over previous
#include <cuda_runtime.h>
#include <cuda_fp16.h>
#include <stdint.h>
#include <math.h>

// Problem dims
#define Bb   16
#define Ss   512
#define Dd   768
#define Hh   8
#define Vv   100
#define Ff   2048
#define Ll   6
#define DHd  96
#define Mm   (Bb*Ss)   // 8192
#define QKVS (3*Dd)    // 2304

// ================= low-level helpers =================
__device__ __forceinline__ uint32_t smem_u32(const void* p) {
    return (uint32_t)__cvta_generic_to_shared(p);
}
__device__ __forceinline__ void cp_async16(uint32_t dst, const void* src, int szvalid) {
    asm volatile("cp.async.cg.shared.global [%0], [%1], 16, %2;"
                 :: "r"(dst), "l"(src), "r"(szvalid) : "memory");
}
#define CP_COMMIT() asm volatile("cp.async.commit_group;" ::: "memory")
#define CP_WAIT(n)  asm volatile("cp.async.wait_group %0;" :: "n"(n) : "memory")

__device__ __forceinline__ void ldm_x4(uint32_t* r, uint32_t addr) {
    asm volatile("ldmatrix.sync.aligned.m8n8.x4.shared.b16 {%0,%1,%2,%3}, [%4];"
                 : "=r"(r[0]), "=r"(r[1]), "=r"(r[2]), "=r"(r[3]) : "r"(addr));
}
__device__ __forceinline__ void ldm_trans_x4(uint32_t* r, uint32_t addr) {
    asm volatile("ldmatrix.sync.aligned.m8n8.x4.trans.shared.b16 {%0,%1,%2,%3}, [%4];"
                 : "=r"(r[0]), "=r"(r[1]), "=r"(r[2]), "=r"(r[3]) : "r"(addr));
}
__device__ __forceinline__ void mma16816(float* d, const uint32_t* a, const uint32_t* b) {
    asm volatile("mma.sync.aligned.m16n8k16.row.col.f32.f16.f16.f32 "
                 "{%0,%1,%2,%3}, {%4,%5,%6,%7}, {%8,%9}, {%0,%1,%2,%3};"
                 : "+f"(d[0]), "+f"(d[1]), "+f"(d[2]), "+f"(d[3])
                 : "r"(a[0]), "r"(a[1]), "r"(a[2]), "r"(a[3]), "r"(b[0]), "r"(b[1]));
}

// ================= device scratch =================
__device__ float g_x   [Mm * Dd];
__device__ float g_y   [Mm * Dd];
__device__ float g_cat [Ll * Bb * Dd];
__device__ float g_ca  [Ll * Bb * Dd];

__device__ __align__(16) __half g_x16 [Mm * Dd];
__device__ __align__(16) __half g_o16 [Mm * Dd];
__device__ __align__(16) __half g_h16 [Mm * Ff];
__device__ __align__(16) __half g_qkv16[Mm * QKVS];

__device__ __align__(16) __half g_wqkv16[Ll*3*Dd*Dd];
__device__ __align__(16) __half g_wo16  [Ll*Dd*Dd];
__device__ __align__(16) __half g_w116  [Ll*Ff*Dd];
__device__ __align__(16) __half g_w216  [Ll*Dd*Ff];
__device__ __align__(16) __half g_wout16[Vv*Dd];

// ================= weight convert =================
__global__ __launch_bounds__(256) void convert_all(
    const float* __restrict__ s0, __half* __restrict__ d0, int b0,
    const float* __restrict__ s1, __half* __restrict__ d1, int b1,
    const float* __restrict__ s2, __half* __restrict__ d2, int b2,
    const float* __restrict__ s3, __half* __restrict__ d3, int b3,
    const float* __restrict__ s4, __half* __restrict__ d4, int b4)
{
    int bid = blockIdx.x;
    const float* src; __half* dst; int nb;
    if      (bid < b0)          { src = s0; dst = d0; nb = bid; }
    else if (bid < b0+b1)       { src = s1; dst = d1; nb = bid - b0; }
    else if (bid < b0+b1+b2)    { src = s2; dst = d2; nb = bid - b0 - b1; }
    else if (bid < b0+b1+b2+b3) { src = s3; dst = d3; nb = bid - b0 - b1 - b2; }
    else                        { src = s4; dst = d4; nb = bid - b0 - b1 - b2 - b3; }
    int i = (nb * 256 + threadIdx.x) * 4;
    float4 v = *(const float4*)&src[i];
    *(__half2*)&dst[i]     = __floats2half2_rn(v.x, v.y);
    *(__half2*)&dst[i + 2] = __floats2half2_rn(v.z, v.w);
}

// ================= embed =================
__global__ __launch_bounds__(256) void embed_kernel(
    const int* __restrict__ target, const float* __restrict__ tok,
    const float* __restrict__ pos, float* __restrict__ x,
    __half* __restrict__ x16)
{
    int row = blockIdx.x;
    int s   = row & (Ss - 1);
    int t   = target[row];
    const float* tp = tok + (size_t)t * Dd;
    const float* pp = pos + (size_t)s * Dd;
    size_t base = (size_t)row * Dd;
    for (int c = threadIdx.x; c < Dd; c += 256) {
        float v = tp[c] + pp[c];
        x[base + c] = v;
        x16[base + c] = __float2half(v);
    }
}

// ================= fp16 GEMM: CTA 128x256, warp tile 64x64, BK=32 =================
// mode 0: fp32 out + bias. mode 1: relu + fp16 out. mode 2: fp16 out (no relu).
#define BKc 32
#define APITCH 80
#define A_TILE_B (128*APITCH)           // 10240
#define W_TILE_B (256*APITCH)           // 20480
#define STAGE_B  (A_TILE_B + W_TILE_B)  // 30720
#define GEMM_SMEM (2*STAGE_B)           // 61440

__global__ void __launch_bounds__(256) gemm_fp16(
    const __half* __restrict__ A, const __half* __restrict__ W,
    const float* __restrict__ bias, float* __restrict__ C,
    __half* __restrict__ Ch,
    int M, int N, int K, int mode)
{
    extern __shared__ char sm[];
    const uint32_t smU = smem_u32(sm);
    const int tid  = threadIdx.x;
    const int lane = tid & 31;
    const int wid  = tid >> 5;
    const int bm   = blockIdx.y * 128;
    const int bn   = blockIdx.x * 256;
    const int wm   = (wid >> 2) * 64;
    const int wn   = (wid & 3) * 64;

    float acc[4][8][4];
    #pragma unroll
    for (int i = 0; i < 4; ++i)
        #pragma unroll
        for (int j = 0; j < 8; ++j)
            #pragma unroll
            for (int r = 0; r < 4; ++r) acc[i][j][r] = 0.f;

    const int NC = K / BKc;

    auto issue = [&](int chunk, int s) {
        const int k0 = chunk * BKc;
        #pragma unroll
        for (int i = 0; i < 6; ++i) {
            int c = tid + 256 * i;      // 0..1535
            if (c < 512) {
                int row = c >> 2, c16 = c & 3;
                uint32_t dst = smU + s * STAGE_B + row * APITCH + c16 * 16;
                cp_async16(dst, (const char*)(A + (size_t)(bm + row) * K + k0) + c16 * 16, 16);
            } else {
                int cw = c - 512;
                int row = cw >> 2, c16 = cw & 3;
                int rn = bn + row;
                uint32_t dst = smU + s * STAGE_B + A_TILE_B + row * APITCH + c16 * 16;
                const char* g = (const char*)(W + (size_t)rn * K + k0) + c16 * 16;
                int sz = 16;
                if (rn >= N) { sz = 0; g = (const char*)W; }
                cp_async16(dst, g, sz);
            }
        }
        CP_COMMIT();
    };

    const int wrow_off = ((lane >> 4) << 3) + (lane & 7);
    const int wcol_off = ((lane >> 3) & 1) * 8;
    const int arow_off = lane & 15;
    const int acol_off = (lane >> 4) << 3;

    auto compute = [&](int s) {
        const uint32_t aB = smU + s * STAGE_B;
        const uint32_t wB = aB + A_TILE_B;
        #pragma unroll
        for (int ks = 0; ks < BKc; ks += 16) {
            uint32_t wh[4][4];
            #pragma unroll
            for (int nb = 0; nb < 4; ++nb)
                ldm_x4(wh[nb], wB + (wn + nb * 16 + wrow_off) * APITCH + (ks + wcol_off) * 2);
            #pragma unroll
            for (int mi = 0; mi < 4; ++mi) {
                uint32_t ah[4];
                ldm_x4(ah, aB + (wm + mi * 16 + arow_off) * APITCH + (ks + acol_off) * 2);
                #pragma unroll
                for (int nb = 0; nb < 4; ++nb) {
                    mma16816(&acc[mi][nb * 2][0],     ah, &wh[nb][0]);
                    mma16816(&acc[mi][nb * 2 + 1][0], ah, &wh[nb][2]);
                }
            }
        }
    };

    issue(0, 0);
    for (int c = 0; c < NC; ++c) {
        if (c + 1 < NC) {
            issue(c + 1, (c + 1) & 1);
            CP_WAIT(1);
        } else {
            CP_WAIT(0);
        }
        __syncthreads();
        compute(c & 1);
        __syncthreads();
    }

    // epilogue: bias regs then vectorized stores (N always even)
    float bs[16];
    #pragma unroll
    for (int nj = 0; nj < 8; ++nj) {
        int c0 = bn + wn + nj * 8 + (lane & 3) * 2;
        bs[nj * 2]     = (c0 < N)     ? bias[c0]     : 0.f;
        bs[nj * 2 + 1] = (c0 + 1 < N) ? bias[c0 + 1] : 0.f;
    }
    #pragma unroll
    for (int mi = 0; mi < 4; ++mi) {
        #pragma unroll
        for (int nj = 0; nj < 8; ++nj) {
            int c0 = bn + wn + nj * 8 + (lane & 3) * 2;
            if (c0 >= N) continue;
            #pragma unroll
            for (int p = 0; p < 2; ++p) {
                int row = bm + wm + mi * 16 + (lane >> 2) + p * 8;
                float v0 = acc[mi][nj][p * 2]     + bs[nj * 2];
                float v1 = acc[mi][nj][p * 2 + 1] + bs[nj * 2 + 1];
                if (mode == 0) {
                    *(float2*)(C + (size_t)row * N + c0) = make_float2(v0, v1);
                } else {
                    if (mode == 1) { v0 = fmaxf(v0, 0.f); v1 = fmaxf(v1, 0.f); }
                    *(__half2*)(Ch + (size_t)row * N + c0) = __floats2half2_rn(v0, v1);
                }
            }
        }
    }
}

// ================= tiny GEMM for cross-attn shortcut =================
__global__ __launch_bounds__(256) void small_gemm(
    const float* __restrict__ A, const float* __restrict__ W,
    const float* __restrict__ bias, float* __restrict__ C,
    int Bq, int N, int K)
{
    int wg   = (blockIdx.x * blockDim.x + threadIdx.x) >> 5;
    int lane = threadIdx.x & 31;
    if (wg >= Bq * N) return;
    int bq = wg / N, n = wg - bq * N;
    const float* a = A + (size_t)bq * K;
    const float* w = W + (size_t)n * K;
    float s = 0.f;
    for (int k = lane; k < K; k += 32) s = fmaf(a[k], w[k], s);
    #pragma unroll
    for (int o = 16; o; o >>= 1) s += __shfl_xor_sync(0xffffffffu, s, o);
    if (lane == 0) C[wg] = s + bias[n];
}

// ================= fused residual-add + LayerNorm =================
__global__ __launch_bounds__(256) void add_ln_kernel(
    float* __restrict__ x, const float* __restrict__ br,
    const float* __restrict__ g, const float* __restrict__ b, int bcast,
    __half* __restrict__ x16)
{
    int row = blockIdx.x;
    const float* brp = br + (size_t)(bcast ? (row >> 9) : row) * Dd;
    float* xp = x + (size_t)row * Dd;
    int tid = threadIdx.x;

    float v[3];
    float sum = 0.f, sq = 0.f;
    #pragma unroll
    for (int i = 0; i < 3; ++i) {
        int c = tid + i * 256;
        float t = xp[c] + brp[c];
        v[i] = t; sum += t; sq = fmaf(t, t, sq);
    }
    #pragma unroll
    for (int o = 16; o; o >>= 1) {
        sum += __shfl_xor_sync(0xffffffffu, sum, o);
        sq  += __shfl_xor_sync(0xffffffffu, sq,  o);
    }
    __shared__ float sh1[8], sh2[8];
    int warp = tid >> 5, lane = tid & 31;
    if (lane == 0) { sh1[warp] = sum; sh2[warp] = sq; }
    __syncthreads();
    if (tid == 0) {
        float a = 0.f, c2 = 0.f;
        #pragma unroll
        for (int i = 0; i < 8; ++i) { a += sh1[i]; c2 += sh2[i]; }
        sh1[0] = a; sh2[0] = c2;
    }
    __syncthreads();
    float mu  = sh1[0] * (1.f / Dd);
    float var = sh2[0] * (1.f / Dd) - mu * mu;
    float rs  = rsqrtf(var + 1e-5f);
    #pragma unroll
    for (int i = 0; i < 3; ++i) {
        int c = tid + i * 256;
        float o = (v[i] - mu) * rs * g[c] + b[c];
        xp[c] = o;
        if (x16) x16[(size_t)row * Dd + c] = __float2half(o);
    }
}

// ================= mma.sync causal self-attention =================
// Block = (qb=16 q rows, h, b). 256 threads.
// smem: [0,3328)    Q tile (16x104 halves) / V tile in phase 2
//       [3328,29952)  per-warp K staging 8 x 3328
//       [29952,62720) sS fp32 16x512
//       [62720,79360) sPh fp16 16x520
#define ATT_SMEM 79360
#define KPITCHB 208   // bytes per staged row
#define SPH_PITCHB 1040

__global__ void __launch_bounds__(256) attn_mma(
    const __half* __restrict__ qkv, __half* __restrict__ o16)
{
    extern __shared__ char smd[];
    const int qb  = blockIdx.x * 16;
    const int h   = blockIdx.y;
    const int b   = blockIdx.z;
    const int tid = threadIdx.x;
    const int lane = tid & 31;
    const int wid  = tid >> 5;
    const int ntiles = blockIdx.x + 1;
    const int jmax   = ntiles * 16;

    const uint32_t sq  = smem_u32(smd);
    const uint32_t skw = sq + 3328 + wid * 3328;
    float* sS = (float*)(smd + 29952);
    const uint32_t sph = sq + 62720;
    __half* sPh = (__half*)(smd + 62720);

    // stage Q (16 rows x 96 halves, padded pitch 208B)
    if (tid < 192) {
        int row = tid / 12, dc = tid % 12;
        const __half* src = qkv + (size_t)(b * Ss + qb + row) * QKVS + h * DHd + dc * 8;
        *(uint4*)(smd + row * KPITCHB + dc * 16) = *(const uint4*)src;
    }
    __syncthreads();

    // preload Q fragments (A operand) for all 6 k-steps
    uint32_t qf[6][4];
    {
        uint32_t base = sq + (lane & 15) * KPITCHB + ((lane >> 4) << 3) * 2;
        #pragma unroll
        for (int ks = 0; ks < 6; ++ks)
            ldm_x4(qf[ks], base + ks * 32);
    }

    const float scale = rsqrtf((float)DHd);

    // ---- phase 1: scores (warp-private j-tiles) ----
    for (int t = wid; t < ntiles; t += 8) {
        const int jt = t * 16;
        // stage K tile 16x96 into this warp's buffer
        #pragma unroll
        for (int i = 0; i < 6; ++i) {
            int c = lane + 32 * i;      // 0..191
            int row = c / 12, dc = c % 12;
            const __half* src = qkv + (size_t)(b * Ss + jt + row) * QKVS + Dd + h * DHd + dc * 8;
            *(uint4*)(smd + 3328 + wid * 3328 + row * KPITCHB + dc * 16) = *(const uint4*)src;
        }
        __syncwarp();
        float acc[2][4] = {{0.f,0.f,0.f,0.f},{0.f,0.f,0.f,0.f}};
        const uint32_t kbase = skw + ((lane & 7) + ((lane >> 4) << 3)) * KPITCHB
                             + (((lane >> 3) & 1) << 3) * 2;
        #pragma unroll
        for (int ks = 0; ks < 6; ++ks) {
            uint32_t kf[4];
            ldm_x4(kf, kbase + ks * 32);
            mma16816(acc[0], qf[ks], &kf[0]);
            mma16816(acc[1], qf[ks], &kf[2]);
        }
        #pragma unroll
        for (int nj = 0; nj < 2; ++nj)
            #pragma unroll
            for (int e = 0; e < 4; ++e) {
                int r = (lane >> 2) + (e >> 1) * 8;
                int j = jt + nj * 8 + (lane & 3) * 2 + (e & 1);
                float v = acc[nj][e] * scale;
                if (j > qb + r) v = -1e9f;
                sS[r * 512 + j] = v;
            }
        __syncwarp();
    }
    __syncthreads();

    // ---- softmax (fp32), write normalized P as fp16 ----
    for (int rr = wid; rr < 16; rr += 8) {
        float mx = -1e30f;
        for (int j = lane; j < jmax; j += 32) mx = fmaxf(mx, sS[rr * 512 + j]);
        #pragma unroll
        for (int o = 16; o; o >>= 1) mx = fmaxf(mx, __shfl_xor_sync(0xffffffffu, mx, o));
        float sum = 0.f;
        for (int j = lane; j < jmax; j += 32) {
            float e = __expf(sS[rr * 512 + j] - mx);
            sS[rr * 512 + j] = e; sum += e;
        }
        #pragma unroll
        for (int o = 16; o; o >>= 1) sum += __shfl_xor_sync(0xffffffffu, sum, o);
        float inv = 1.f / sum;
        for (int j = lane; j < jmax; j += 32)
            sPh[rr * 520 + j] = __float2half(sS[rr * 512 + j] * inv);
    }
    __syncthreads();

    // ---- phase 2: PV (cooperative V tiles; warps 0-5 own 16 d-cols each) ----
    float oacc[2][4] = {{0.f,0.f,0.f,0.f},{0.f,0.f,0.f,0.f}};
    const int wd = wid * 16;
    for (int t = 0; t < ntiles; ++t) {
        const int jt = t * 16;
        if (tid < 192) {
            int row = tid / 12, dc = tid % 12;
            const __half* src = qkv + (size_t)(b * Ss + jt + row) * QKVS + 2 * Dd + h * DHd + dc * 8;
            *(uint4*)(smd + row * KPITCHB + dc * 16) = *(const uint4*)src;
        }
        __syncthreads();
        if (wid < 6) {
            uint32_t pf[4], vf[4];
            ldm_x4(pf, sph + (lane & 15) * SPH_PITCHB + (jt + ((lane >> 4) << 3)) * 2);
            ldm_trans_x4(vf, sq + ((lane & 7) + (((lane >> 3) & 1) << 3)) * KPITCHB
                             + (wd + ((lane >> 4) << 3)) * 2);
            mma16816(oacc[0], pf, &vf[0]);
            mma16816(oacc[1], pf, &vf[2]);
        }
        __syncthreads();
    }
    if (wid < 6) {
        #pragma unroll
        for (int nj = 0; nj < 2; ++nj) {
            int col = h * DHd + wd + nj * 8 + (lane & 3) * 2;
            #pragma unroll
            for (int p = 0; p < 2; ++p) {
                int r = qb + (lane >> 2) + p * 8;
                *(__half2*)(o16 + (size_t)(b * Ss + r) * Dd + col) =
                    __floats2half2_rn(oacc[nj][p * 2], oacc[nj][p * 2 + 1]);
            }
        }
    }
}

// ================= launcher =================
extern "C" void kernel_launch(void* const* d_in, const int* in_sizes, int n_in,
                              void* d_out, int out_size)
{
    (void)in_sizes; (void)n_in; (void)out_size;
    const float* latent   = (const float*)d_in[0];
    const int*   target   = (const int*)  d_in[1];
    const float* tok_emb  = (const float*)d_in[2];
    const float* pos_emb  = (const float*)d_in[3];
    const float* sa_w_qkv = (const float*)d_in[4];
    const float* sa_b_qkv = (const float*)d_in[5];
    const float* sa_w_o   = (const float*)d_in[6];
    const float* sa_b_o   = (const float*)d_in[7];
    const float* ca_w_qkv = (const float*)d_in[8];
    const float* ca_b_qkv = (const float*)d_in[9];
    const float* ca_w_o   = (const float*)d_in[10];
    const float* ca_b_o   = (const float*)d_in[11];
    const float* ffn_w1   = (const float*)d_in[12];
    const float* ffn_b1   = (const float*)d_in[13];
    const float* ffn_w2   = (const float*)d_in[14];
    const float* ffn_b2   = (const float*)d_in[15];
    const float* ln1_g    = (const float*)d_in[16];
    const float* ln1_b    = (const float*)d_in[17];
    const float* ln2_g    = (const float*)d_in[18];
    const float* ln2_b    = (const float*)d_in[19];
    const float* ln3_g    = (const float*)d_in[20];
    const float* ln3_b    = (const float*)d_in[21];
    const float* out_w    = (const float*)d_in[22];
    const float* out_b    = (const float*)d_in[23];

    float *x, *y, *cat, *ca;
    __half *x16, *o16, *h16, *qkv16, *wqkv16, *wo16, *w116, *w216, *wout16;
    cudaGetSymbolAddress((void**)&x,   g_x);
    cudaGetSymbolAddress((void**)&y,   g_y);
    cudaGetSymbolAddress((void**)&cat, g_cat);
    cudaGetSymbolAddress((void**)&ca,  g_ca);
    cudaGetSymbolAddress((void**)&x16, g_x16);
    cudaGetSymbolAddress((void**)&o16, g_o16);
    cudaGetSymbolAddress((void**)&h16, g_h16);
    cudaGetSymbolAddress((void**)&qkv16, g_qkv16);
    cudaGetSymbolAddress((void**)&wqkv16, g_wqkv16);
    cudaGetSymbolAddress((void**)&wo16,   g_wo16);
    cudaGetSymbolAddress((void**)&w116,   g_w116);
    cudaGetSymbolAddress((void**)&w216,   g_w216);
    cudaGetSymbolAddress((void**)&wout16, g_wout16);

    cudaFuncSetAttribute(gemm_fp16, cudaFuncAttributeMaxDynamicSharedMemorySize, GEMM_SMEM);
    cudaFuncSetAttribute(attn_mma,  cudaFuncAttributeMaxDynamicSharedMemorySize, ATT_SMEM);

    // 0: all weight conversions
    const int nb0 = (Ll*3*Dd*Dd) / 1024, nb1 = (Ll*Dd*Dd) / 1024,
              nb2 = (Ll*Ff*Dd) / 1024,   nb3 = (Ll*Dd*Ff) / 1024,
              nb4 = (Vv*Dd) / 1024;
    convert_all<<<nb0 + nb1 + nb2 + nb3 + nb4, 256>>>(
        sa_w_qkv, wqkv16, nb0, sa_w_o, wo16, nb1,
        ffn_w1, w116, nb2, ffn_w2, w216, nb3, out_w, wout16, nb4);

    // 1: embed
    embed_kernel<<<Mm, 256>>>(target, tok_emb, pos_emb, x, x16);

    // 2-4: QKV gemm / attention / O-proj gemm for layer 0 (profiling window)
    gemm_fp16<<<dim3(9, 64), 256, GEMM_SMEM>>>(
        x16, wqkv16, sa_b_qkv, nullptr, qkv16, Mm, QKVS, Dd, 2);
    attn_mma<<<dim3(Ss/16, Hh, Bb), 256, ATT_SMEM>>>(qkv16, o16);
    gemm_fp16<<<dim3(3, 64), 256, GEMM_SMEM>>>(
        o16, wo16, sa_b_o, y, nullptr, Mm, Dd, Dd, 0);

    // hoisted analytic cross-attention vectors for all layers
    const int SGG = (Bb * Dd * 32 + 255) / 256;
    for (int l = 0; l < Ll; ++l) {
        small_gemm<<<SGG, 256>>>(latent, ca_w_qkv + (size_t)l*3*Dd*Dd + (size_t)2*Dd*Dd,
                                 ca_b_qkv + (size_t)l*3*Dd + 2*Dd, cat + l*Bb*Dd, Bb, Dd, Dd);
        small_gemm<<<SGG, 256>>>(cat + l*Bb*Dd, ca_w_o + (size_t)l*Dd*Dd,
                                 ca_b_o + (size_t)l*Dd, ca + l*Bb*Dd, Bb, Dd, Dd);
    }

    for (int l = 0; l < Ll; ++l) {
        if (l > 0) {
            gemm_fp16<<<dim3(9, 64), 256, GEMM_SMEM>>>(
                x16, wqkv16 + (size_t)l*3*Dd*Dd, sa_b_qkv + (size_t)l*3*Dd,
                nullptr, qkv16, Mm, QKVS, Dd, 2);
            attn_mma<<<dim3(Ss/16, Hh, Bb), 256, ATT_SMEM>>>(qkv16, o16);
            gemm_fp16<<<dim3(3, 64), 256, GEMM_SMEM>>>(
                o16, wo16 + (size_t)l*Dd*Dd, sa_b_o + (size_t)l*Dd,
                y, nullptr, Mm, Dd, Dd, 0);
        }
        add_ln_kernel<<<Mm, 256>>>(x, y, ln1_g + (size_t)l*Dd, ln1_b + (size_t)l*Dd, 0,
                                   nullptr);
        add_ln_kernel<<<Mm, 256>>>(x, ca + l*Bb*Dd, ln2_g + (size_t)l*Dd,
                                   ln2_b + (size_t)l*Dd, 1, x16);
        gemm_fp16<<<dim3(8, 64), 256, GEMM_SMEM>>>(
            x16, w116 + (size_t)l*Ff*Dd, ffn_b1 + (size_t)l*Ff,
            nullptr, h16, Mm, Ff, Dd, 1);
        gemm_fp16<<<dim3(3, 64), 256, GEMM_SMEM>>>(
            h16, w216 + (size_t)l*Dd*Ff, ffn_b2 + (size_t)l*Dd,
            y, nullptr, Mm, Dd, Ff, 0);
        add_ln_kernel<<<Mm, 256>>>(x, y, ln3_g + (size_t)l*Dd, ln3_b + (size_t)l*Dd, 0,
                                   x16);
    }

    // output projection
    gemm_fp16<<<dim3(1, 64), 256, GEMM_SMEM>>>(
        x16, wout16, out_b, (float*)d_out, nullptr, Mm, Vv, Dd, 0);
}

// round 6
// speedup vs baseline: 7.3623x; 1.2002x over previous
#include <cuda_runtime.h>
#include <cuda_fp16.h>
#include <stdint.h>
#include <math.h>

// Problem dims
#define Bb   16
#define Ss   512
#define Dd   768
#define Hh   8
#define Vv   100
#define Ff   2048
#define Ll   6
#define DHd  96
#define Mm   (Bb*Ss)   // 8192
#define QKVS (3*Dd)    // 2304

// ================= low-level helpers =================
__device__ __forceinline__ uint32_t smem_u32(const void* p) {
    return (uint32_t)__cvta_generic_to_shared(p);
}
__device__ __forceinline__ void cp_async16(uint32_t dst, const void* src, int szvalid) {
    asm volatile("cp.async.cg.shared.global [%0], [%1], 16, %2;"
                 :: "r"(dst), "l"(src), "r"(szvalid) : "memory");
}
#define CP_COMMIT() asm volatile("cp.async.commit_group;" ::: "memory")
#define CP_WAIT(n)  asm volatile("cp.async.wait_group %0;" :: "n"(n) : "memory")

__device__ __forceinline__ void ldm_x4(uint32_t* r, uint32_t addr) {
    asm volatile("ldmatrix.sync.aligned.m8n8.x4.shared.b16 {%0,%1,%2,%3}, [%4];"
                 : "=r"(r[0]), "=r"(r[1]), "=r"(r[2]), "=r"(r[3]) : "r"(addr));
}
__device__ __forceinline__ void ldm_trans_x4(uint32_t* r, uint32_t addr) {
    asm volatile("ldmatrix.sync.aligned.m8n8.x4.trans.shared.b16 {%0,%1,%2,%3}, [%4];"
                 : "=r"(r[0]), "=r"(r[1]), "=r"(r[2]), "=r"(r[3]) : "r"(addr));
}
__device__ __forceinline__ void mma16816(float* d, const uint32_t* a, const uint32_t* b) {
    asm volatile("mma.sync.aligned.m16n8k16.row.col.f32.f16.f16.f32 "
                 "{%0,%1,%2,%3}, {%4,%5,%6,%7}, {%8,%9}, {%0,%1,%2,%3};"
                 : "+f"(d[0]), "+f"(d[1]), "+f"(d[2]), "+f"(d[3])
                 : "r"(a[0]), "r"(a[1]), "r"(a[2]), "r"(a[3]), "r"(b[0]), "r"(b[1]));
}
__device__ __forceinline__ uint32_t pack_h2(float a, float b) {
    __half2 t = __floats2half2_rn(a, b);
    return *(uint32_t*)&t;
}

// ================= device scratch =================
__device__ float g_x   [Mm * Dd];
__device__ float g_y   [Mm * Dd];
__device__ float g_cat [Ll * Bb * Dd];
__device__ float g_ca  [Ll * Bb * Dd];

__device__ __align__(16) __half g_x16 [Mm * Dd];
__device__ __align__(16) __half g_o16 [Mm * Dd];
__device__ __align__(16) __half g_h16 [Mm * Ff];
__device__ __align__(16) __half g_qkv16[Mm * QKVS];

__device__ __align__(16) __half g_wqkv16[Ll*3*Dd*Dd];
__device__ __align__(16) __half g_wo16  [Ll*Dd*Dd];
__device__ __align__(16) __half g_w116  [Ll*Ff*Dd];
__device__ __align__(16) __half g_w216  [Ll*Dd*Ff];
__device__ __align__(16) __half g_wout16[Vv*Dd];

// ================= weight convert =================
__global__ __launch_bounds__(256) void convert_all(
    const float* __restrict__ s0, __half* __restrict__ d0, int b0,
    const float* __restrict__ s1, __half* __restrict__ d1, int b1,
    const float* __restrict__ s2, __half* __restrict__ d2, int b2,
    const float* __restrict__ s3, __half* __restrict__ d3, int b3,
    const float* __restrict__ s4, __half* __restrict__ d4, int b4)
{
    int bid = blockIdx.x;
    const float* src; __half* dst; int nb;
    if      (bid < b0)          { src = s0; dst = d0; nb = bid; }
    else if (bid < b0+b1)       { src = s1; dst = d1; nb = bid - b0; }
    else if (bid < b0+b1+b2)    { src = s2; dst = d2; nb = bid - b0 - b1; }
    else if (bid < b0+b1+b2+b3) { src = s3; dst = d3; nb = bid - b0 - b1 - b2; }
    else                        { src = s4; dst = d4; nb = bid - b0 - b1 - b2 - b3; }
    int i = (nb * 256 + threadIdx.x) * 4;
    float4 v = *(const float4*)&src[i];
    *(__half2*)&dst[i]     = __floats2half2_rn(v.x, v.y);
    *(__half2*)&dst[i + 2] = __floats2half2_rn(v.z, v.w);
}

// ================= embed =================
__global__ __launch_bounds__(256) void embed_kernel(
    const int* __restrict__ target, const float* __restrict__ tok,
    const float* __restrict__ pos, float* __restrict__ x,
    __half* __restrict__ x16)
{
    int row = blockIdx.x;
    int s   = row & (Ss - 1);
    int t   = target[row];
    const float* tp = tok + (size_t)t * Dd;
    const float* pp = pos + (size_t)s * Dd;
    size_t base = (size_t)row * Dd;
    for (int c = threadIdx.x; c < Dd; c += 256) {
        float v = tp[c] + pp[c];
        x[base + c] = v;
        x16[base + c] = __float2half(v);
    }
}

// ================= fp16 GEMM: CTA 128x256, warp tile 64x64, BK=32, 3 stages =====
#define BKc 32
#define APITCH 80
#define A_TILE_B (128*APITCH)           // 10240
#define W_TILE_B (256*APITCH)           // 20480
#define STAGE_B  (A_TILE_B + W_TILE_B)  // 30720
#define GEMM_SMEM (3*STAGE_B)           // 92160

__global__ void __launch_bounds__(256) gemm_fp16(
    const __half* __restrict__ A, const __half* __restrict__ W,
    const float* __restrict__ bias, float* __restrict__ C,
    __half* __restrict__ Ch,
    int M, int N, int K, int mode)
{
    extern __shared__ char sm[];
    const uint32_t smU = smem_u32(sm);
    const int tid  = threadIdx.x;
    const int lane = tid & 31;
    const int wid  = tid >> 5;
    const int bm   = blockIdx.y * 128;
    const int bn   = blockIdx.x * 256;
    const int wm   = (wid >> 2) * 64;
    const int wn   = (wid & 3) * 64;

    float acc[4][8][4];
    #pragma unroll
    for (int i = 0; i < 4; ++i)
        #pragma unroll
        for (int j = 0; j < 8; ++j)
            #pragma unroll
            for (int r = 0; r < 4; ++r) acc[i][j][r] = 0.f;

    const int NC = K / BKc;

    auto issue = [&](int chunk, int s) {
        const int k0 = chunk * BKc;
        #pragma unroll
        for (int i = 0; i < 6; ++i) {
            int c = tid + 256 * i;      // 0..1535
            if (c < 512) {
                int row = c >> 2, c16 = c & 3;
                uint32_t dst = smU + s * STAGE_B + row * APITCH + c16 * 16;
                cp_async16(dst, (const char*)(A + (size_t)(bm + row) * K + k0) + c16 * 16, 16);
            } else {
                int cw = c - 512;
                int row = cw >> 2, c16 = cw & 3;
                int rn = bn + row;
                uint32_t dst = smU + s * STAGE_B + A_TILE_B + row * APITCH + c16 * 16;
                const char* g = (const char*)(W + (size_t)rn * K + k0) + c16 * 16;
                int sz = 16;
                if (rn >= N) { sz = 0; g = (const char*)W; }
                cp_async16(dst, g, sz);
            }
        }
        CP_COMMIT();
    };

    const int wrow_off = ((lane >> 4) << 3) + (lane & 7);
    const int wcol_off = ((lane >> 3) & 1) * 8;
    const int arow_off = lane & 15;
    const int acol_off = (lane >> 4) << 3;

    auto compute = [&](int s) {
        const uint32_t aB = smU + s * STAGE_B;
        const uint32_t wB = aB + A_TILE_B;
        #pragma unroll
        for (int ks = 0; ks < BKc; ks += 16) {
            uint32_t wh[4][4];
            #pragma unroll
            for (int nb = 0; nb < 4; ++nb)
                ldm_x4(wh[nb], wB + (wn + nb * 16 + wrow_off) * APITCH + (ks + wcol_off) * 2);
            #pragma unroll
            for (int mi = 0; mi < 4; ++mi) {
                uint32_t ah[4];
                ldm_x4(ah, aB + (wm + mi * 16 + arow_off) * APITCH + (ks + acol_off) * 2);
                #pragma unroll
                for (int nb = 0; nb < 4; ++nb) {
                    mma16816(&acc[mi][nb * 2][0],     ah, &wh[nb][0]);
                    mma16816(&acc[mi][nb * 2 + 1][0], ah, &wh[nb][2]);
                }
            }
        }
    };

    issue(0, 0);
    issue(1, 1);
    for (int c = 0; c < NC; ++c) {
        if (c + 2 < NC) {
            issue(c + 2, (c + 2) % 3);
            CP_WAIT(2);
        } else if (c + 1 < NC) {
            CP_WAIT(1);
        } else {
            CP_WAIT(0);
        }
        __syncthreads();
        compute(c % 3);
        __syncthreads();
    }

    float bs[16];
    #pragma unroll
    for (int nj = 0; nj < 8; ++nj) {
        int c0 = bn + wn + nj * 8 + (lane & 3) * 2;
        bs[nj * 2]     = (c0 < N)     ? bias[c0]     : 0.f;
        bs[nj * 2 + 1] = (c0 + 1 < N) ? bias[c0 + 1] : 0.f;
    }
    #pragma unroll
    for (int mi = 0; mi < 4; ++mi) {
        #pragma unroll
        for (int nj = 0; nj < 8; ++nj) {
            int c0 = bn + wn + nj * 8 + (lane & 3) * 2;
            if (c0 >= N) continue;
            #pragma unroll
            for (int p = 0; p < 2; ++p) {
                int row = bm + wm + mi * 16 + (lane >> 2) + p * 8;
                float v0 = acc[mi][nj][p * 2]     + bs[nj * 2];
                float v1 = acc[mi][nj][p * 2 + 1] + bs[nj * 2 + 1];
                if (mode == 0) {
                    *(float2*)(C + (size_t)row * N + c0) = make_float2(v0, v1);
                } else {
                    if (mode == 1) { v0 = fmaxf(v0, 0.f); v1 = fmaxf(v1, 0.f); }
                    *(__half2*)(Ch + (size_t)row * N + c0) = __floats2half2_rn(v0, v1);
                }
            }
        }
    }
}

// ================= tiny GEMM for cross-attn shortcut =================
__global__ __launch_bounds__(256) void small_gemm(
    const float* __restrict__ A, const float* __restrict__ W,
    const float* __restrict__ bias, float* __restrict__ C,
    int Bq, int N, int K)
{
    int wg   = (blockIdx.x * blockDim.x + threadIdx.x) >> 5;
    int lane = threadIdx.x & 31;
    if (wg >= Bq * N) return;
    int bq = wg / N, n = wg - bq * N;
    const float* a = A + (size_t)bq * K;
    const float* w = W + (size_t)n * K;
    float s = 0.f;
    for (int k = lane; k < K; k += 32) s = fmaf(a[k], w[k], s);
    #pragma unroll
    for (int o = 16; o; o >>= 1) s += __shfl_xor_sync(0xffffffffu, s, o);
    if (lane == 0) C[wg] = s + bias[n];
}

// ================= single add+LN (used for ln3) =================
__global__ __launch_bounds__(256) void add_ln_kernel(
    float* __restrict__ x, const float* __restrict__ br,
    const float* __restrict__ g, const float* __restrict__ b,
    __half* __restrict__ x16)
{
    int row = blockIdx.x;
    const float* brp = br + (size_t)row * Dd;
    float* xp = x + (size_t)row * Dd;
    int tid = threadIdx.x;

    float v[3];
    float sum = 0.f, sq = 0.f;
    #pragma unroll
    for (int i = 0; i < 3; ++i) {
        int c = tid + i * 256;
        float t = xp[c] + brp[c];
        v[i] = t; sum += t; sq = fmaf(t, t, sq);
    }
    #pragma unroll
    for (int o = 16; o; o >>= 1) {
        sum += __shfl_xor_sync(0xffffffffu, sum, o);
        sq  += __shfl_xor_sync(0xffffffffu, sq,  o);
    }
    __shared__ float sh1[8], sh2[8];
    int warp = tid >> 5, lane = tid & 31;
    if (lane == 0) { sh1[warp] = sum; sh2[warp] = sq; }
    __syncthreads();
    if (tid == 0) {
        float a = 0.f, c2 = 0.f;
        #pragma unroll
        for (int i = 0; i < 8; ++i) { a += sh1[i]; c2 += sh2[i]; }
        sh1[0] = a; sh2[0] = c2;
    }
    __syncthreads();
    float mu  = sh1[0] * (1.f / Dd);
    float var = sh2[0] * (1.f / Dd) - mu * mu;
    float rs  = rsqrtf(var + 1e-5f);
    #pragma unroll
    for (int i = 0; i < 3; ++i) {
        int c = tid + i * 256;
        float o = (v[i] - mu) * rs * g[c] + b[c];
        xp[c] = o;
        x16[(size_t)row * Dd + c] = __float2half(o);
    }
}

// ================= fused (add+LN1) then (add bcast + LN2) =================
__global__ __launch_bounds__(256) void add_ln2_kernel(
    float* __restrict__ x, const float* __restrict__ y, const float* __restrict__ ca,
    const float* __restrict__ g1, const float* __restrict__ b1,
    const float* __restrict__ g2, const float* __restrict__ b2,
    __half* __restrict__ x16)
{
    int row = blockIdx.x;
    const float* yp  = y  + (size_t)row * Dd;
    const float* cap = ca + (size_t)(row >> 9) * Dd;
    float* xp = x + (size_t)row * Dd;
    int tid = threadIdx.x;
    __shared__ float sh1[8], sh2[8];
    int warp = tid >> 5, lane = tid & 31;

    float v[3];
    float sum = 0.f, sq = 0.f;
    #pragma unroll
    for (int i = 0; i < 3; ++i) {
        int c = tid + i * 256;
        float t = xp[c] + yp[c];
        v[i] = t; sum += t; sq = fmaf(t, t, sq);
    }
    #pragma unroll
    for (int o = 16; o; o >>= 1) {
        sum += __shfl_xor_sync(0xffffffffu, sum, o);
        sq  += __shfl_xor_sync(0xffffffffu, sq,  o);
    }
    if (lane == 0) { sh1[warp] = sum; sh2[warp] = sq; }
    __syncthreads();
    if (tid == 0) {
        float a = 0.f, c2 = 0.f;
        #pragma unroll
        for (int i = 0; i < 8; ++i) { a += sh1[i]; c2 += sh2[i]; }
        sh1[0] = a; sh2[0] = c2;
    }
    __syncthreads();
    float mu = sh1[0] * (1.f / Dd);
    float rs = rsqrtf(sh2[0] * (1.f / Dd) - mu * mu + 1e-5f);
    __syncthreads();

    // second add + LN
    sum = 0.f; sq = 0.f;
    #pragma unroll
    for (int i = 0; i < 3; ++i) {
        int c = tid + i * 256;
        float t = (v[i] - mu) * rs * g1[c] + b1[c] + cap[c];
        v[i] = t; sum += t; sq = fmaf(t, t, sq);
    }
    #pragma unroll
    for (int o = 16; o; o >>= 1) {
        sum += __shfl_xor_sync(0xffffffffu, sum, o);
        sq  += __shfl_xor_sync(0xffffffffu, sq,  o);
    }
    if (lane == 0) { sh1[warp] = sum; sh2[warp] = sq; }
    __syncthreads();
    if (tid == 0) {
        float a = 0.f, c2 = 0.f;
        #pragma unroll
        for (int i = 0; i < 8; ++i) { a += sh1[i]; c2 += sh2[i]; }
        sh1[0] = a; sh2[0] = c2;
    }
    __syncthreads();
    float mu2 = sh1[0] * (1.f / Dd);
    float rs2 = rsqrtf(sh2[0] * (1.f / Dd) - mu2 * mu2 + 1e-5f);
    #pragma unroll
    for (int i = 0; i < 3; ++i) {
        int c = tid + i * 256;
        float o = (v[i] - mu2) * rs2 * g2[c] + b2[c];
        xp[c] = o;
        x16[(size_t)row * Dd + c] = __float2half(o);
    }
}

// ================= flash-attention (mma.sync, online softmax) =================
// CTA = 128 q rows (8 warps x 16), K/V tiles of 32 keys, cp.async double buffer.
// smem: Q 128x208B = 26624; KV 2 stages x (K 6656 + V 6656) = 26624.  total 53248.
#define FATT_SMEM 53248
#define QPITCH 208

__global__ void __launch_bounds__(256) attn_flash(
    const __half* __restrict__ qkv, __half* __restrict__ o16)
{
    extern __shared__ char smd[];
    const int qb  = blockIdx.x * 128;
    const int h   = blockIdx.y;
    const int b   = blockIdx.z;
    const int tid = threadIdx.x;
    const int lane = tid & 31;
    const int wid  = tid >> 5;
    const uint32_t sQ  = smem_u32(smd);
    const uint32_t sKV = sQ + 26624;
    const float scale = rsqrtf((float)DHd);

    // stage Q: 128 rows x 12 16B-chunks
    #pragma unroll
    for (int i = 0; i < 6; ++i) {
        int c = tid + 256 * i;
        int row = c / 12, dc = c - row * 12;
        cp_async16(sQ + row * QPITCH + dc * 16,
                   qkv + (size_t)(b * Ss + qb + row) * QKVS + h * DHd + dc * 8, 16);
    }
    CP_COMMIT();

    auto load_kv = [&](int jt, int s) {
        #pragma unroll
        for (int i = 0; i < 3; ++i) {
            int c = tid + 256 * i;          // 0..767
            int kv = (c >= 384) ? 1 : 0;
            int cc = c - kv * 384;
            int row = cc / 12, dc = cc - row * 12;
            cp_async16(sKV + s * 13312 + kv * 6656 + row * QPITCH + dc * 16,
                       qkv + (size_t)(b * Ss + jt + row) * QKVS + (1 + kv) * Dd
                           + h * DHd + dc * 8, 16);
        }
        CP_COMMIT();
    };

    load_kv(0, 0);
    CP_WAIT(1);            // Q complete (kv0 may still be in flight)
    __syncthreads();

    // preload Q fragments for this warp's 16 rows
    uint32_t qf[6][4];
    {
        uint32_t base = sQ + (wid * 16 + (lane & 15)) * QPITCH + ((lane >> 4) << 3) * 2;
        #pragma unroll
        for (int ks = 0; ks < 6; ++ks)
            ldm_x4(qf[ks], base + ks * 32);
    }

    float oacc[12][4];
    #pragma unroll
    for (int i = 0; i < 12; ++i)
        #pragma unroll
        for (int r = 0; r < 4; ++r) oacc[i][r] = 0.f;
    float m0 = -1e30f, m1 = -1e30f, l0 = 0.f, l1 = 0.f;

    const int ntiles  = (qb + 128) / 32;
    const int my_last = qb + wid * 16 + 15;   // last key this warp can see
    const int r0g     = qb + wid * 16 + (lane >> 2);

    for (int t = 0; t < ntiles; ++t) {
        const int jt = t * 32;
        if (t + 1 < ntiles) {
            load_kv((t + 1) * 32, (t + 1) & 1);
            CP_WAIT(1);
        } else {
            CP_WAIT(0);
        }
        __syncthreads();

        if (jt <= my_last) {
            const uint32_t kb = sKV + (t & 1) * 13312;
            const uint32_t vb = kb + 6656;

            // ---- S = Q K^T for 32 keys ----
            float sacc[4][4];
            #pragma unroll
            for (int i = 0; i < 4; ++i)
                #pragma unroll
                for (int r = 0; r < 4; ++r) sacc[i][r] = 0.f;
            const uint32_t kbase = kb + ((lane & 7) + ((lane >> 4) << 3)) * QPITCH
                                 + (((lane >> 3) & 1) << 4);
            #pragma unroll
            for (int ks = 0; ks < 6; ++ks) {
                uint32_t kf[4], kg[4];
                ldm_x4(kf, kbase + ks * 32);
                ldm_x4(kg, kbase + 16 * QPITCH + ks * 32);
                mma16816(sacc[0], qf[ks], &kf[0]);
                mma16816(sacc[1], qf[ks], &kf[2]);
                mma16816(sacc[2], qf[ks], &kg[0]);
                mma16816(sacc[3], qf[ks], &kg[2]);
            }

            // ---- scale + causal mask ----
            #pragma unroll
            for (int nb = 0; nb < 4; ++nb)
                #pragma unroll
                for (int e = 0; e < 4; ++e) {
                    int j = jt + nb * 8 + (lane & 3) * 2 + (e & 1);
                    int r = r0g + ((e >> 1) << 3);
                    float v = sacc[nb][e] * scale;
                    sacc[nb][e] = (j <= r) ? v : -1e30f;
                }

            // ---- online softmax update ----
            float mx0 = -1e30f, mx1 = -1e30f;
            #pragma unroll
            for (int nb = 0; nb < 4; ++nb) {
                mx0 = fmaxf(mx0, fmaxf(sacc[nb][0], sacc[nb][1]));
                mx1 = fmaxf(mx1, fmaxf(sacc[nb][2], sacc[nb][3]));
            }
            mx0 = fmaxf(mx0, __shfl_xor_sync(0xffffffffu, mx0, 1));
            mx0 = fmaxf(mx0, __shfl_xor_sync(0xffffffffu, mx0, 2));
            mx1 = fmaxf(mx1, __shfl_xor_sync(0xffffffffu, mx1, 1));
            mx1 = fmaxf(mx1, __shfl_xor_sync(0xffffffffu, mx1, 2));
            float mn0 = fmaxf(m0, mx0), mn1 = fmaxf(m1, mx1);
            float f0 = __expf(m0 - mn0), f1 = __expf(m1 - mn1);
            m0 = mn0; m1 = mn1;

            float s0 = 0.f, s1 = 0.f;
            #pragma unroll
            for (int nb = 0; nb < 4; ++nb) {
                float p0 = __expf(sacc[nb][0] - mn0);
                float p1 = __expf(sacc[nb][1] - mn0);
                float p2 = __expf(sacc[nb][2] - mn1);
                float p3 = __expf(sacc[nb][3] - mn1);
                sacc[nb][0] = p0; sacc[nb][1] = p1;
                sacc[nb][2] = p2; sacc[nb][3] = p3;
                s0 += p0 + p1; s1 += p2 + p3;
            }
            s0 += __shfl_xor_sync(0xffffffffu, s0, 1);
            s0 += __shfl_xor_sync(0xffffffffu, s0, 2);
            s1 += __shfl_xor_sync(0xffffffffu, s1, 1);
            s1 += __shfl_xor_sync(0xffffffffu, s1, 2);
            l0 = l0 * f0 + s0;
            l1 = l1 * f1 + s1;
            #pragma unroll
            for (int c6 = 0; c6 < 12; ++c6) {
                oacc[c6][0] *= f0; oacc[c6][1] *= f0;
                oacc[c6][2] *= f1; oacc[c6][3] *= f1;
            }

            // ---- pack P as A-fragments (2 ksteps of 16 keys) ----
            uint32_t pa[2][4];
            #pragma unroll
            for (int kk = 0; kk < 2; ++kk) {
                pa[kk][0] = pack_h2(sacc[kk*2][0],   sacc[kk*2][1]);
                pa[kk][1] = pack_h2(sacc[kk*2][2],   sacc[kk*2][3]);
                pa[kk][2] = pack_h2(sacc[kk*2+1][0], sacc[kk*2+1][1]);
                pa[kk][3] = pack_h2(sacc[kk*2+1][2], sacc[kk*2+1][3]);
            }

            // ---- O += P V ----
            const uint32_t vrow = vb + ((lane & 7) + (((lane >> 3) & 1) << 3)) * QPITCH;
            #pragma unroll
            for (int kk = 0; kk < 2; ++kk) {
                #pragma unroll
                for (int c6 = 0; c6 < 6; ++c6) {
                    uint32_t vf[4];
                    ldm_trans_x4(vf, vrow + kk * 16 * QPITCH
                                     + (c6 * 16 + ((lane >> 4) << 3)) * 2);
                    mma16816(oacc[c6 * 2],     pa[kk], &vf[0]);
                    mma16816(oacc[c6 * 2 + 1], pa[kk], &vf[2]);
                }
            }
        }
        __syncthreads();
    }

    // ---- epilogue ----
    float il0 = 1.f / l0, il1 = 1.f / l1;
    #pragma unroll
    for (int c6 = 0; c6 < 12; ++c6) {
        int col = h * DHd + c6 * 8 + (lane & 3) * 2;
        *(__half2*)(o16 + (size_t)(b * Ss + r0g) * Dd + col) =
            __floats2half2_rn(oacc[c6][0] * il0, oacc[c6][1] * il0);
        *(__half2*)(o16 + (size_t)(b * Ss + r0g + 8) * Dd + col) =
            __floats2half2_rn(oacc[c6][2] * il1, oacc[c6][3] * il1);
    }
}

// ================= launcher =================
extern "C" void kernel_launch(void* const* d_in, const int* in_sizes, int n_in,
                              void* d_out, int out_size)
{
    (void)in_sizes; (void)n_in; (void)out_size;
    const float* latent   = (const float*)d_in[0];
    const int*   target   = (const int*)  d_in[1];
    const float* tok_emb  = (const float*)d_in[2];
    const float* pos_emb  = (const float*)d_in[3];
    const float* sa_w_qkv = (const float*)d_in[4];
    const float* sa_b_qkv = (const float*)d_in[5];
    const float* sa_w_o   = (const float*)d_in[6];
    const float* sa_b_o   = (const float*)d_in[7];
    const float* ca_w_qkv = (const float*)d_in[8];
    const float* ca_b_qkv = (const float*)d_in[9];
    const float* ca_w_o   = (const float*)d_in[10];
    const float* ca_b_o   = (const float*)d_in[11];
    const float* ffn_w1   = (const float*)d_in[12];
    const float* ffn_b1   = (const float*)d_in[13];
    const float* ffn_w2   = (const float*)d_in[14];
    const float* ffn_b2   = (const float*)d_in[15];
    const float* ln1_g    = (const float*)d_in[16];
    const float* ln1_b    = (const float*)d_in[17];
    const float* ln2_g    = (const float*)d_in[18];
    const float* ln2_b    = (const float*)d_in[19];
    const float* ln3_g    = (const float*)d_in[20];
    const float* ln3_b    = (const float*)d_in[21];
    const float* out_w    = (const float*)d_in[22];
    const float* out_b    = (const float*)d_in[23];

    float *x, *y, *cat, *ca;
    __half *x16, *o16, *h16, *qkv16, *wqkv16, *wo16, *w116, *w216, *wout16;
    cudaGetSymbolAddress((void**)&x,   g_x);
    cudaGetSymbolAddress((void**)&y,   g_y);
    cudaGetSymbolAddress((void**)&cat, g_cat);
    cudaGetSymbolAddress((void**)&ca,  g_ca);
    cudaGetSymbolAddress((void**)&x16, g_x16);
    cudaGetSymbolAddress((void**)&o16, g_o16);
    cudaGetSymbolAddress((void**)&h16, g_h16);
    cudaGetSymbolAddress((void**)&qkv16, g_qkv16);
    cudaGetSymbolAddress((void**)&wqkv16, g_wqkv16);
    cudaGetSymbolAddress((void**)&wo16,   g_wo16);
    cudaGetSymbolAddress((void**)&w116,   g_w116);
    cudaGetSymbolAddress((void**)&w216,   g_w216);
    cudaGetSymbolAddress((void**)&wout16, g_wout16);

    cudaFuncSetAttribute(gemm_fp16,  cudaFuncAttributeMaxDynamicSharedMemorySize, GEMM_SMEM);
    cudaFuncSetAttribute(attn_flash, cudaFuncAttributeMaxDynamicSharedMemorySize, FATT_SMEM);

    // 0: weight conversions
    const int nb0 = (Ll*3*Dd*Dd) / 1024, nb1 = (Ll*Dd*Dd) / 1024,
              nb2 = (Ll*Ff*Dd) / 1024,   nb3 = (Ll*Dd*Ff) / 1024,
              nb4 = (Vv*Dd) / 1024;
    convert_all<<<nb0 + nb1 + nb2 + nb3 + nb4, 256>>>(
        sa_w_qkv, wqkv16, nb0, sa_w_o, wo16, nb1,
        ffn_w1, w116, nb2, ffn_w2, w216, nb3, out_w, wout16, nb4);

    // 1: embed
    embed_kernel<<<Mm, 256>>>(target, tok_emb, pos_emb, x, x16);

    // 2: QKV gemm (layer 0), 3: flash attention (profiling slot), 4: O-proj
    gemm_fp16<<<dim3(9, 64), 256, GEMM_SMEM>>>(
        x16, wqkv16, sa_b_qkv, nullptr, qkv16, Mm, QKVS, Dd, 2);
    attn_flash<<<dim3(Ss/128, Hh, Bb), 256, FATT_SMEM>>>(qkv16, o16);
    gemm_fp16<<<dim3(3, 64), 256, GEMM_SMEM>>>(
        o16, wo16, sa_b_o, y, nullptr, Mm, Dd, Dd, 0);

    // hoisted analytic cross-attention vectors
    const int SGG = (Bb * Dd * 32 + 255) / 256;
    for (int l = 0; l < Ll; ++l) {
        small_gemm<<<SGG, 256>>>(latent, ca_w_qkv + (size_t)l*3*Dd*Dd + (size_t)2*Dd*Dd,
                                 ca_b_qkv + (size_t)l*3*Dd + 2*Dd, cat + l*Bb*Dd, Bb, Dd, Dd);
        small_gemm<<<SGG, 256>>>(cat + l*Bb*Dd, ca_w_o + (size_t)l*Dd*Dd,
                                 ca_b_o + (size_t)l*Dd, ca + l*Bb*Dd, Bb, Dd, Dd);
    }

    for (int l = 0; l < Ll; ++l) {
        if (l > 0) {
            gemm_fp16<<<dim3(9, 64), 256, GEMM_SMEM>>>(
                x16, wqkv16 + (size_t)l*3*Dd*Dd, sa_b_qkv + (size_t)l*3*Dd,
                nullptr, qkv16, Mm, QKVS, Dd, 2);
            attn_flash<<<dim3(Ss/128, Hh, Bb), 256, FATT_SMEM>>>(qkv16, o16);
            gemm_fp16<<<dim3(3, 64), 256, GEMM_SMEM>>>(
                o16, wo16 + (size_t)l*Dd*Dd, sa_b_o + (size_t)l*Dd,
                y, nullptr, Mm, Dd, Dd, 0);
        }
        // fused ln1 + (cross-attn add) + ln2
        add_ln2_kernel<<<Mm, 256>>>(x, y, ca + l*Bb*Dd,
                                    ln1_g + (size_t)l*Dd, ln1_b + (size_t)l*Dd,
                                    ln2_g + (size_t)l*Dd, ln2_b + (size_t)l*Dd, x16);
        gemm_fp16<<<dim3(8, 64), 256, GEMM_SMEM>>>(
            x16, w116 + (size_t)l*Ff*Dd, ffn_b1 + (size_t)l*Ff,
            nullptr, h16, Mm, Ff, Dd, 1);
        gemm_fp16<<<dim3(3, 64), 256, GEMM_SMEM>>>(
            h16, w216 + (size_t)l*Dd*Ff, ffn_b2 + (size_t)l*Dd,
            y, nullptr, Mm, Dd, Ff, 0);
        add_ln_kernel<<<Mm, 256>>>(x, y, ln3_g + (size_t)l*Dd, ln3_b + (size_t)l*Dd,
                                   x16);
    }

    // output projection
    gemm_fp16<<<dim3(1, 64), 256, GEMM_SMEM>>>(
        x16, wout16, out_b, (float*)d_out, nullptr, Mm, Vv, Dd, 0);
}

// round 7
// speedup vs baseline: 9.4278x; 1.2806x over previous
#include <cuda_runtime.h>
#include <cuda_fp16.h>
#include <stdint.h>
#include <math.h>

// Problem dims
#define Bb   16
#define Ss   512
#define Dd   768
#define Hh   8
#define Vv   100
#define Ff   2048
#define Ll   6
#define DHd  96
#define Mm   (Bb*Ss)   // 8192
#define QKVS (3*Dd)    // 2304

// ================= low-level helpers =================
__device__ __forceinline__ uint32_t smem_u32(const void* p) {
    return (uint32_t)__cvta_generic_to_shared(p);
}
__device__ __forceinline__ void cp_async16(uint32_t dst, const void* src, int szvalid) {
    asm volatile("cp.async.cg.shared.global [%0], [%1], 16, %2;"
                 :: "r"(dst), "l"(src), "r"(szvalid) : "memory");
}
#define CP_COMMIT() asm volatile("cp.async.commit_group;" ::: "memory")
#define CP_WAIT(n)  asm volatile("cp.async.wait_group %0;" :: "n"(n) : "memory")

__device__ __forceinline__ void ldm_x4(uint32_t* r, uint32_t addr) {
    asm volatile("ldmatrix.sync.aligned.m8n8.x4.shared.b16 {%0,%1,%2,%3}, [%4];"
                 : "=r"(r[0]), "=r"(r[1]), "=r"(r[2]), "=r"(r[3]) : "r"(addr));
}
__device__ __forceinline__ void ldm_trans_x4(uint32_t* r, uint32_t addr) {
    asm volatile("ldmatrix.sync.aligned.m8n8.x4.trans.shared.b16 {%0,%1,%2,%3}, [%4];"
                 : "=r"(r[0]), "=r"(r[1]), "=r"(r[2]), "=r"(r[3]) : "r"(addr));
}
__device__ __forceinline__ void mma16816(float* d, const uint32_t* a, const uint32_t* b) {
    asm volatile("mma.sync.aligned.m16n8k16.row.col.f32.f16.f16.f32 "
                 "{%0,%1,%2,%3}, {%4,%5,%6,%7}, {%8,%9}, {%0,%1,%2,%3};"
                 : "+f"(d[0]), "+f"(d[1]), "+f"(d[2]), "+f"(d[3])
                 : "r"(a[0]), "r"(a[1]), "r"(a[2]), "r"(a[3]), "r"(b[0]), "r"(b[1]));
}
__device__ __forceinline__ uint32_t pack_h2(float a, float b) {
    __half2 t = __floats2half2_rn(a, b);
    return *(uint32_t*)&t;
}

// ================= device scratch =================
__device__ float g_x   [Mm * Dd];
__device__ float g_y   [Mm * Dd];
__device__ float g_cat [Ll * Bb * Dd];
__device__ float g_ca  [Ll * Bb * Dd];

__device__ __align__(16) __half g_x16 [Mm * Dd];
__device__ __align__(16) __half g_o16 [Mm * Dd];
__device__ __align__(16) __half g_h16 [Mm * Ff];
__device__ __align__(16) __half g_qkv16[Mm * QKVS];

__device__ __align__(16) __half g_wqkv16[Ll*3*Dd*Dd];
__device__ __align__(16) __half g_wo16  [Ll*Dd*Dd];
__device__ __align__(16) __half g_w116  [Ll*Ff*Dd];
__device__ __align__(16) __half g_w216  [Ll*Dd*Ff];
__device__ __align__(16) __half g_wout16[Vv*Dd];

// ================= weight convert =================
__global__ __launch_bounds__(256) void convert_all(
    const float* __restrict__ s0, __half* __restrict__ d0, int b0,
    const float* __restrict__ s1, __half* __restrict__ d1, int b1,
    const float* __restrict__ s2, __half* __restrict__ d2, int b2,
    const float* __restrict__ s3, __half* __restrict__ d3, int b3,
    const float* __restrict__ s4, __half* __restrict__ d4, int b4)
{
    int bid = blockIdx.x;
    const float* src; __half* dst; int nb;
    if      (bid < b0)          { src = s0; dst = d0; nb = bid; }
    else if (bid < b0+b1)       { src = s1; dst = d1; nb = bid - b0; }
    else if (bid < b0+b1+b2)    { src = s2; dst = d2; nb = bid - b0 - b1; }
    else if (bid < b0+b1+b2+b3) { src = s3; dst = d3; nb = bid - b0 - b1 - b2; }
    else                        { src = s4; dst = d4; nb = bid - b0 - b1 - b2 - b3; }
    int i = (nb * 256 + threadIdx.x) * 4;
    float4 v = *(const float4*)&src[i];
    *(__half2*)&dst[i]     = __floats2half2_rn(v.x, v.y);
    *(__half2*)&dst[i + 2] = __floats2half2_rn(v.z, v.w);
}

// ================= embed =================
__global__ __launch_bounds__(256) void embed_kernel(
    const int* __restrict__ target, const float* __restrict__ tok,
    const float* __restrict__ pos, float* __restrict__ x,
    __half* __restrict__ x16)
{
    int row = blockIdx.x;
    int s   = row & (Ss - 1);
    int t   = target[row];
    const float* tp = tok + (size_t)t * Dd;
    const float* pp = pos + (size_t)s * Dd;
    size_t base = (size_t)row * Dd;
    for (int c = threadIdx.x; c < Dd; c += 256) {
        float v = tp[c] + pp[c];
        x[base + c] = v;
        x16[base + c] = __float2half(v);
    }
}

// ================= fp16 GEMM: CTA 128x128, 4 warps, warp tile 64x64 =============
// BK=32, 2-stage cp.async, 3 CTAs/SM target.
// mode 0: fp32 out + bias. mode 1: relu + fp16 out. mode 2: fp16 out (no relu).
#define BKc 32
#define APITCH 80
#define T128_B   (128*APITCH)           // 10240 per operand tile
#define STAGE_B  (2*T128_B)             // 20480 per stage (A + W)
#define GEMM_SMEM (2*STAGE_B)           // 40960

__global__ void __launch_bounds__(128, 3) gemm_fp16(
    const __half* __restrict__ A, const __half* __restrict__ W,
    const float* __restrict__ bias, float* __restrict__ C,
    __half* __restrict__ Ch,
    int M, int N, int K, int mode)
{
    extern __shared__ char sm[];
    const uint32_t smU = smem_u32(sm);
    const int tid  = threadIdx.x;
    const int lane = tid & 31;
    const int wid  = tid >> 5;          // 0..3
    const int bm   = blockIdx.y * 128;
    const int bn   = blockIdx.x * 128;
    const int wm   = (wid >> 1) * 64;
    const int wn   = (wid & 1) * 64;

    float acc[4][8][4];
    #pragma unroll
    for (int i = 0; i < 4; ++i)
        #pragma unroll
        for (int j = 0; j < 8; ++j)
            #pragma unroll
            for (int r = 0; r < 4; ++r) acc[i][j][r] = 0.f;

    const int NC = K / BKc;

    auto issue = [&](int chunk, int s) {
        const int k0 = chunk * BKc;
        // A: 128 rows x 4 chunks = 512 chunks; 128 threads x 4 iters
        #pragma unroll
        for (int i = 0; i < 4; ++i) {
            int c = tid + 128 * i;
            int row = c >> 2, c16 = c & 3;
            cp_async16(smU + s * STAGE_B + row * APITCH + c16 * 16,
                       (const char*)(A + (size_t)(bm + row) * K + k0) + c16 * 16, 16);
        }
        // W: 128 rows x 4 chunks
        #pragma unroll
        for (int i = 0; i < 4; ++i) {
            int c = tid + 128 * i;
            int row = c >> 2, c16 = c & 3;
            int rn = bn + row;
            const char* g = (const char*)(W + (size_t)rn * K + k0) + c16 * 16;
            int sz = 16;
            if (rn >= N) { sz = 0; g = (const char*)W; }
            cp_async16(smU + s * STAGE_B + T128_B + row * APITCH + c16 * 16, g, sz);
        }
        CP_COMMIT();
    };

    const int wrow_off = ((lane >> 4) << 3) + (lane & 7);
    const int wcol_off = ((lane >> 3) & 1) * 8;
    const int arow_off = lane & 15;
    const int acol_off = (lane >> 4) << 3;

    auto compute = [&](int s) {
        const uint32_t aB = smU + s * STAGE_B;
        const uint32_t wB = aB + T128_B;
        #pragma unroll
        for (int ks = 0; ks < BKc; ks += 16) {
            uint32_t wh[4][4];
            #pragma unroll
            for (int nb = 0; nb < 4; ++nb)
                ldm_x4(wh[nb], wB + (wn + nb * 16 + wrow_off) * APITCH + (ks + wcol_off) * 2);
            #pragma unroll
            for (int mi = 0; mi < 4; ++mi) {
                uint32_t ah[4];
                ldm_x4(ah, aB + (wm + mi * 16 + arow_off) * APITCH + (ks + acol_off) * 2);
                #pragma unroll
                for (int nb = 0; nb < 4; ++nb) {
                    mma16816(&acc[mi][nb * 2][0],     ah, &wh[nb][0]);
                    mma16816(&acc[mi][nb * 2 + 1][0], ah, &wh[nb][2]);
                }
            }
        }
    };

    issue(0, 0);
    for (int c = 0; c < NC; ++c) {
        if (c + 1 < NC) {
            issue(c + 1, (c + 1) & 1);
            CP_WAIT(1);
        } else {
            CP_WAIT(0);
        }
        __syncthreads();
        compute(c & 1);
        __syncthreads();
    }

    float bs[16];
    #pragma unroll
    for (int nj = 0; nj < 8; ++nj) {
        int c0 = bn + wn + nj * 8 + (lane & 3) * 2;
        bs[nj * 2]     = (c0 < N)     ? bias[c0]     : 0.f;
        bs[nj * 2 + 1] = (c0 + 1 < N) ? bias[c0 + 1] : 0.f;
    }
    #pragma unroll
    for (int mi = 0; mi < 4; ++mi) {
        #pragma unroll
        for (int nj = 0; nj < 8; ++nj) {
            int c0 = bn + wn + nj * 8 + (lane & 3) * 2;
            if (c0 >= N) continue;
            #pragma unroll
            for (int p = 0; p < 2; ++p) {
                int row = bm + wm + mi * 16 + (lane >> 2) + p * 8;
                float v0 = acc[mi][nj][p * 2]     + bs[nj * 2];
                float v1 = acc[mi][nj][p * 2 + 1] + bs[nj * 2 + 1];
                if (mode == 0) {
                    *(float2*)(C + (size_t)row * N + c0) = make_float2(v0, v1);
                } else {
                    if (mode == 1) { v0 = fmaxf(v0, 0.f); v1 = fmaxf(v1, 0.f); }
                    *(__half2*)(Ch + (size_t)row * N + c0) = __floats2half2_rn(v0, v1);
                }
            }
        }
    }
}

// ================= batched tiny GEMM (all layers in one launch) =================
// out[l, bq, n] = A[l? or shared][bq, :] . W[l, n, :] + bias[l, n]
__global__ __launch_bounds__(256) void small_gemm_all(
    const float* __restrict__ A, int aStrideL,
    const float* __restrict__ W, size_t wStrideL,
    const float* __restrict__ bias, int biasStrideL,
    float* __restrict__ C)
{
    int wg   = blockIdx.x * 8 + (threadIdx.x >> 5);
    int lane = threadIdx.x & 31;
    if (wg >= Ll * Bb * Dd) return;
    int l  = wg / (Bb * Dd);
    int r  = wg - l * (Bb * Dd);
    int bq = r / Dd;
    int n  = r - bq * Dd;
    const float* a = A + (size_t)l * aStrideL + (size_t)bq * Dd;
    const float* w = W + (size_t)l * wStrideL + (size_t)n * Dd;
    float s = 0.f;
    #pragma unroll 4
    for (int k = lane; k < Dd; k += 32) s = fmaf(a[k], w[k], s);
    #pragma unroll
    for (int o = 16; o; o >>= 1) s += __shfl_xor_sync(0xffffffffu, s, o);
    if (lane == 0) C[wg] = s + bias[(size_t)l * biasStrideL + n];
}

// ================= single add+LN (used for ln3) =================
__global__ __launch_bounds__(256) void add_ln_kernel(
    float* __restrict__ x, const float* __restrict__ br,
    const float* __restrict__ g, const float* __restrict__ b,
    __half* __restrict__ x16)
{
    int row = blockIdx.x;
    const float* brp = br + (size_t)row * Dd;
    float* xp = x + (size_t)row * Dd;
    int tid = threadIdx.x;

    float v[3];
    float sum = 0.f, sq = 0.f;
    #pragma unroll
    for (int i = 0; i < 3; ++i) {
        int c = tid + i * 256;
        float t = xp[c] + brp[c];
        v[i] = t; sum += t; sq = fmaf(t, t, sq);
    }
    #pragma unroll
    for (int o = 16; o; o >>= 1) {
        sum += __shfl_xor_sync(0xffffffffu, sum, o);
        sq  += __shfl_xor_sync(0xffffffffu, sq,  o);
    }
    __shared__ float sh1[8], sh2[8];
    int warp = tid >> 5, lane = tid & 31;
    if (lane == 0) { sh1[warp] = sum; sh2[warp] = sq; }
    __syncthreads();
    if (tid == 0) {
        float a = 0.f, c2 = 0.f;
        #pragma unroll
        for (int i = 0; i < 8; ++i) { a += sh1[i]; c2 += sh2[i]; }
        sh1[0] = a; sh2[0] = c2;
    }
    __syncthreads();
    float mu  = sh1[0] * (1.f / Dd);
    float var = sh2[0] * (1.f / Dd) - mu * mu;
    float rs  = rsqrtf(var + 1e-5f);
    #pragma unroll
    for (int i = 0; i < 3; ++i) {
        int c = tid + i * 256;
        float o = (v[i] - mu) * rs * g[c] + b[c];
        xp[c] = o;
        x16[(size_t)row * Dd + c] = __float2half(o);
    }
}

// ================= fused (add+LN1) then (add bcast + LN2) =================
__global__ __launch_bounds__(256) void add_ln2_kernel(
    float* __restrict__ x, const float* __restrict__ y, const float* __restrict__ ca,
    const float* __restrict__ g1, const float* __restrict__ b1,
    const float* __restrict__ g2, const float* __restrict__ b2,
    __half* __restrict__ x16)
{
    int row = blockIdx.x;
    const float* yp  = y  + (size_t)row * Dd;
    const float* cap = ca + (size_t)(row >> 9) * Dd;
    float* xp = x + (size_t)row * Dd;
    int tid = threadIdx.x;
    __shared__ float sh1[8], sh2[8];
    int warp = tid >> 5, lane = tid & 31;

    float v[3];
    float sum = 0.f, sq = 0.f;
    #pragma unroll
    for (int i = 0; i < 3; ++i) {
        int c = tid + i * 256;
        float t = xp[c] + yp[c];
        v[i] = t; sum += t; sq = fmaf(t, t, sq);
    }
    #pragma unroll
    for (int o = 16; o; o >>= 1) {
        sum += __shfl_xor_sync(0xffffffffu, sum, o);
        sq  += __shfl_xor_sync(0xffffffffu, sq,  o);
    }
    if (lane == 0) { sh1[warp] = sum; sh2[warp] = sq; }
    __syncthreads();
    if (tid == 0) {
        float a = 0.f, c2 = 0.f;
        #pragma unroll
        for (int i = 0; i < 8; ++i) { a += sh1[i]; c2 += sh2[i]; }
        sh1[0] = a; sh2[0] = c2;
    }
    __syncthreads();
    float mu = sh1[0] * (1.f / Dd);
    float rs = rsqrtf(sh2[0] * (1.f / Dd) - mu * mu + 1e-5f);
    __syncthreads();

    sum = 0.f; sq = 0.f;
    #pragma unroll
    for (int i = 0; i < 3; ++i) {
        int c = tid + i * 256;
        float t = (v[i] - mu) * rs * g1[c] + b1[c] + cap[c];
        v[i] = t; sum += t; sq = fmaf(t, t, sq);
    }
    #pragma unroll
    for (int o = 16; o; o >>= 1) {
        sum += __shfl_xor_sync(0xffffffffu, sum, o);
        sq  += __shfl_xor_sync(0xffffffffu, sq,  o);
    }
    if (lane == 0) { sh1[warp] = sum; sh2[warp] = sq; }
    __syncthreads();
    if (tid == 0) {
        float a = 0.f, c2 = 0.f;
        #pragma unroll
        for (int i = 0; i < 8; ++i) { a += sh1[i]; c2 += sh2[i]; }
        sh1[0] = a; sh2[0] = c2;
    }
    __syncthreads();
    float mu2 = sh1[0] * (1.f / Dd);
    float rs2 = rsqrtf(sh2[0] * (1.f / Dd) - mu2 * mu2 + 1e-5f);
    #pragma unroll
    for (int i = 0; i < 3; ++i) {
        int c = tid + i * 256;
        float o = (v[i] - mu2) * rs2 * g2[c] + b2[c];
        xp[c] = o;
        x16[(size_t)row * Dd + c] = __float2half(o);
    }
}

// ================= flash-attention (mma.sync, online softmax) =================
#define FATT_SMEM 53248
#define QPITCH 208

__global__ void __launch_bounds__(256) attn_flash(
    const __half* __restrict__ qkv, __half* __restrict__ o16)
{
    extern __shared__ char smd[];
    const int qb  = blockIdx.x * 128;
    const int h   = blockIdx.y;
    const int b   = blockIdx.z;
    const int tid = threadIdx.x;
    const int lane = tid & 31;
    const int wid  = tid >> 5;
    const uint32_t sQ  = smem_u32(smd);
    const uint32_t sKV = sQ + 26624;
    const float scale = rsqrtf((float)DHd);

    #pragma unroll
    for (int i = 0; i < 6; ++i) {
        int c = tid + 256 * i;
        int row = c / 12, dc = c - row * 12;
        cp_async16(sQ + row * QPITCH + dc * 16,
                   qkv + (size_t)(b * Ss + qb + row) * QKVS + h * DHd + dc * 8, 16);
    }
    CP_COMMIT();

    auto load_kv = [&](int jt, int s) {
        #pragma unroll
        for (int i = 0; i < 3; ++i) {
            int c = tid + 256 * i;
            int kv = (c >= 384) ? 1 : 0;
            int cc = c - kv * 384;
            int row = cc / 12, dc = cc - row * 12;
            cp_async16(sKV + s * 13312 + kv * 6656 + row * QPITCH + dc * 16,
                       qkv + (size_t)(b * Ss + jt + row) * QKVS + (1 + kv) * Dd
                           + h * DHd + dc * 8, 16);
        }
        CP_COMMIT();
    };

    load_kv(0, 0);
    CP_WAIT(1);
    __syncthreads();

    uint32_t qf[6][4];
    {
        uint32_t base = sQ + (wid * 16 + (lane & 15)) * QPITCH + ((lane >> 4) << 3) * 2;
        #pragma unroll
        for (int ks = 0; ks < 6; ++ks)
            ldm_x4(qf[ks], base + ks * 32);
    }

    float oacc[12][4];
    #pragma unroll
    for (int i = 0; i < 12; ++i)
        #pragma unroll
        for (int r = 0; r < 4; ++r) oacc[i][r] = 0.f;
    float m0 = -1e30f, m1 = -1e30f, l0 = 0.f, l1 = 0.f;

    const int ntiles  = (qb + 128) / 32;
    const int my_last = qb + wid * 16 + 15;
    const int r0g     = qb + wid * 16 + (lane >> 2);

    for (int t = 0; t < ntiles; ++t) {
        const int jt = t * 32;
        if (t + 1 < ntiles) {
            load_kv((t + 1) * 32, (t + 1) & 1);
            CP_WAIT(1);
        } else {
            CP_WAIT(0);
        }
        __syncthreads();

        if (jt <= my_last) {
            const uint32_t kb = sKV + (t & 1) * 13312;
            const uint32_t vb = kb + 6656;

            float sacc[4][4];
            #pragma unroll
            for (int i = 0; i < 4; ++i)
                #pragma unroll
                for (int r = 0; r < 4; ++r) sacc[i][r] = 0.f;
            const uint32_t kbase = kb + ((lane & 7) + ((lane >> 4) << 3)) * QPITCH
                                 + (((lane >> 3) & 1) << 4);
            #pragma unroll
            for (int ks = 0; ks < 6; ++ks) {
                uint32_t kf[4], kg[4];
                ldm_x4(kf, kbase + ks * 32);
                ldm_x4(kg, kbase + 16 * QPITCH + ks * 32);
                mma16816(sacc[0], qf[ks], &kf[0]);
                mma16816(sacc[1], qf[ks], &kf[2]);
                mma16816(sacc[2], qf[ks], &kg[0]);
                mma16816(sacc[3], qf[ks], &kg[2]);
            }

            #pragma unroll
            for (int nb = 0; nb < 4; ++nb)
                #pragma unroll
                for (int e = 0; e < 4; ++e) {
                    int j = jt + nb * 8 + (lane & 3) * 2 + (e & 1);
                    int r = r0g + ((e >> 1) << 3);
                    float v = sacc[nb][e] * scale;
                    sacc[nb][e] = (j <= r) ? v : -1e30f;
                }

            float mx0 = -1e30f, mx1 = -1e30f;
            #pragma unroll
            for (int nb = 0; nb < 4; ++nb) {
                mx0 = fmaxf(mx0, fmaxf(sacc[nb][0], sacc[nb][1]));
                mx1 = fmaxf(mx1, fmaxf(sacc[nb][2], sacc[nb][3]));
            }
            mx0 = fmaxf(mx0, __shfl_xor_sync(0xffffffffu, mx0, 1));
            mx0 = fmaxf(mx0, __shfl_xor_sync(0xffffffffu, mx0, 2));
            mx1 = fmaxf(mx1, __shfl_xor_sync(0xffffffffu, mx1, 1));
            mx1 = fmaxf(mx1, __shfl_xor_sync(0xffffffffu, mx1, 2));
            float mn0 = fmaxf(m0, mx0), mn1 = fmaxf(m1, mx1);
            float f0 = __expf(m0 - mn0), f1 = __expf(m1 - mn1);
            m0 = mn0; m1 = mn1;

            float s0 = 0.f, s1 = 0.f;
            #pragma unroll
            for (int nb = 0; nb < 4; ++nb) {
                float p0 = __expf(sacc[nb][0] - mn0);
                float p1 = __expf(sacc[nb][1] - mn0);
                float p2 = __expf(sacc[nb][2] - mn1);
                float p3 = __expf(sacc[nb][3] - mn1);
                sacc[nb][0] = p0; sacc[nb][1] = p1;
                sacc[nb][2] = p2; sacc[nb][3] = p3;
                s0 += p0 + p1; s1 += p2 + p3;
            }
            s0 += __shfl_xor_sync(0xffffffffu, s0, 1);
            s0 += __shfl_xor_sync(0xffffffffu, s0, 2);
            s1 += __shfl_xor_sync(0xffffffffu, s1, 1);
            s1 += __shfl_xor_sync(0xffffffffu, s1, 2);
            l0 = l0 * f0 + s0;
            l1 = l1 * f1 + s1;
            #pragma unroll
            for (int c6 = 0; c6 < 12; ++c6) {
                oacc[c6][0] *= f0; oacc[c6][1] *= f0;
                oacc[c6][2] *= f1; oacc[c6][3] *= f1;
            }

            uint32_t pa[2][4];
            #pragma unroll
            for (int kk = 0; kk < 2; ++kk) {
                pa[kk][0] = pack_h2(sacc[kk*2][0],   sacc[kk*2][1]);
                pa[kk][1] = pack_h2(sacc[kk*2][2],   sacc[kk*2][3]);
                pa[kk][2] = pack_h2(sacc[kk*2+1][0], sacc[kk*2+1][1]);
                pa[kk][3] = pack_h2(sacc[kk*2+1][2], sacc[kk*2+1][3]);
            }

            const uint32_t vrow = vb + ((lane & 7) + (((lane >> 3) & 1) << 3)) * QPITCH;
            #pragma unroll
            for (int kk = 0; kk < 2; ++kk) {
                #pragma unroll
                for (int c6 = 0; c6 < 6; ++c6) {
                    uint32_t vf[4];
                    ldm_trans_x4(vf, vrow + kk * 16 * QPITCH
                                     + (c6 * 16 + ((lane >> 4) << 3)) * 2);
                    mma16816(oacc[c6 * 2],     pa[kk], &vf[0]);
                    mma16816(oacc[c6 * 2 + 1], pa[kk], &vf[2]);
                }
            }
        }
        __syncthreads();
    }

    float il0 = 1.f / l0, il1 = 1.f / l1;
    #pragma unroll
    for (int c6 = 0; c6 < 12; ++c6) {
        int col = h * DHd + c6 * 8 + (lane & 3) * 2;
        *(__half2*)(o16 + (size_t)(b * Ss + r0g) * Dd + col) =
            __floats2half2_rn(oacc[c6][0] * il0, oacc[c6][1] * il0);
        *(__half2*)(o16 + (size_t)(b * Ss + r0g + 8) * Dd + col) =
            __floats2half2_rn(oacc[c6][2] * il1, oacc[c6][3] * il1);
    }
}

// ================= launcher =================
extern "C" void kernel_launch(void* const* d_in, const int* in_sizes, int n_in,
                              void* d_out, int out_size)
{
    (void)in_sizes; (void)n_in; (void)out_size;
    const float* latent   = (const float*)d_in[0];
    const int*   target   = (const int*)  d_in[1];
    const float* tok_emb  = (const float*)d_in[2];
    const float* pos_emb  = (const float*)d_in[3];
    const float* sa_w_qkv = (const float*)d_in[4];
    const float* sa_b_qkv = (const float*)d_in[5];
    const float* sa_w_o   = (const float*)d_in[6];
    const float* sa_b_o   = (const float*)d_in[7];
    const float* ca_w_qkv = (const float*)d_in[8];
    const float* ca_b_qkv = (const float*)d_in[9];
    const float* ca_w_o   = (const float*)d_in[10];
    const float* ca_b_o   = (const float*)d_in[11];
    const float* ffn_w1   = (const float*)d_in[12];
    const float* ffn_b1   = (const float*)d_in[13];
    const float* ffn_w2   = (const float*)d_in[14];
    const float* ffn_b2   = (const float*)d_in[15];
    const float* ln1_g    = (const float*)d_in[16];
    const float* ln1_b    = (const float*)d_in[17];
    const float* ln2_g    = (const float*)d_in[18];
    const float* ln2_b    = (const float*)d_in[19];
    const float* ln3_g    = (const float*)d_in[20];
    const float* ln3_b    = (const float*)d_in[21];
    const float* out_w    = (const float*)d_in[22];
    const float* out_b    = (const float*)d_in[23];

    float *x, *y, *cat, *ca;
    __half *x16, *o16, *h16, *qkv16, *wqkv16, *wo16, *w116, *w216, *wout16;
    cudaGetSymbolAddress((void**)&x,   g_x);
    cudaGetSymbolAddress((void**)&y,   g_y);
    cudaGetSymbolAddress((void**)&cat, g_cat);
    cudaGetSymbolAddress((void**)&ca,  g_ca);
    cudaGetSymbolAddress((void**)&x16, g_x16);
    cudaGetSymbolAddress((void**)&o16, g_o16);
    cudaGetSymbolAddress((void**)&h16, g_h16);
    cudaGetSymbolAddress((void**)&qkv16, g_qkv16);
    cudaGetSymbolAddress((void**)&wqkv16, g_wqkv16);
    cudaGetSymbolAddress((void**)&wo16,   g_wo16);
    cudaGetSymbolAddress((void**)&w116,   g_w116);
    cudaGetSymbolAddress((void**)&w216,   g_w216);
    cudaGetSymbolAddress((void**)&wout16, g_wout16);

    cudaFuncSetAttribute(gemm_fp16,  cudaFuncAttributeMaxDynamicSharedMemorySize, GEMM_SMEM);
    cudaFuncSetAttribute(attn_flash, cudaFuncAttributeMaxDynamicSharedMemorySize, FATT_SMEM);

    // 0: weight conversions
    const int nb0 = (Ll*3*Dd*Dd) / 1024, nb1 = (Ll*Dd*Dd) / 1024,
              nb2 = (Ll*Ff*Dd) / 1024,   nb3 = (Ll*Dd*Ff) / 1024,
              nb4 = (Vv*Dd) / 1024;
    convert_all<<<nb0 + nb1 + nb2 + nb3 + nb4, 256>>>(
        sa_w_qkv, wqkv16, nb0, sa_w_o, wo16, nb1,
        ffn_w1, w116, nb2, ffn_w2, w216, nb3, out_w, wout16, nb4);

    // 1: embed
    embed_kernel<<<Mm, 256>>>(target, tok_emb, pos_emb, x, x16);

    // 2: batched cross-attn stage-1 (cat[l] = latent @ Wv_l^T + bv_l)
    const int SGB = (Ll * Bb * Dd) / 8;
    small_gemm_all<<<SGB, 256>>>(
        latent, 0,
        ca_w_qkv + (size_t)2*Dd*Dd, (size_t)3*Dd*Dd,
        ca_b_qkv + 2*Dd, 3*Dd, cat);

    // 3: QKV gemm (layer 0), 4: attention, 5: O-proj gemm  <-- ncu -s 5 profiles O-proj
    gemm_fp16<<<dim3(18, 64), 128, GEMM_SMEM>>>(
        x16, wqkv16, sa_b_qkv, nullptr, qkv16, Mm, QKVS, Dd, 2);
    attn_flash<<<dim3(Ss/128, Hh, Bb), 256, FATT_SMEM>>>(qkv16, o16);
    gemm_fp16<<<dim3(6, 64), 128, GEMM_SMEM>>>(
        o16, wo16, sa_b_o, y, nullptr, Mm, Dd, Dd, 0);

    // 6: batched cross-attn stage-2 (ca[l] = cat[l] @ Wo_l^T + bo_l)
    small_gemm_all<<<SGB, 256>>>(
        cat, Bb*Dd,
        ca_w_o, (size_t)Dd*Dd,
        ca_b_o, Dd, ca);

    for (int l = 0; l < Ll; ++l) {
        if (l > 0) {
            gemm_fp16<<<dim3(18, 64), 128, GEMM_SMEM>>>(
                x16, wqkv16 + (size_t)l*3*Dd*Dd, sa_b_qkv + (size_t)l*3*Dd,
                nullptr, qkv16, Mm, QKVS, Dd, 2);
            attn_flash<<<dim3(Ss/128, Hh, Bb), 256, FATT_SMEM>>>(qkv16, o16);
            gemm_fp16<<<dim3(6, 64), 128, GEMM_SMEM>>>(
                o16, wo16 + (size_t)l*Dd*Dd, sa_b_o + (size_t)l*Dd,
                y, nullptr, Mm, Dd, Dd, 0);
        }
        add_ln2_kernel<<<Mm, 256>>>(x, y, ca + l*Bb*Dd,
                                    ln1_g + (size_t)l*Dd, ln1_b + (size_t)l*Dd,
                                    ln2_g + (size_t)l*Dd, ln2_b + (size_t)l*Dd, x16);
        gemm_fp16<<<dim3(16, 64), 128, GEMM_SMEM>>>(
            x16, w116 + (size_t)l*Ff*Dd, ffn_b1 + (size_t)l*Ff,
            nullptr, h16, Mm, Ff, Dd, 1);
        gemm_fp16<<<dim3(6, 64), 128, GEMM_SMEM>>>(
            h16, w216 + (size_t)l*Dd*Ff, ffn_b2 + (size_t)l*Dd,
            y, nullptr, Mm, Dd, Ff, 0);
        add_ln_kernel<<<Mm, 256>>>(x, y, ln3_g + (size_t)l*Dd, ln3_b + (size_t)l*Dd,
                                   x16);
    }

    // output projection
    gemm_fp16<<<dim3(1, 64), 128, GEMM_SMEM>>>(
        x16, wout16, out_b, (float*)d_out, nullptr, Mm, Vv, Dd, 0);
}

// round 8
// speedup vs baseline: 9.7280x; 1.0318x over previous
#include <cuda_runtime.h>
#include <cuda_fp16.h>
#include <stdint.h>
#include <math.h>

// Problem dims
#define Bb   16
#define Ss   512
#define Dd   768
#define Hh   8
#define Vv   100
#define Ff   2048
#define Ll   6
#define DHd  96
#define Mm   (Bb*Ss)   // 8192
#define QKVS (3*Dd)    // 2304

// ================= low-level helpers =================
__device__ __forceinline__ uint32_t smem_u32(const void* p) {
    return (uint32_t)__cvta_generic_to_shared(p);
}
__device__ __forceinline__ void cp_async16(uint32_t dst, const void* src, int szvalid) {
    asm volatile("cp.async.cg.shared.global [%0], [%1], 16, %2;"
                 :: "r"(dst), "l"(src), "r"(szvalid) : "memory");
}
#define CP_COMMIT() asm volatile("cp.async.commit_group;" ::: "memory")
#define CP_WAIT(n)  asm volatile("cp.async.wait_group %0;" :: "n"(n) : "memory")

__device__ __forceinline__ void ldm_x4(uint32_t* r, uint32_t addr) {
    asm volatile("ldmatrix.sync.aligned.m8n8.x4.shared.b16 {%0,%1,%2,%3}, [%4];"
                 : "=r"(r[0]), "=r"(r[1]), "=r"(r[2]), "=r"(r[3]) : "r"(addr));
}
__device__ __forceinline__ void ldm_trans_x4(uint32_t* r, uint32_t addr) {
    asm volatile("ldmatrix.sync.aligned.m8n8.x4.trans.shared.b16 {%0,%1,%2,%3}, [%4];"
                 : "=r"(r[0]), "=r"(r[1]), "=r"(r[2]), "=r"(r[3]) : "r"(addr));
}
__device__ __forceinline__ void mma16816(float* d, const uint32_t* a, const uint32_t* b) {
    asm volatile("mma.sync.aligned.m16n8k16.row.col.f32.f16.f16.f32 "
                 "{%0,%1,%2,%3}, {%4,%5,%6,%7}, {%8,%9}, {%0,%1,%2,%3};"
                 : "+f"(d[0]), "+f"(d[1]), "+f"(d[2]), "+f"(d[3])
                 : "r"(a[0]), "r"(a[1]), "r"(a[2]), "r"(a[3]), "r"(b[0]), "r"(b[1]));
}
__device__ __forceinline__ uint32_t pack_h2(float a, float b) {
    __half2 t = __floats2half2_rn(a, b);
    return *(uint32_t*)&t;
}

// ================= device scratch =================
__device__ float g_x   [Mm * Dd];
__device__ float g_y   [Mm * Dd];
__device__ float g_cat [Ll * Bb * Dd];
__device__ float g_ca  [Ll * Bb * Dd];

__device__ __align__(16) __half g_x16 [Mm * Dd];
__device__ __align__(16) __half g_o16 [Mm * Dd];
__device__ __align__(16) __half g_h16 [Mm * Ff];
__device__ __align__(16) __half g_qkv16[Mm * QKVS];

__device__ __align__(16) __half g_wqkv16[Ll*3*Dd*Dd];
__device__ __align__(16) __half g_wo16  [Ll*Dd*Dd];
__device__ __align__(16) __half g_w116  [Ll*Ff*Dd];
__device__ __align__(16) __half g_w216  [Ll*Dd*Ff];
__device__ __align__(16) __half g_wout16[Vv*Dd];

// ================= weight convert =================
__global__ __launch_bounds__(256) void convert_all(
    const float* __restrict__ s0, __half* __restrict__ d0, int b0,
    const float* __restrict__ s1, __half* __restrict__ d1, int b1,
    const float* __restrict__ s2, __half* __restrict__ d2, int b2,
    const float* __restrict__ s3, __half* __restrict__ d3, int b3,
    const float* __restrict__ s4, __half* __restrict__ d4, int b4)
{
    int bid = blockIdx.x;
    const float* src; __half* dst; int nb;
    if      (bid < b0)          { src = s0; dst = d0; nb = bid; }
    else if (bid < b0+b1)       { src = s1; dst = d1; nb = bid - b0; }
    else if (bid < b0+b1+b2)    { src = s2; dst = d2; nb = bid - b0 - b1; }
    else if (bid < b0+b1+b2+b3) { src = s3; dst = d3; nb = bid - b0 - b1 - b2; }
    else                        { src = s4; dst = d4; nb = bid - b0 - b1 - b2 - b3; }
    int i = (nb * 256 + threadIdx.x) * 4;
    float4 v = *(const float4*)&src[i];
    *(__half2*)&dst[i]     = __floats2half2_rn(v.x, v.y);
    *(__half2*)&dst[i + 2] = __floats2half2_rn(v.z, v.w);
}

// ================= embed =================
__global__ __launch_bounds__(256) void embed_kernel(
    const int* __restrict__ target, const float* __restrict__ tok,
    const float* __restrict__ pos, float* __restrict__ x,
    __half* __restrict__ x16)
{
    int row = blockIdx.x;
    int s   = row & (Ss - 1);
    int t   = target[row];
    const float* tp = tok + (size_t)t * Dd;
    const float* pp = pos + (size_t)s * Dd;
    size_t base = (size_t)row * Dd;
    for (int c = threadIdx.x; c < Dd; c += 256) {
        float v = tp[c] + pp[c];
        x[base + c] = v;
        x16[base + c] = __float2half(v);
    }
}

// ================= fp16 GEMM: CTA 128x128, 4 warps, 3-stage, 1 sync/chunk =======
#define BKc 32
#define APITCH 80
#define T128_B   (128*APITCH)           // 10240 per operand tile
#define STAGE_B  (2*T128_B)             // 20480 per stage (A + W)
#define GEMM_SMEM (3*STAGE_B)           // 61440

__global__ void __launch_bounds__(128, 3) gemm_fp16(
    const __half* __restrict__ A, const __half* __restrict__ W,
    const float* __restrict__ bias, float* __restrict__ C,
    __half* __restrict__ Ch,
    int M, int N, int K, int mode)
{
    extern __shared__ char sm[];
    const uint32_t smU = smem_u32(sm);
    const int tid  = threadIdx.x;
    const int lane = tid & 31;
    const int wid  = tid >> 5;          // 0..3
    const int bm   = blockIdx.y * 128;
    const int bn   = blockIdx.x * 128;
    const int wm   = (wid >> 1) * 64;
    const int wn   = (wid & 1) * 64;

    float acc[4][8][4];
    #pragma unroll
    for (int i = 0; i < 4; ++i)
        #pragma unroll
        for (int j = 0; j < 8; ++j)
            #pragma unroll
            for (int r = 0; r < 4; ++r) acc[i][j][r] = 0.f;

    const int NC = K / BKc;

    auto issue = [&](int chunk, int s) {
        const int k0 = chunk * BKc;
        #pragma unroll
        for (int i = 0; i < 4; ++i) {
            int c = tid + 128 * i;
            int row = c >> 2, c16 = c & 3;
            cp_async16(smU + s * STAGE_B + row * APITCH + c16 * 16,
                       (const char*)(A + (size_t)(bm + row) * K + k0) + c16 * 16, 16);
        }
        #pragma unroll
        for (int i = 0; i < 4; ++i) {
            int c = tid + 128 * i;
            int row = c >> 2, c16 = c & 3;
            int rn = bn + row;
            const char* g = (const char*)(W + (size_t)rn * K + k0) + c16 * 16;
            int sz = 16;
            if (rn >= N) { sz = 0; g = (const char*)W; }
            cp_async16(smU + s * STAGE_B + T128_B + row * APITCH + c16 * 16, g, sz);
        }
        CP_COMMIT();
    };

    const int wrow_off = ((lane >> 4) << 3) + (lane & 7);
    const int wcol_off = ((lane >> 3) & 1) * 8;
    const int arow_off = lane & 15;
    const int acol_off = (lane >> 4) << 3;

    auto compute = [&](int s) {
        const uint32_t aB = smU + s * STAGE_B;
        const uint32_t wB = aB + T128_B;
        #pragma unroll
        for (int ks = 0; ks < BKc; ks += 16) {
            uint32_t wh[4][4];
            #pragma unroll
            for (int nb = 0; nb < 4; ++nb)
                ldm_x4(wh[nb], wB + (wn + nb * 16 + wrow_off) * APITCH + (ks + wcol_off) * 2);
            #pragma unroll
            for (int mi = 0; mi < 4; ++mi) {
                uint32_t ah[4];
                ldm_x4(ah, aB + (wm + mi * 16 + arow_off) * APITCH + (ks + acol_off) * 2);
                #pragma unroll
                for (int nb = 0; nb < 4; ++nb) {
                    mma16816(&acc[mi][nb * 2][0],     ah, &wh[nb][0]);
                    mma16816(&acc[mi][nb * 2 + 1][0], ah, &wh[nb][2]);
                }
            }
        }
    };

    issue(0, 0);
    issue(1, 1);
    for (int c = 0; c < NC; ++c) {
        if (c + 1 < NC) { CP_WAIT(1); } else { CP_WAIT(0); }
        __syncthreads();
        if (c + 2 < NC) issue(c + 2, (c + 2) % 3);
        compute(c % 3);
    }

    float bs[16];
    #pragma unroll
    for (int nj = 0; nj < 8; ++nj) {
        int c0 = bn + wn + nj * 8 + (lane & 3) * 2;
        bs[nj * 2]     = (c0 < N)     ? bias[c0]     : 0.f;
        bs[nj * 2 + 1] = (c0 + 1 < N) ? bias[c0 + 1] : 0.f;
    }
    #pragma unroll
    for (int mi = 0; mi < 4; ++mi) {
        #pragma unroll
        for (int nj = 0; nj < 8; ++nj) {
            int c0 = bn + wn + nj * 8 + (lane & 3) * 2;
            if (c0 >= N) continue;
            #pragma unroll
            for (int p = 0; p < 2; ++p) {
                int row = bm + wm + mi * 16 + (lane >> 2) + p * 8;
                float v0 = acc[mi][nj][p * 2]     + bs[nj * 2];
                float v1 = acc[mi][nj][p * 2 + 1] + bs[nj * 2 + 1];
                if (mode == 0) {
                    *(float2*)(C + (size_t)row * N + c0) = make_float2(v0, v1);
                } else {
                    if (mode == 1) { v0 = fmaxf(v0, 0.f); v1 = fmaxf(v1, 0.f); }
                    *(__half2*)(Ch + (size_t)row * N + c0) = __floats2half2_rn(v0, v1);
                }
            }
        }
    }
}

// ================= batched tiny GEMM (all layers in one launch) =================
__global__ __launch_bounds__(256) void small_gemm_all(
    const float* __restrict__ A, int aStrideL,
    const float* __restrict__ W, size_t wStrideL,
    const float* __restrict__ bias, int biasStrideL,
    float* __restrict__ C)
{
    int wg   = blockIdx.x * 8 + (threadIdx.x >> 5);
    int lane = threadIdx.x & 31;
    if (wg >= Ll * Bb * Dd) return;
    int l  = wg / (Bb * Dd);
    int r  = wg - l * (Bb * Dd);
    int bq = r / Dd;
    int n  = r - bq * Dd;
    const float* a = A + (size_t)l * aStrideL + (size_t)bq * Dd;
    const float* w = W + (size_t)l * wStrideL + (size_t)n * Dd;
    float s = 0.f;
    #pragma unroll 4
    for (int k = lane; k < Dd; k += 32) s = fmaf(a[k], w[k], s);
    #pragma unroll
    for (int o = 16; o; o >>= 1) s += __shfl_xor_sync(0xffffffffu, s, o);
    if (lane == 0) C[wg] = s + bias[(size_t)l * biasStrideL + n];
}

// ================= single add+LN (used for ln3) =================
__global__ __launch_bounds__(256) void add_ln_kernel(
    float* __restrict__ x, const float* __restrict__ br,
    const float* __restrict__ g, const float* __restrict__ b,
    __half* __restrict__ x16)
{
    int row = blockIdx.x;
    const float* brp = br + (size_t)row * Dd;
    float* xp = x + (size_t)row * Dd;
    int tid = threadIdx.x;

    float v[3];
    float sum = 0.f, sq = 0.f;
    #pragma unroll
    for (int i = 0; i < 3; ++i) {
        int c = tid + i * 256;
        float t = xp[c] + brp[c];
        v[i] = t; sum += t; sq = fmaf(t, t, sq);
    }
    #pragma unroll
    for (int o = 16; o; o >>= 1) {
        sum += __shfl_xor_sync(0xffffffffu, sum, o);
        sq  += __shfl_xor_sync(0xffffffffu, sq,  o);
    }
    __shared__ float sh1[8], sh2[8];
    int warp = tid >> 5, lane = tid & 31;
    if (lane == 0) { sh1[warp] = sum; sh2[warp] = sq; }
    __syncthreads();
    if (tid == 0) {
        float a = 0.f, c2 = 0.f;
        #pragma unroll
        for (int i = 0; i < 8; ++i) { a += sh1[i]; c2 += sh2[i]; }
        sh1[0] = a; sh2[0] = c2;
    }
    __syncthreads();
    float mu  = sh1[0] * (1.f / Dd);
    float var = sh2[0] * (1.f / Dd) - mu * mu;
    float rs  = rsqrtf(var + 1e-5f);
    #pragma unroll
    for (int i = 0; i < 3; ++i) {
        int c = tid + i * 256;
        float o = (v[i] - mu) * rs * g[c] + b[c];
        xp[c] = o;
        x16[(size_t)row * Dd + c] = __float2half(o);
    }
}

// ================= fused (add+LN1) then (add bcast + LN2) =================
__global__ __launch_bounds__(256) void add_ln2_kernel(
    float* __restrict__ x, const float* __restrict__ y, const float* __restrict__ ca,
    const float* __restrict__ g1, const float* __restrict__ b1,
    const float* __restrict__ g2, const float* __restrict__ b2,
    __half* __restrict__ x16)
{
    int row = blockIdx.x;
    const float* yp  = y  + (size_t)row * Dd;
    const float* cap = ca + (size_t)(row >> 9) * Dd;
    float* xp = x + (size_t)row * Dd;
    int tid = threadIdx.x;
    __shared__ float sh1[8], sh2[8];
    int warp = tid >> 5, lane = tid & 31;

    float v[3];
    float sum = 0.f, sq = 0.f;
    #pragma unroll
    for (int i = 0; i < 3; ++i) {
        int c = tid + i * 256;
        float t = xp[c] + yp[c];
        v[i] = t; sum += t; sq = fmaf(t, t, sq);
    }
    #pragma unroll
    for (int o = 16; o; o >>= 1) {
        sum += __shfl_xor_sync(0xffffffffu, sum, o);
        sq  += __shfl_xor_sync(0xffffffffu, sq,  o);
    }
    if (lane == 0) { sh1[warp] = sum; sh2[warp] = sq; }
    __syncthreads();
    if (tid == 0) {
        float a = 0.f, c2 = 0.f;
        #pragma unroll
        for (int i = 0; i < 8; ++i) { a += sh1[i]; c2 += sh2[i]; }
        sh1[0] = a; sh2[0] = c2;
    }
    __syncthreads();
    float mu = sh1[0] * (1.f / Dd);
    float rs = rsqrtf(sh2[0] * (1.f / Dd) - mu * mu + 1e-5f);
    __syncthreads();

    sum = 0.f; sq = 0.f;
    #pragma unroll
    for (int i = 0; i < 3; ++i) {
        int c = tid + i * 256;
        float t = (v[i] - mu) * rs * g1[c] + b1[c] + cap[c];
        v[i] = t; sum += t; sq = fmaf(t, t, sq);
    }
    #pragma unroll
    for (int o = 16; o; o >>= 1) {
        sum += __shfl_xor_sync(0xffffffffu, sum, o);
        sq  += __shfl_xor_sync(0xffffffffu, sq,  o);
    }
    if (lane == 0) { sh1[warp] = sum; sh2[warp] = sq; }
    __syncthreads();
    if (tid == 0) {
        float a = 0.f, c2 = 0.f;
        #pragma unroll
        for (int i = 0; i < 8; ++i) { a += sh1[i]; c2 += sh2[i]; }
        sh1[0] = a; sh2[0] = c2;
    }
    __syncthreads();
    float mu2 = sh1[0] * (1.f / Dd);
    float rs2 = rsqrtf(sh2[0] * (1.f / Dd) - mu2 * mu2 + 1e-5f);
    #pragma unroll
    for (int i = 0; i < 3; ++i) {
        int c = tid + i * 256;
        float o = (v[i] - mu2) * rs2 * g2[c] + b2[c];
        xp[c] = o;
        x16[(size_t)row * Dd + c] = __float2half(o);
    }
}

// ================= flash-attention: 3-stage KV, 1 sync/tile, long-first order ===
#define FATT_SMEM 66560
#define QPITCH 208

__global__ void __launch_bounds__(256) attn_flash(
    const __half* __restrict__ qkv, __half* __restrict__ o16)
{
    extern __shared__ char smd[];
    const int bid  = blockIdx.x;
    const int qidx = (Ss/128 - 1) - (bid >> 7);   // longest blocks first
    const int rem  = bid & 127;
    const int h    = rem >> 4;
    const int b    = rem & 15;
    const int qb   = qidx * 128;
    const int tid  = threadIdx.x;
    const int lane = tid & 31;
    const int wid  = tid >> 5;
    const uint32_t sQ  = smem_u32(smd);
    const uint32_t sKV = sQ + 26624;
    const float scale = rsqrtf((float)DHd);

    // group 0: Q
    #pragma unroll
    for (int i = 0; i < 6; ++i) {
        int c = tid + 256 * i;
        int row = c / 12, dc = c - row * 12;
        cp_async16(sQ + row * QPITCH + dc * 16,
                   qkv + (size_t)(b * Ss + qb + row) * QKVS + h * DHd + dc * 8, 16);
    }
    CP_COMMIT();

    auto load_kv = [&](int jt, int s) {
        #pragma unroll
        for (int i = 0; i < 3; ++i) {
            int c = tid + 256 * i;
            int kv = (c >= 384) ? 1 : 0;
            int cc = c - kv * 384;
            int row = cc / 12, dc = cc - row * 12;
            cp_async16(sKV + s * 13312 + kv * 6656 + row * QPITCH + dc * 16,
                       qkv + (size_t)(b * Ss + jt + row) * QKVS + (1 + kv) * Dd
                           + h * DHd + dc * 8, 16);
        }
        CP_COMMIT();
    };

    const int ntiles  = (qb + 128) / 32;   // >= 4 always
    load_kv(0, 0);      // group 1
    load_kv(32, 1);     // group 2
    CP_WAIT(2);         // Q complete
    __syncthreads();

    uint32_t qf[6][4];
    {
        uint32_t base = sQ + (wid * 16 + (lane & 15)) * QPITCH + ((lane >> 4) << 3) * 2;
        #pragma unroll
        for (int ks = 0; ks < 6; ++ks)
            ldm_x4(qf[ks], base + ks * 32);
    }

    float oacc[12][4];
    #pragma unroll
    for (int i = 0; i < 12; ++i)
        #pragma unroll
        for (int r = 0; r < 4; ++r) oacc[i][r] = 0.f;
    float m0 = -1e30f, m1 = -1e30f, l0 = 0.f, l1 = 0.f;

    const int my_last = qb + wid * 16 + 15;
    const int r0g     = qb + wid * 16 + (lane >> 2);

    for (int t = 0; t < ntiles; ++t) {
        const int jt = t * 32;
        if (t + 1 < ntiles) { CP_WAIT(1); } else { CP_WAIT(0); }
        __syncthreads();
        if (t + 2 < ntiles) load_kv((t + 2) * 32, (t + 2) % 3);

        if (jt <= my_last) {
            const uint32_t kb = sKV + (t % 3) * 13312;
            const uint32_t vb = kb + 6656;

            float sacc[4][4];
            #pragma unroll
            for (int i = 0; i < 4; ++i)
                #pragma unroll
                for (int r = 0; r < 4; ++r) sacc[i][r] = 0.f;
            const uint32_t kbase = kb + ((lane & 7) + ((lane >> 4) << 3)) * QPITCH
                                 + (((lane >> 3) & 1) << 4);
            #pragma unroll
            for (int ks = 0; ks < 6; ++ks) {
                uint32_t kf[4], kg[4];
                ldm_x4(kf, kbase + ks * 32);
                ldm_x4(kg, kbase + 16 * QPITCH + ks * 32);
                mma16816(sacc[0], qf[ks], &kf[0]);
                mma16816(sacc[1], qf[ks], &kf[2]);
                mma16816(sacc[2], qf[ks], &kg[0]);
                mma16816(sacc[3], qf[ks], &kg[2]);
            }

            #pragma unroll
            for (int nb = 0; nb < 4; ++nb)
                #pragma unroll
                for (int e = 0; e < 4; ++e) {
                    int j = jt + nb * 8 + (lane & 3) * 2 + (e & 1);
                    int r = r0g + ((e >> 1) << 3);
                    float v = sacc[nb][e] * scale;
                    sacc[nb][e] = (j <= r) ? v : -1e30f;
                }

            float mx0 = -1e30f, mx1 = -1e30f;
            #pragma unroll
            for (int nb = 0; nb < 4; ++nb) {
                mx0 = fmaxf(mx0, fmaxf(sacc[nb][0], sacc[nb][1]));
                mx1 = fmaxf(mx1, fmaxf(sacc[nb][2], sacc[nb][3]));
            }
            mx0 = fmaxf(mx0, __shfl_xor_sync(0xffffffffu, mx0, 1));
            mx0 = fmaxf(mx0, __shfl_xor_sync(0xffffffffu, mx0, 2));
            mx1 = fmaxf(mx1, __shfl_xor_sync(0xffffffffu, mx1, 1));
            mx1 = fmaxf(mx1, __shfl_xor_sync(0xffffffffu, mx1, 2));
            float mn0 = fmaxf(m0, mx0), mn1 = fmaxf(m1, mx1);
            float f0 = __expf(m0 - mn0), f1 = __expf(m1 - mn1);
            m0 = mn0; m1 = mn1;

            float s0 = 0.f, s1 = 0.f;
            #pragma unroll
            for (int nb = 0; nb < 4; ++nb) {
                float p0 = __expf(sacc[nb][0] - mn0);
                float p1 = __expf(sacc[nb][1] - mn0);
                float p2 = __expf(sacc[nb][2] - mn1);
                float p3 = __expf(sacc[nb][3] - mn1);
                sacc[nb][0] = p0; sacc[nb][1] = p1;
                sacc[nb][2] = p2; sacc[nb][3] = p3;
                s0 += p0 + p1; s1 += p2 + p3;
            }
            s0 += __shfl_xor_sync(0xffffffffu, s0, 1);
            s0 += __shfl_xor_sync(0xffffffffu, s0, 2);
            s1 += __shfl_xor_sync(0xffffffffu, s1, 1);
            s1 += __shfl_xor_sync(0xffffffffu, s1, 2);
            l0 = l0 * f0 + s0;
            l1 = l1 * f1 + s1;
            #pragma unroll
            for (int c6 = 0; c6 < 12; ++c6) {
                oacc[c6][0] *= f0; oacc[c6][1] *= f0;
                oacc[c6][2] *= f1; oacc[c6][3] *= f1;
            }

            uint32_t pa[2][4];
            #pragma unroll
            for (int kk = 0; kk < 2; ++kk) {
                pa[kk][0] = pack_h2(sacc[kk*2][0],   sacc[kk*2][1]);
                pa[kk][1] = pack_h2(sacc[kk*2][2],   sacc[kk*2][3]);
                pa[kk][2] = pack_h2(sacc[kk*2+1][0], sacc[kk*2+1][1]);
                pa[kk][3] = pack_h2(sacc[kk*2+1][2], sacc[kk*2+1][3]);
            }

            const uint32_t vrow = vb + ((lane & 7) + (((lane >> 3) & 1) << 3)) * QPITCH;
            #pragma unroll
            for (int kk = 0; kk < 2; ++kk) {
                #pragma unroll
                for (int c6 = 0; c6 < 6; ++c6) {
                    uint32_t vf[4];
                    ldm_trans_x4(vf, vrow + kk * 16 * QPITCH
                                     + (c6 * 16 + ((lane >> 4) << 3)) * 2);
                    mma16816(oacc[c6 * 2],     pa[kk], &vf[0]);
                    mma16816(oacc[c6 * 2 + 1], pa[kk], &vf[2]);
                }
            }
        }
    }

    float il0 = 1.f / l0, il1 = 1.f / l1;
    #pragma unroll
    for (int c6 = 0; c6 < 12; ++c6) {
        int col = h * DHd + c6 * 8 + (lane & 3) * 2;
        *(__half2*)(o16 + (size_t)(b * Ss + r0g) * Dd + col) =
            __floats2half2_rn(oacc[c6][0] * il0, oacc[c6][1] * il0);
        *(__half2*)(o16 + (size_t)(b * Ss + r0g + 8) * Dd + col) =
            __floats2half2_rn(oacc[c6][2] * il1, oacc[c6][3] * il1);
    }
}

// ================= launcher =================
extern "C" void kernel_launch(void* const* d_in, const int* in_sizes, int n_in,
                              void* d_out, int out_size)
{
    (void)in_sizes; (void)n_in; (void)out_size;
    const float* latent   = (const float*)d_in[0];
    const int*   target   = (const int*)  d_in[1];
    const float* tok_emb  = (const float*)d_in[2];
    const float* pos_emb  = (const float*)d_in[3];
    const float* sa_w_qkv = (const float*)d_in[4];
    const float* sa_b_qkv = (const float*)d_in[5];
    const float* sa_w_o   = (const float*)d_in[6];
    const float* sa_b_o   = (const float*)d_in[7];
    const float* ca_w_qkv = (const float*)d_in[8];
    const float* ca_b_qkv = (const float*)d_in[9];
    const float* ca_w_o   = (const float*)d_in[10];
    const float* ca_b_o   = (const float*)d_in[11];
    const float* ffn_w1   = (const float*)d_in[12];
    const float* ffn_b1   = (const float*)d_in[13];
    const float* ffn_w2   = (const float*)d_in[14];
    const float* ffn_b2   = (const float*)d_in[15];
    const float* ln1_g    = (const float*)d_in[16];
    const float* ln1_b    = (const float*)d_in[17];
    const float* ln2_g    = (const float*)d_in[18];
    const float* ln2_b    = (const float*)d_in[19];
    const float* ln3_g    = (const float*)d_in[20];
    const float* ln3_b    = (const float*)d_in[21];
    const float* out_w    = (const float*)d_in[22];
    const float* out_b    = (const float*)d_in[23];

    float *x, *y, *cat, *ca;
    __half *x16, *o16, *h16, *qkv16, *wqkv16, *wo16, *w116, *w216, *wout16;
    cudaGetSymbolAddress((void**)&x,   g_x);
    cudaGetSymbolAddress((void**)&y,   g_y);
    cudaGetSymbolAddress((void**)&cat, g_cat);
    cudaGetSymbolAddress((void**)&ca,  g_ca);
    cudaGetSymbolAddress((void**)&x16, g_x16);
    cudaGetSymbolAddress((void**)&o16, g_o16);
    cudaGetSymbolAddress((void**)&h16, g_h16);
    cudaGetSymbolAddress((void**)&qkv16, g_qkv16);
    cudaGetSymbolAddress((void**)&wqkv16, g_wqkv16);
    cudaGetSymbolAddress((void**)&wo16,   g_wo16);
    cudaGetSymbolAddress((void**)&w116,   g_w116);
    cudaGetSymbolAddress((void**)&w216,   g_w216);
    cudaGetSymbolAddress((void**)&wout16, g_wout16);

    cudaFuncSetAttribute(gemm_fp16,  cudaFuncAttributeMaxDynamicSharedMemorySize, GEMM_SMEM);
    cudaFuncSetAttribute(attn_flash, cudaFuncAttributeMaxDynamicSharedMemorySize, FATT_SMEM);

    // 0: weight conversions
    const int nb0 = (Ll*3*Dd*Dd) / 1024, nb1 = (Ll*Dd*Dd) / 1024,
              nb2 = (Ll*Ff*Dd) / 1024,   nb3 = (Ll*Dd*Ff) / 1024,
              nb4 = (Vv*Dd) / 1024;
    convert_all<<<nb0 + nb1 + nb2 + nb3 + nb4, 256>>>(
        sa_w_qkv, wqkv16, nb0, sa_w_o, wo16, nb1,
        ffn_w1, w116, nb2, ffn_w2, w216, nb3, out_w, wout16, nb4);

    // 1: embed
    embed_kernel<<<Mm, 256>>>(target, tok_emb, pos_emb, x, x16);

    // 2: batched cross-attn stage-1
    const int SGB = (Ll * Bb * Dd) / 8;
    small_gemm_all<<<SGB, 256>>>(
        latent, 0,
        ca_w_qkv + (size_t)2*Dd*Dd, (size_t)3*Dd*Dd,
        ca_b_qkv + 2*Dd, 3*Dd, cat);

    // 3: QKV gemm (layer 0), 4: attention, 5: O-proj
    gemm_fp16<<<dim3(18, 64), 128, GEMM_SMEM>>>(
        x16, wqkv16, sa_b_qkv, nullptr, qkv16, Mm, QKVS, Dd, 2);
    attn_flash<<<512, 256, FATT_SMEM>>>(qkv16, o16);
    gemm_fp16<<<dim3(6, 64), 128, GEMM_SMEM>>>(
        o16, wo16, sa_b_o, y, nullptr, Mm, Dd, Dd, 0);

    // 6: batched cross-attn stage-2
    small_gemm_all<<<SGB, 256>>>(
        cat, Bb*Dd,
        ca_w_o, (size_t)Dd*Dd,
        ca_b_o, Dd, ca);

    for (int l = 0; l < Ll; ++l) {
        if (l > 0) {
            gemm_fp16<<<dim3(18, 64), 128, GEMM_SMEM>>>(
                x16, wqkv16 + (size_t)l*3*Dd*Dd, sa_b_qkv + (size_t)l*3*Dd,
                nullptr, qkv16, Mm, QKVS, Dd, 2);
            attn_flash<<<512, 256, FATT_SMEM>>>(qkv16, o16);
            gemm_fp16<<<dim3(6, 64), 128, GEMM_SMEM>>>(
                o16, wo16 + (size_t)l*Dd*Dd, sa_b_o + (size_t)l*Dd,
                y, nullptr, Mm, Dd, Dd, 0);
        }
        add_ln2_kernel<<<Mm, 256>>>(x, y, ca + l*Bb*Dd,
                                    ln1_g + (size_t)l*Dd, ln1_b + (size_t)l*Dd,
                                    ln2_g + (size_t)l*Dd, ln2_b + (size_t)l*Dd, x16);
        gemm_fp16<<<dim3(16, 64), 128, GEMM_SMEM>>>(
            x16, w116 + (size_t)l*Ff*Dd, ffn_b1 + (size_t)l*Ff,
            nullptr, h16, Mm, Ff, Dd, 1);
        gemm_fp16<<<dim3(6, 64), 128, GEMM_SMEM>>>(
            h16, w216 + (size_t)l*Dd*Ff, ffn_b2 + (size_t)l*Dd,
            y, nullptr, Mm, Dd, Ff, 0);
        add_ln_kernel<<<Mm, 256>>>(x, y, ln3_g + (size_t)l*Dd, ln3_b + (size_t)l*Dd,
                                   x16);
    }

    // output projection
    gemm_fp16<<<dim3(1, 64), 128, GEMM_SMEM>>>(
        x16, wout16, out_b, (float*)d_out, nullptr, Mm, Vv, Dd, 0);
}

// round 9
// speedup vs baseline: 9.7432x; 1.0016x over previous
#include <cuda_runtime.h>
#include <cuda_fp16.h>
#include <stdint.h>
#include <math.h>

// Problem dims
#define Bb   16
#define Ss   512
#define Dd   768
#define Hh   8
#define Vv   100
#define Ff   2048
#define Ll   6
#define DHd  96
#define Mm   (Bb*Ss)   // 8192
#define QKVS (3*Dd)    // 2304

// ================= low-level helpers =================
__device__ __forceinline__ uint32_t smem_u32(const void* p) {
    return (uint32_t)__cvta_generic_to_shared(p);
}
__device__ __forceinline__ void cp_async16(uint32_t dst, const void* src, int szvalid) {
    asm volatile("cp.async.cg.shared.global [%0], [%1], 16, %2;"
                 :: "r"(dst), "l"(src), "r"(szvalid) : "memory");
}
#define CP_COMMIT() asm volatile("cp.async.commit_group;" ::: "memory")
#define CP_WAIT(n)  asm volatile("cp.async.wait_group %0;" :: "n"(n) : "memory")

__device__ __forceinline__ void ldm_x4(uint32_t* r, uint32_t addr) {
    asm volatile("ldmatrix.sync.aligned.m8n8.x4.shared.b16 {%0,%1,%2,%3}, [%4];"
                 : "=r"(r[0]), "=r"(r[1]), "=r"(r[2]), "=r"(r[3]) : "r"(addr));
}
__device__ __forceinline__ void ldm_trans_x4(uint32_t* r, uint32_t addr) {
    asm volatile("ldmatrix.sync.aligned.m8n8.x4.trans.shared.b16 {%0,%1,%2,%3}, [%4];"
                 : "=r"(r[0]), "=r"(r[1]), "=r"(r[2]), "=r"(r[3]) : "r"(addr));
}
__device__ __forceinline__ void mma16816(float* d, const uint32_t* a, const uint32_t* b) {
    asm volatile("mma.sync.aligned.m16n8k16.row.col.f32.f16.f16.f32 "
                 "{%0,%1,%2,%3}, {%4,%5,%6,%7}, {%8,%9}, {%0,%1,%2,%3};"
                 : "+f"(d[0]), "+f"(d[1]), "+f"(d[2]), "+f"(d[3])
                 : "r"(a[0]), "r"(a[1]), "r"(a[2]), "r"(a[3]), "r"(b[0]), "r"(b[1]));
}
__device__ __forceinline__ uint32_t pack_h2(float a, float b) {
    __half2 t = __floats2half2_rn(a, b);
    return *(uint32_t*)&t;
}

// ================= device scratch =================
__device__ float g_x   [Mm * Dd];
__device__ float g_cat [Ll * Bb * Dd];
__device__ float g_ca  [Ll * Bb * Dd];

__device__ __align__(16) __half g_x16 [Mm * Dd];
__device__ __align__(16) __half g_o16 [Mm * Dd];
__device__ __align__(16) __half g_y16 [Mm * Dd];
__device__ __align__(16) __half g_h16 [Mm * Ff];
__device__ __align__(16) __half g_qkv16[Mm * QKVS];

__device__ __align__(16) __half g_wqkv16[Ll*3*Dd*Dd];
__device__ __align__(16) __half g_wo16  [Ll*Dd*Dd];
__device__ __align__(16) __half g_w116  [Ll*Ff*Dd];
__device__ __align__(16) __half g_w216  [Ll*Dd*Ff];
__device__ __align__(16) __half g_wout16[Vv*Dd];

// ================= weight convert =================
__global__ __launch_bounds__(256) void convert_all(
    const float* __restrict__ s0, __half* __restrict__ d0, int b0,
    const float* __restrict__ s1, __half* __restrict__ d1, int b1,
    const float* __restrict__ s2, __half* __restrict__ d2, int b2,
    const float* __restrict__ s3, __half* __restrict__ d3, int b3,
    const float* __restrict__ s4, __half* __restrict__ d4, int b4)
{
    int bid = blockIdx.x;
    const float* src; __half* dst; int nb;
    if      (bid < b0)          { src = s0; dst = d0; nb = bid; }
    else if (bid < b0+b1)       { src = s1; dst = d1; nb = bid - b0; }
    else if (bid < b0+b1+b2)    { src = s2; dst = d2; nb = bid - b0 - b1; }
    else if (bid < b0+b1+b2+b3) { src = s3; dst = d3; nb = bid - b0 - b1 - b2; }
    else                        { src = s4; dst = d4; nb = bid - b0 - b1 - b2 - b3; }
    int i = (nb * 256 + threadIdx.x) * 4;
    float4 v = *(const float4*)&src[i];
    *(__half2*)&dst[i]     = __floats2half2_rn(v.x, v.y);
    *(__half2*)&dst[i + 2] = __floats2half2_rn(v.z, v.w);
}

// ================= embed =================
__global__ __launch_bounds__(256) void embed_kernel(
    const int* __restrict__ target, const float* __restrict__ tok,
    const float* __restrict__ pos, float* __restrict__ x,
    __half* __restrict__ x16)
{
    int row = blockIdx.x;
    int s   = row & (Ss - 1);
    int t   = target[row];
    const float* tp = tok + (size_t)t * Dd;
    const float* pp = pos + (size_t)s * Dd;
    size_t base = (size_t)row * Dd;
    for (int c = threadIdx.x; c < Dd; c += 256) {
        float v = tp[c] + pp[c];
        x[base + c] = v;
        x16[base + c] = __float2half(v);
    }
}

// ================= fp16 GEMM: CTA 128x128, 4 warps, 3-stage, 1 sync/chunk =======
#define BKc 32
#define APITCH 80
#define T128_B   (128*APITCH)           // 10240 per operand tile
#define STAGE_B  (2*T128_B)             // 20480 per stage (A + W)
#define GEMM_SMEM (3*STAGE_B)           // 61440

__global__ void __launch_bounds__(128, 3) gemm_fp16(
    const __half* __restrict__ A, const __half* __restrict__ W,
    const float* __restrict__ bias, float* __restrict__ C,
    __half* __restrict__ Ch,
    int M, int N, int K, int mode)
{
    extern __shared__ char sm[];
    const uint32_t smU = smem_u32(sm);
    const int tid  = threadIdx.x;
    const int lane = tid & 31;
    const int wid  = tid >> 5;          // 0..3
    const int bm   = blockIdx.y * 128;
    const int bn   = blockIdx.x * 128;
    const int wm   = (wid >> 1) * 64;
    const int wn   = (wid & 1) * 64;

    float acc[4][8][4];
    #pragma unroll
    for (int i = 0; i < 4; ++i)
        #pragma unroll
        for (int j = 0; j < 8; ++j)
            #pragma unroll
            for (int r = 0; r < 4; ++r) acc[i][j][r] = 0.f;

    const int NC = K / BKc;

    auto issue = [&](int chunk, int s) {
        const int k0 = chunk * BKc;
        #pragma unroll
        for (int i = 0; i < 4; ++i) {
            int c = tid + 128 * i;
            int row = c >> 2, c16 = c & 3;
            cp_async16(smU + s * STAGE_B + row * APITCH + c16 * 16,
                       (const char*)(A + (size_t)(bm + row) * K + k0) + c16 * 16, 16);
        }
        #pragma unroll
        for (int i = 0; i < 4; ++i) {
            int c = tid + 128 * i;
            int row = c >> 2, c16 = c & 3;
            int rn = bn + row;
            const char* g = (const char*)(W + (size_t)rn * K + k0) + c16 * 16;
            int sz = 16;
            if (rn >= N) { sz = 0; g = (const char*)W; }
            cp_async16(smU + s * STAGE_B + T128_B + row * APITCH + c16 * 16, g, sz);
        }
        CP_COMMIT();
    };

    const int wrow_off = ((lane >> 4) << 3) + (lane & 7);
    const int wcol_off = ((lane >> 3) & 1) * 8;
    const int arow_off = lane & 15;
    const int acol_off = (lane >> 4) << 3;

    auto compute = [&](int s) {
        const uint32_t aB = smU + s * STAGE_B;
        const uint32_t wB = aB + T128_B;
        #pragma unroll
        for (int ks = 0; ks < BKc; ks += 16) {
            uint32_t wh[4][4];
            #pragma unroll
            for (int nb = 0; nb < 4; ++nb)
                ldm_x4(wh[nb], wB + (wn + nb * 16 + wrow_off) * APITCH + (ks + wcol_off) * 2);
            #pragma unroll
            for (int mi = 0; mi < 4; ++mi) {
                uint32_t ah[4];
                ldm_x4(ah, aB + (wm + mi * 16 + arow_off) * APITCH + (ks + acol_off) * 2);
                #pragma unroll
                for (int nb = 0; nb < 4; ++nb) {
                    mma16816(&acc[mi][nb * 2][0],     ah, &wh[nb][0]);
                    mma16816(&acc[mi][nb * 2 + 1][0], ah, &wh[nb][2]);
                }
            }
        }
    };

    issue(0, 0);
    issue(1, 1);
    for (int c = 0; c < NC; ++c) {
        if (c + 1 < NC) { CP_WAIT(1); } else { CP_WAIT(0); }
        __syncthreads();
        if (c + 2 < NC) issue(c + 2, (c + 2) % 3);
        compute(c % 3);
    }

    float bs[16];
    #pragma unroll
    for (int nj = 0; nj < 8; ++nj) {
        int c0 = bn + wn + nj * 8 + (lane & 3) * 2;
        bs[nj * 2]     = (c0 < N)     ? bias[c0]     : 0.f;
        bs[nj * 2 + 1] = (c0 + 1 < N) ? bias[c0 + 1] : 0.f;
    }
    #pragma unroll
    for (int mi = 0; mi < 4; ++mi) {
        #pragma unroll
        for (int nj = 0; nj < 8; ++nj) {
            int c0 = bn + wn + nj * 8 + (lane & 3) * 2;
            if (c0 >= N) continue;
            #pragma unroll
            for (int p = 0; p < 2; ++p) {
                int row = bm + wm + mi * 16 + (lane >> 2) + p * 8;
                float v0 = acc[mi][nj][p * 2]     + bs[nj * 2];
                float v1 = acc[mi][nj][p * 2 + 1] + bs[nj * 2 + 1];
                if (mode == 0) {
                    *(float2*)(C + (size_t)row * N + c0) = make_float2(v0, v1);
                } else {
                    if (mode == 1) { v0 = fmaxf(v0, 0.f); v1 = fmaxf(v1, 0.f); }
                    *(__half2*)(Ch + (size_t)row * N + c0) = __floats2half2_rn(v0, v1);
                }
            }
        }
    }
}

// ================= batched tiny GEMM (all layers in one launch) =================
__global__ __launch_bounds__(256) void small_gemm_all(
    const float* __restrict__ A, int aStrideL,
    const float* __restrict__ W, size_t wStrideL,
    const float* __restrict__ bias, int biasStrideL,
    float* __restrict__ C)
{
    int wg   = blockIdx.x * 8 + (threadIdx.x >> 5);
    int lane = threadIdx.x & 31;
    if (wg >= Ll * Bb * Dd) return;
    int l  = wg / (Bb * Dd);
    int r  = wg - l * (Bb * Dd);
    int bq = r / Dd;
    int n  = r - bq * Dd;
    const float* a = A + (size_t)l * aStrideL + (size_t)bq * Dd;
    const float* w = W + (size_t)l * wStrideL + (size_t)n * Dd;
    float s = 0.f;
    #pragma unroll 4
    for (int k = lane; k < Dd; k += 32) s = fmaf(a[k], w[k], s);
    #pragma unroll
    for (int o = 16; o; o >>= 1) s += __shfl_xor_sync(0xffffffffu, s, o);
    if (lane == 0) C[wg] = s + bias[(size_t)l * biasStrideL + n];
}

// ================= single add+LN (ln3): y in fp16 =================
__global__ __launch_bounds__(256) void add_ln_kernel(
    float* __restrict__ x, const __half* __restrict__ y16,
    const float* __restrict__ g, const float* __restrict__ b,
    __half* __restrict__ x16)
{
    int row = blockIdx.x;
    const __half* yp = y16 + (size_t)row * Dd;
    float* xp = x + (size_t)row * Dd;
    int tid = threadIdx.x;

    float v[3];
    float sum = 0.f, sq = 0.f;
    #pragma unroll
    for (int i = 0; i < 3; ++i) {
        int c = tid + i * 256;
        float t = xp[c] + __half2float(yp[c]);
        v[i] = t; sum += t; sq = fmaf(t, t, sq);
    }
    #pragma unroll
    for (int o = 16; o; o >>= 1) {
        sum += __shfl_xor_sync(0xffffffffu, sum, o);
        sq  += __shfl_xor_sync(0xffffffffu, sq,  o);
    }
    __shared__ float sh1[8], sh2[8];
    int warp = tid >> 5, lane = tid & 31;
    if (lane == 0) { sh1[warp] = sum; sh2[warp] = sq; }
    __syncthreads();
    if (tid == 0) {
        float a = 0.f, c2 = 0.f;
        #pragma unroll
        for (int i = 0; i < 8; ++i) { a += sh1[i]; c2 += sh2[i]; }
        sh1[0] = a; sh2[0] = c2;
    }
    __syncthreads();
    float mu  = sh1[0] * (1.f / Dd);
    float var = sh2[0] * (1.f / Dd) - mu * mu;
    float rs  = rsqrtf(var + 1e-5f);
    #pragma unroll
    for (int i = 0; i < 3; ++i) {
        int c = tid + i * 256;
        float o = (v[i] - mu) * rs * g[c] + b[c];
        xp[c] = o;
        x16[(size_t)row * Dd + c] = __float2half(o);
    }
}

// ================= fused (add+LN1) then (add bcast + LN2): y in fp16 ============
__global__ __launch_bounds__(256) void add_ln2_kernel(
    float* __restrict__ x, const __half* __restrict__ y16,
    const float* __restrict__ ca,
    const float* __restrict__ g1, const float* __restrict__ b1,
    const float* __restrict__ g2, const float* __restrict__ b2,
    __half* __restrict__ x16)
{
    int row = blockIdx.x;
    const __half* yp  = y16 + (size_t)row * Dd;
    const float* cap  = ca  + (size_t)(row >> 9) * Dd;
    float* xp = x + (size_t)row * Dd;
    int tid = threadIdx.x;
    __shared__ float sh1[8], sh2[8];
    int warp = tid >> 5, lane = tid & 31;

    float v[3];
    float sum = 0.f, sq = 0.f;
    #pragma unroll
    for (int i = 0; i < 3; ++i) {
        int c = tid + i * 256;
        float t = xp[c] + __half2float(yp[c]);
        v[i] = t; sum += t; sq = fmaf(t, t, sq);
    }
    #pragma unroll
    for (int o = 16; o; o >>= 1) {
        sum += __shfl_xor_sync(0xffffffffu, sum, o);
        sq  += __shfl_xor_sync(0xffffffffu, sq,  o);
    }
    if (lane == 0) { sh1[warp] = sum; sh2[warp] = sq; }
    __syncthreads();
    if (tid == 0) {
        float a = 0.f, c2 = 0.f;
        #pragma unroll
        for (int i = 0; i < 8; ++i) { a += sh1[i]; c2 += sh2[i]; }
        sh1[0] = a; sh2[0] = c2;
    }
    __syncthreads();
    float mu = sh1[0] * (1.f / Dd);
    float rs = rsqrtf(sh2[0] * (1.f / Dd) - mu * mu + 1e-5f);
    __syncthreads();

    sum = 0.f; sq = 0.f;
    #pragma unroll
    for (int i = 0; i < 3; ++i) {
        int c = tid + i * 256;
        float t = (v[i] - mu) * rs * g1[c] + b1[c] + cap[c];
        v[i] = t; sum += t; sq = fmaf(t, t, sq);
    }
    #pragma unroll
    for (int o = 16; o; o >>= 1) {
        sum += __shfl_xor_sync(0xffffffffu, sum, o);
        sq  += __shfl_xor_sync(0xffffffffu, sq,  o);
    }
    if (lane == 0) { sh1[warp] = sum; sh2[warp] = sq; }
    __syncthreads();
    if (tid == 0) {
        float a = 0.f, c2 = 0.f;
        #pragma unroll
        for (int i = 0; i < 8; ++i) { a += sh1[i]; c2 += sh2[i]; }
        sh1[0] = a; sh2[0] = c2;
    }
    __syncthreads();
    float mu2 = sh1[0] * (1.f / Dd);
    float rs2 = rsqrtf(sh2[0] * (1.f / Dd) - mu2 * mu2 + 1e-5f);
    #pragma unroll
    for (int i = 0; i < 3; ++i) {
        int c = tid + i * 256;
        float o = (v[i] - mu2) * rs2 * g2[c] + b2[c];
        xp[c] = o;
        x16[(size_t)row * Dd + c] = __float2half(o);
    }
}

// ================= flash-attention: 3-stage KV, 1 sync/tile, long-first order ===
#define FATT_SMEM 66560
#define QPITCH 208

__global__ void __launch_bounds__(256) attn_flash(
    const __half* __restrict__ qkv, __half* __restrict__ o16)
{
    extern __shared__ char smd[];
    const int bid  = blockIdx.x;
    const int qidx = (Ss/128 - 1) - (bid >> 7);   // longest blocks first
    const int rem  = bid & 127;
    const int h    = rem >> 4;
    const int b    = rem & 15;
    const int qb   = qidx * 128;
    const int tid  = threadIdx.x;
    const int lane = tid & 31;
    const int wid  = tid >> 5;
    const uint32_t sQ  = smem_u32(smd);
    const uint32_t sKV = sQ + 26624;
    const float scale = rsqrtf((float)DHd);

    #pragma unroll
    for (int i = 0; i < 6; ++i) {
        int c = tid + 256 * i;
        int row = c / 12, dc = c - row * 12;
        cp_async16(sQ + row * QPITCH + dc * 16,
                   qkv + (size_t)(b * Ss + qb + row) * QKVS + h * DHd + dc * 8, 16);
    }
    CP_COMMIT();

    auto load_kv = [&](int jt, int s) {
        #pragma unroll
        for (int i = 0; i < 3; ++i) {
            int c = tid + 256 * i;
            int kv = (c >= 384) ? 1 : 0;
            int cc = c - kv * 384;
            int row = cc / 12, dc = cc - row * 12;
            cp_async16(sKV + s * 13312 + kv * 6656 + row * QPITCH + dc * 16,
                       qkv + (size_t)(b * Ss + jt + row) * QKVS + (1 + kv) * Dd
                           + h * DHd + dc * 8, 16);
        }
        CP_COMMIT();
    };

    const int ntiles  = (qb + 128) / 32;   // >= 4 always
    load_kv(0, 0);
    load_kv(32, 1);
    CP_WAIT(2);
    __syncthreads();

    uint32_t qf[6][4];
    {
        uint32_t base = sQ + (wid * 16 + (lane & 15)) * QPITCH + ((lane >> 4) << 3) * 2;
        #pragma unroll
        for (int ks = 0; ks < 6; ++ks)
            ldm_x4(qf[ks], base + ks * 32);
    }

    float oacc[12][4];
    #pragma unroll
    for (int i = 0; i < 12; ++i)
        #pragma unroll
        for (int r = 0; r < 4; ++r) oacc[i][r] = 0.f;
    float m0 = -1e30f, m1 = -1e30f, l0 = 0.f, l1 = 0.f;

    const int my_last = qb + wid * 16 + 15;
    const int r0g     = qb + wid * 16 + (lane >> 2);

    for (int t = 0; t < ntiles; ++t) {
        const int jt = t * 32;
        if (t + 1 < ntiles) { CP_WAIT(1); } else { CP_WAIT(0); }
        __syncthreads();
        if (t + 2 < ntiles) load_kv((t + 2) * 32, (t + 2) % 3);

        if (jt <= my_last) {
            const uint32_t kb = sKV + (t % 3) * 13312;
            const uint32_t vb = kb + 6656;

            float sacc[4][4];
            #pragma unroll
            for (int i = 0; i < 4; ++i)
                #pragma unroll
                for (int r = 0; r < 4; ++r) sacc[i][r] = 0.f;
            const uint32_t kbase = kb + ((lane & 7) + ((lane >> 4) << 3)) * QPITCH
                                 + (((lane >> 3) & 1) << 4);
            #pragma unroll
            for (int ks = 0; ks < 6; ++ks) {
                uint32_t kf[4], kg[4];
                ldm_x4(kf, kbase + ks * 32);
                ldm_x4(kg, kbase + 16 * QPITCH + ks * 32);
                mma16816(sacc[0], qf[ks], &kf[0]);
                mma16816(sacc[1], qf[ks], &kf[2]);
                mma16816(sacc[2], qf[ks], &kg[0]);
                mma16816(sacc[3], qf[ks], &kg[2]);
            }

            #pragma unroll
            for (int nb = 0; nb < 4; ++nb)
                #pragma unroll
                for (int e = 0; e < 4; ++e) {
                    int j = jt + nb * 8 + (lane & 3) * 2 + (e & 1);
                    int r = r0g + ((e >> 1) << 3);
                    float v = sacc[nb][e] * scale;
                    sacc[nb][e] = (j <= r) ? v : -1e30f;
                }

            float mx0 = -1e30f, mx1 = -1e30f;
            #pragma unroll
            for (int nb = 0; nb < 4; ++nb) {
                mx0 = fmaxf(mx0, fmaxf(sacc[nb][0], sacc[nb][1]));
                mx1 = fmaxf(mx1, fmaxf(sacc[nb][2], sacc[nb][3]));
            }
            mx0 = fmaxf(mx0, __shfl_xor_sync(0xffffffffu, mx0, 1));
            mx0 = fmaxf(mx0, __shfl_xor_sync(0xffffffffu, mx0, 2));
            mx1 = fmaxf(mx1, __shfl_xor_sync(0xffffffffu, mx1, 1));
            mx1 = fmaxf(mx1, __shfl_xor_sync(0xffffffffu, mx1, 2));
            float mn0 = fmaxf(m0, mx0), mn1 = fmaxf(m1, mx1);
            float f0 = __expf(m0 - mn0), f1 = __expf(m1 - mn1);
            m0 = mn0; m1 = mn1;

            float s0 = 0.f, s1 = 0.f;
            #pragma unroll
            for (int nb = 0; nb < 4; ++nb) {
                float p0 = __expf(sacc[nb][0] - mn0);
                float p1 = __expf(sacc[nb][1] - mn0);
                float p2 = __expf(sacc[nb][2] - mn1);
                float p3 = __expf(sacc[nb][3] - mn1);
                sacc[nb][0] = p0; sacc[nb][1] = p1;
                sacc[nb][2] = p2; sacc[nb][3] = p3;
                s0 += p0 + p1; s1 += p2 + p3;
            }
            s0 += __shfl_xor_sync(0xffffffffu, s0, 1);
            s0 += __shfl_xor_sync(0xffffffffu, s0, 2);
            s1 += __shfl_xor_sync(0xffffffffu, s1, 1);
            s1 += __shfl_xor_sync(0xffffffffu, s1, 2);
            l0 = l0 * f0 + s0;
            l1 = l1 * f1 + s1;
            #pragma unroll
            for (int c6 = 0; c6 < 12; ++c6) {
                oacc[c6][0] *= f0; oacc[c6][1] *= f0;
                oacc[c6][2] *= f1; oacc[c6][3] *= f1;
            }

            uint32_t pa[2][4];
            #pragma unroll
            for (int kk = 0; kk < 2; ++kk) {
                pa[kk][0] = pack_h2(sacc[kk*2][0],   sacc[kk*2][1]);
                pa[kk][1] = pack_h2(sacc[kk*2][2],   sacc[kk*2][3]);
                pa[kk][2] = pack_h2(sacc[kk*2+1][0], sacc[kk*2+1][1]);
                pa[kk][3] = pack_h2(sacc[kk*2+1][2], sacc[kk*2+1][3]);
            }

            const uint32_t vrow = vb + ((lane & 7) + (((lane >> 3) & 1) << 3)) * QPITCH;
            #pragma unroll
            for (int kk = 0; kk < 2; ++kk) {
                #pragma unroll
                for (int c6 = 0; c6 < 6; ++c6) {
                    uint32_t vf[4];
                    ldm_trans_x4(vf, vrow + kk * 16 * QPITCH
                                     + (c6 * 16 + ((lane >> 4) << 3)) * 2);
                    mma16816(oacc[c6 * 2],     pa[kk], &vf[0]);
                    mma16816(oacc[c6 * 2 + 1], pa[kk], &vf[2]);
                }
            }
        }
    }

    float il0 = 1.f / l0, il1 = 1.f / l1;
    #pragma unroll
    for (int c6 = 0; c6 < 12; ++c6) {
        int col = h * DHd + c6 * 8 + (lane & 3) * 2;
        *(__half2*)(o16 + (size_t)(b * Ss + r0g) * Dd + col) =
            __floats2half2_rn(oacc[c6][0] * il0, oacc[c6][1] * il0);
        *(__half2*)(o16 + (size_t)(b * Ss + r0g + 8) * Dd + col) =
            __floats2half2_rn(oacc[c6][2] * il1, oacc[c6][3] * il1);
    }
}

// ================= launcher =================
extern "C" void kernel_launch(void* const* d_in, const int* in_sizes, int n_in,
                              void* d_out, int out_size)
{
    (void)in_sizes; (void)n_in; (void)out_size;
    const float* latent   = (const float*)d_in[0];
    const int*   target   = (const int*)  d_in[1];
    const float* tok_emb  = (const float*)d_in[2];
    const float* pos_emb  = (const float*)d_in[3];
    const float* sa_w_qkv = (const float*)d_in[4];
    const float* sa_b_qkv = (const float*)d_in[5];
    const float* sa_w_o   = (const float*)d_in[6];
    const float* sa_b_o   = (const float*)d_in[7];
    const float* ca_w_qkv = (const float*)d_in[8];
    const float* ca_b_qkv = (const float*)d_in[9];
    const float* ca_w_o   = (const float*)d_in[10];
    const float* ca_b_o   = (const float*)d_in[11];
    const float* ffn_w1   = (const float*)d_in[12];
    const float* ffn_b1   = (const float*)d_in[13];
    const float* ffn_w2   = (const float*)d_in[14];
    const float* ffn_b2   = (const float*)d_in[15];
    const float* ln1_g    = (const float*)d_in[16];
    const float* ln1_b    = (const float*)d_in[17];
    const float* ln2_g    = (const float*)d_in[18];
    const float* ln2_b    = (const float*)d_in[19];
    const float* ln3_g    = (const float*)d_in[20];
    const float* ln3_b    = (const float*)d_in[21];
    const float* out_w    = (const float*)d_in[22];
    const float* out_b    = (const float*)d_in[23];

    float *x, *cat, *ca;
    __half *x16, *o16, *y16, *h16, *qkv16, *wqkv16, *wo16, *w116, *w216, *wout16;
    cudaGetSymbolAddress((void**)&x,   g_x);
    cudaGetSymbolAddress((void**)&cat, g_cat);
    cudaGetSymbolAddress((void**)&ca,  g_ca);
    cudaGetSymbolAddress((void**)&x16, g_x16);
    cudaGetSymbolAddress((void**)&o16, g_o16);
    cudaGetSymbolAddress((void**)&y16, g_y16);
    cudaGetSymbolAddress((void**)&h16, g_h16);
    cudaGetSymbolAddress((void**)&qkv16, g_qkv16);
    cudaGetSymbolAddress((void**)&wqkv16, g_wqkv16);
    cudaGetSymbolAddress((void**)&wo16,   g_wo16);
    cudaGetSymbolAddress((void**)&w116,   g_w116);
    cudaGetSymbolAddress((void**)&w216,   g_w216);
    cudaGetSymbolAddress((void**)&wout16, g_wout16);

    cudaFuncSetAttribute(gemm_fp16,  cudaFuncAttributeMaxDynamicSharedMemorySize, GEMM_SMEM);
    cudaFuncSetAttribute(attn_flash, cudaFuncAttributeMaxDynamicSharedMemorySize, FATT_SMEM);

    // 0: weight conversions
    const int nb0 = (Ll*3*Dd*Dd) / 1024, nb1 = (Ll*Dd*Dd) / 1024,
              nb2 = (Ll*Ff*Dd) / 1024,   nb3 = (Ll*Dd*Ff) / 1024,
              nb4 = (Vv*Dd) / 1024;
    convert_all<<<nb0 + nb1 + nb2 + nb3 + nb4, 256>>>(
        sa_w_qkv, wqkv16, nb0, sa_w_o, wo16, nb1,
        ffn_w1, w116, nb2, ffn_w2, w216, nb3, out_w, wout16, nb4);

    // 1: embed
    embed_kernel<<<Mm, 256>>>(target, tok_emb, pos_emb, x, x16);

    // 2: batched cross-attn stage-1
    const int SGB = (Ll * Bb * Dd) / 8;
    small_gemm_all<<<SGB, 256>>>(
        latent, 0,
        ca_w_qkv + (size_t)2*Dd*Dd, (size_t)3*Dd*Dd,
        ca_b_qkv + 2*Dd, 3*Dd, cat);

    // 3: QKV gemm (layer 0), 4: attention, 5: O-proj (ncu slot)
    gemm_fp16<<<dim3(18, 64), 128, GEMM_SMEM>>>(
        x16, wqkv16, sa_b_qkv, nullptr, qkv16, Mm, QKVS, Dd, 2);
    attn_flash<<<512, 256, FATT_SMEM>>>(qkv16, o16);
    gemm_fp16<<<dim3(6, 64), 128, GEMM_SMEM>>>(
        o16, wo16, sa_b_o, nullptr, y16, Mm, Dd, Dd, 2);

    // 6: batched cross-attn stage-2
    small_gemm_all<<<SGB, 256>>>(
        cat, Bb*Dd,
        ca_w_o, (size_t)Dd*Dd,
        ca_b_o, Dd, ca);

    for (int l = 0; l < Ll; ++l) {
        if (l > 0) {
            gemm_fp16<<<dim3(18, 64), 128, GEMM_SMEM>>>(
                x16, wqkv16 + (size_t)l*3*Dd*Dd, sa_b_qkv + (size_t)l*3*Dd,
                nullptr, qkv16, Mm, QKVS, Dd, 2);
            attn_flash<<<512, 256, FATT_SMEM>>>(qkv16, o16);
            gemm_fp16<<<dim3(6, 64), 128, GEMM_SMEM>>>(
                o16, wo16 + (size_t)l*Dd*Dd, sa_b_o + (size_t)l*Dd,
                nullptr, y16, Mm, Dd, Dd, 2);
        }
        add_ln2_kernel<<<Mm, 256>>>(x, y16, ca + l*Bb*Dd,
                                    ln1_g + (size_t)l*Dd, ln1_b + (size_t)l*Dd,
                                    ln2_g + (size_t)l*Dd, ln2_b + (size_t)l*Dd, x16);
        gemm_fp16<<<dim3(16, 64), 128, GEMM_SMEM>>>(
            x16, w116 + (size_t)l*Ff*Dd, ffn_b1 + (size_t)l*Ff,
            nullptr, h16, Mm, Ff, Dd, 1);
        gemm_fp16<<<dim3(6, 64), 128, GEMM_SMEM>>>(
            h16, w216 + (size_t)l*Dd*Ff, ffn_b2 + (size_t)l*Dd,
            nullptr, y16, Mm, Dd, Ff, 2);
        add_ln_kernel<<<Mm, 256>>>(x, y16, ln3_g + (size_t)l*Dd, ln3_b + (size_t)l*Dd,
                                   x16);
    }

    // output projection (fp32 out)
    gemm_fp16<<<dim3(1, 64), 128, GEMM_SMEM>>>(
        x16, wout16, out_b, (float*)d_out, nullptr, Mm, Vv, Dd, 0);
}

// round 10
// speedup vs baseline: 9.8206x; 1.0079x over previous
#include <cuda_runtime.h>
#include <cuda_fp16.h>
#include <stdint.h>
#include <math.h>

// Problem dims
#define Bb   16
#define Ss   512
#define Dd   768
#define Hh   8
#define Vv   100
#define Ff   2048
#define Ll   6
#define DHd  96
#define Mm   (Bb*Ss)   // 8192
#define QKVS (3*Dd)    // 2304

// ================= low-level helpers =================
__device__ __forceinline__ uint32_t smem_u32(const void* p) {
    return (uint32_t)__cvta_generic_to_shared(p);
}
__device__ __forceinline__ void cp_async16(uint32_t dst, const void* src, int szvalid) {
    asm volatile("cp.async.cg.shared.global [%0], [%1], 16, %2;"
                 :: "r"(dst), "l"(src), "r"(szvalid) : "memory");
}
#define CP_COMMIT() asm volatile("cp.async.commit_group;" ::: "memory")
#define CP_WAIT(n)  asm volatile("cp.async.wait_group %0;" :: "n"(n) : "memory")

__device__ __forceinline__ void ldm_x4(uint32_t* r, uint32_t addr) {
    asm volatile("ldmatrix.sync.aligned.m8n8.x4.shared.b16 {%0,%1,%2,%3}, [%4];"
                 : "=r"(r[0]), "=r"(r[1]), "=r"(r[2]), "=r"(r[3]) : "r"(addr));
}
__device__ __forceinline__ void ldm_trans_x4(uint32_t* r, uint32_t addr) {
    asm volatile("ldmatrix.sync.aligned.m8n8.x4.trans.shared.b16 {%0,%1,%2,%3}, [%4];"
                 : "=r"(r[0]), "=r"(r[1]), "=r"(r[2]), "=r"(r[3]) : "r"(addr));
}
__device__ __forceinline__ void mma16816(float* d, const uint32_t* a, const uint32_t* b) {
    asm volatile("mma.sync.aligned.m16n8k16.row.col.f32.f16.f16.f32 "
                 "{%0,%1,%2,%3}, {%4,%5,%6,%7}, {%8,%9}, {%0,%1,%2,%3};"
                 : "+f"(d[0]), "+f"(d[1]), "+f"(d[2]), "+f"(d[3])
                 : "r"(a[0]), "r"(a[1]), "r"(a[2]), "r"(a[3]), "r"(b[0]), "r"(b[1]));
}
__device__ __forceinline__ uint32_t pack_h2(float a, float b) {
    __half2 t = __floats2half2_rn(a, b);
    return *(uint32_t*)&t;
}
__device__ __forceinline__ float ex2(float x) {
    float y;
    asm("ex2.approx.f32 %0, %1;" : "=f"(y) : "f"(x));
    return y;
}

// ================= device scratch =================
__device__ float g_x   [Mm * Dd];
__device__ float g_cat [Ll * Bb * Dd];
__device__ float g_ca  [Ll * Bb * Dd];

__device__ __align__(16) __half g_x16 [Mm * Dd];
__device__ __align__(16) __half g_o16 [Mm * Dd];
__device__ __align__(16) __half g_y16 [Mm * Dd];
__device__ __align__(16) __half g_h16 [Mm * Ff];
__device__ __align__(16) __half g_qkv16[Mm * QKVS];

__device__ __align__(16) __half g_wqkv16[Ll*3*Dd*Dd];
__device__ __align__(16) __half g_wo16  [Ll*Dd*Dd];
__device__ __align__(16) __half g_w116  [Ll*Ff*Dd];
__device__ __align__(16) __half g_w216  [Ll*Dd*Ff];
__device__ __align__(16) __half g_wout16[Vv*Dd];

// ================= weight convert =================
__global__ __launch_bounds__(256) void convert_all(
    const float* __restrict__ s0, __half* __restrict__ d0, int b0,
    const float* __restrict__ s1, __half* __restrict__ d1, int b1,
    const float* __restrict__ s2, __half* __restrict__ d2, int b2,
    const float* __restrict__ s3, __half* __restrict__ d3, int b3,
    const float* __restrict__ s4, __half* __restrict__ d4, int b4)
{
    int bid = blockIdx.x;
    const float* src; __half* dst; int nb;
    if      (bid < b0)          { src = s0; dst = d0; nb = bid; }
    else if (bid < b0+b1)       { src = s1; dst = d1; nb = bid - b0; }
    else if (bid < b0+b1+b2)    { src = s2; dst = d2; nb = bid - b0 - b1; }
    else if (bid < b0+b1+b2+b3) { src = s3; dst = d3; nb = bid - b0 - b1 - b2; }
    else                        { src = s4; dst = d4; nb = bid - b0 - b1 - b2 - b3; }
    int i = (nb * 256 + threadIdx.x) * 4;
    float4 v = *(const float4*)&src[i];
    *(__half2*)&dst[i]     = __floats2half2_rn(v.x, v.y);
    *(__half2*)&dst[i + 2] = __floats2half2_rn(v.z, v.w);
}

// ================= embed =================
__global__ __launch_bounds__(256) void embed_kernel(
    const int* __restrict__ target, const float* __restrict__ tok,
    const float* __restrict__ pos, float* __restrict__ x,
    __half* __restrict__ x16)
{
    int row = blockIdx.x;
    int s   = row & (Ss - 1);
    int t   = target[row];
    const float* tp = tok + (size_t)t * Dd;
    const float* pp = pos + (size_t)s * Dd;
    size_t base = (size_t)row * Dd;
    for (int c = threadIdx.x; c < Dd; c += 256) {
        float v = tp[c] + pp[c];
        x[base + c] = v;
        x16[base + c] = __float2half(v);
    }
}

// ================= fp16 GEMM: CTA 128x128, 4 warps, 3-stage, 1 sync/chunk =======
// (UNCHANGED from round 8/9 — measured equilibrium, do not disturb)
#define BKc 32
#define APITCH 80
#define T128_B   (128*APITCH)
#define STAGE_B  (2*T128_B)
#define GEMM_SMEM (3*STAGE_B)

__global__ void __launch_bounds__(128, 3) gemm_fp16(
    const __half* __restrict__ A, const __half* __restrict__ W,
    const float* __restrict__ bias, float* __restrict__ C,
    __half* __restrict__ Ch,
    int M, int N, int K, int mode)
{
    extern __shared__ char sm[];
    const uint32_t smU = smem_u32(sm);
    const int tid  = threadIdx.x;
    const int lane = tid & 31;
    const int wid  = tid >> 5;
    const int bm   = blockIdx.y * 128;
    const int bn   = blockIdx.x * 128;
    const int wm   = (wid >> 1) * 64;
    const int wn   = (wid & 1) * 64;

    float acc[4][8][4];
    #pragma unroll
    for (int i = 0; i < 4; ++i)
        #pragma unroll
        for (int j = 0; j < 8; ++j)
            #pragma unroll
            for (int r = 0; r < 4; ++r) acc[i][j][r] = 0.f;

    const int NC = K / BKc;

    auto issue = [&](int chunk, int s) {
        const int k0 = chunk * BKc;
        #pragma unroll
        for (int i = 0; i < 4; ++i) {
            int c = tid + 128 * i;
            int row = c >> 2, c16 = c & 3;
            cp_async16(smU + s * STAGE_B + row * APITCH + c16 * 16,
                       (const char*)(A + (size_t)(bm + row) * K + k0) + c16 * 16, 16);
        }
        #pragma unroll
        for (int i = 0; i < 4; ++i) {
            int c = tid + 128 * i;
            int row = c >> 2, c16 = c & 3;
            int rn = bn + row;
            const char* g = (const char*)(W + (size_t)rn * K + k0) + c16 * 16;
            int sz = 16;
            if (rn >= N) { sz = 0; g = (const char*)W; }
            cp_async16(smU + s * STAGE_B + T128_B + row * APITCH + c16 * 16, g, sz);
        }
        CP_COMMIT();
    };

    const int wrow_off = ((lane >> 4) << 3) + (lane & 7);
    const int wcol_off = ((lane >> 3) & 1) * 8;
    const int arow_off = lane & 15;
    const int acol_off = (lane >> 4) << 3;

    auto compute = [&](int s) {
        const uint32_t aB = smU + s * STAGE_B;
        const uint32_t wB = aB + T128_B;
        #pragma unroll
        for (int ks = 0; ks < BKc; ks += 16) {
            uint32_t wh[4][4];
            #pragma unroll
            for (int nb = 0; nb < 4; ++nb)
                ldm_x4(wh[nb], wB + (wn + nb * 16 + wrow_off) * APITCH + (ks + wcol_off) * 2);
            #pragma unroll
            for (int mi = 0; mi < 4; ++mi) {
                uint32_t ah[4];
                ldm_x4(ah, aB + (wm + mi * 16 + arow_off) * APITCH + (ks + acol_off) * 2);
                #pragma unroll
                for (int nb = 0; nb < 4; ++nb) {
                    mma16816(&acc[mi][nb * 2][0],     ah, &wh[nb][0]);
                    mma16816(&acc[mi][nb * 2 + 1][0], ah, &wh[nb][2]);
                }
            }
        }
    };

    issue(0, 0);
    issue(1, 1);
    for (int c = 0; c < NC; ++c) {
        if (c + 1 < NC) { CP_WAIT(1); } else { CP_WAIT(0); }
        __syncthreads();
        if (c + 2 < NC) issue(c + 2, (c + 2) % 3);
        compute(c % 3);
    }

    float bs[16];
    #pragma unroll
    for (int nj = 0; nj < 8; ++nj) {
        int c0 = bn + wn + nj * 8 + (lane & 3) * 2;
        bs[nj * 2]     = (c0 < N)     ? bias[c0]     : 0.f;
        bs[nj * 2 + 1] = (c0 + 1 < N) ? bias[c0 + 1] : 0.f;
    }
    #pragma unroll
    for (int mi = 0; mi < 4; ++mi) {
        #pragma unroll
        for (int nj = 0; nj < 8; ++nj) {
            int c0 = bn + wn + nj * 8 + (lane & 3) * 2;
            if (c0 >= N) continue;
            #pragma unroll
            for (int p = 0; p < 2; ++p) {
                int row = bm + wm + mi * 16 + (lane >> 2) + p * 8;
                float v0 = acc[mi][nj][p * 2]     + bs[nj * 2];
                float v1 = acc[mi][nj][p * 2 + 1] + bs[nj * 2 + 1];
                if (mode == 0) {
                    *(float2*)(C + (size_t)row * N + c0) = make_float2(v0, v1);
                } else {
                    if (mode == 1) { v0 = fmaxf(v0, 0.f); v1 = fmaxf(v1, 0.f); }
                    *(__half2*)(Ch + (size_t)row * N + c0) = __floats2half2_rn(v0, v1);
                }
            }
        }
    }
}

// ================= batched tiny GEMM (all layers in one launch) =================
__global__ __launch_bounds__(256) void small_gemm_all(
    const float* __restrict__ A, int aStrideL,
    const float* __restrict__ W, size_t wStrideL,
    const float* __restrict__ bias, int biasStrideL,
    float* __restrict__ C)
{
    int wg   = blockIdx.x * 8 + (threadIdx.x >> 5);
    int lane = threadIdx.x & 31;
    if (wg >= Ll * Bb * Dd) return;
    int l  = wg / (Bb * Dd);
    int r  = wg - l * (Bb * Dd);
    int bq = r / Dd;
    int n  = r - bq * Dd;
    const float* a = A + (size_t)l * aStrideL + (size_t)bq * Dd;
    const float* w = W + (size_t)l * wStrideL + (size_t)n * Dd;
    float s = 0.f;
    #pragma unroll 4
    for (int k = lane; k < Dd; k += 32) s = fmaf(a[k], w[k], s);
    #pragma unroll
    for (int o = 16; o; o >>= 1) s += __shfl_xor_sync(0xffffffffu, s, o);
    if (lane == 0) C[wg] = s + bias[(size_t)l * biasStrideL + n];
}

// ================= add+LN (ln3): 2 rows per 256-thread block =================
__global__ __launch_bounds__(256) void add_ln_kernel(
    float* __restrict__ x, const __half* __restrict__ y16,
    const float* __restrict__ g, const float* __restrict__ b,
    __half* __restrict__ x16)
{
    const int tid = threadIdx.x;
    const int grp = tid >> 7;            // 0/1: which row
    const int t   = tid & 127;
    const int row = blockIdx.x * 2 + grp;
    const __half* yp = y16 + (size_t)row * Dd;
    float* xp = x + (size_t)row * Dd;
    __shared__ float sh1[2][4], sh2[2][4];
    const int w4   = (tid >> 5) & 3;     // warp within group
    const int lane = tid & 31;

    float v[6];
    float sum = 0.f, sq = 0.f;
    #pragma unroll
    for (int i = 0; i < 6; ++i) {
        int c = t + i * 128;
        float tt = xp[c] + __half2float(yp[c]);
        v[i] = tt; sum += tt; sq = fmaf(tt, tt, sq);
    }
    #pragma unroll
    for (int o = 16; o; o >>= 1) {
        sum += __shfl_xor_sync(0xffffffffu, sum, o);
        sq  += __shfl_xor_sync(0xffffffffu, sq,  o);
    }
    if (lane == 0) { sh1[grp][w4] = sum; sh2[grp][w4] = sq; }
    __syncthreads();
    if (t == 0) {
        float a = 0.f, c2 = 0.f;
        #pragma unroll
        for (int i = 0; i < 4; ++i) { a += sh1[grp][i]; c2 += sh2[grp][i]; }
        sh1[grp][0] = a; sh2[grp][0] = c2;
    }
    __syncthreads();
    float mu  = sh1[grp][0] * (1.f / Dd);
    float var = sh2[grp][0] * (1.f / Dd) - mu * mu;
    float rs  = rsqrtf(var + 1e-5f);
    #pragma unroll
    for (int i = 0; i < 6; ++i) {
        int c = t + i * 128;
        float o = (v[i] - mu) * rs * g[c] + b[c];
        xp[c] = o;
        x16[(size_t)row * Dd + c] = __float2half(o);
    }
}

// ================= fused (add+LN1)+(add bcast+LN2): 2 rows per block ===========
__global__ __launch_bounds__(256) void add_ln2_kernel(
    float* __restrict__ x, const __half* __restrict__ y16,
    const float* __restrict__ ca,
    const float* __restrict__ g1, const float* __restrict__ b1,
    const float* __restrict__ g2, const float* __restrict__ b2,
    __half* __restrict__ x16)
{
    const int tid = threadIdx.x;
    const int grp = tid >> 7;
    const int t   = tid & 127;
    const int row = blockIdx.x * 2 + grp;
    const __half* yp  = y16 + (size_t)row * Dd;
    const float* cap  = ca  + (size_t)(row >> 9) * Dd;
    float* xp = x + (size_t)row * Dd;
    __shared__ float sh1[2][4], sh2[2][4];
    const int w4   = (tid >> 5) & 3;
    const int lane = tid & 31;

    float v[6];
    float sum = 0.f, sq = 0.f;
    #pragma unroll
    for (int i = 0; i < 6; ++i) {
        int c = t + i * 128;
        float tt = xp[c] + __half2float(yp[c]);
        v[i] = tt; sum += tt; sq = fmaf(tt, tt, sq);
    }
    #pragma unroll
    for (int o = 16; o; o >>= 1) {
        sum += __shfl_xor_sync(0xffffffffu, sum, o);
        sq  += __shfl_xor_sync(0xffffffffu, sq,  o);
    }
    if (lane == 0) { sh1[grp][w4] = sum; sh2[grp][w4] = sq; }
    __syncthreads();
    if (t == 0) {
        float a = 0.f, c2 = 0.f;
        #pragma unroll
        for (int i = 0; i < 4; ++i) { a += sh1[grp][i]; c2 += sh2[grp][i]; }
        sh1[grp][0] = a; sh2[grp][0] = c2;
    }
    __syncthreads();
    float mu = sh1[grp][0] * (1.f / Dd);
    float rs = rsqrtf(sh2[grp][0] * (1.f / Dd) - mu * mu + 1e-5f);
    __syncthreads();

    // second add + LN
    sum = 0.f; sq = 0.f;
    #pragma unroll
    for (int i = 0; i < 6; ++i) {
        int c = t + i * 128;
        float tt = (v[i] - mu) * rs * g1[c] + b1[c] + cap[c];
        v[i] = tt; sum += tt; sq = fmaf(tt, tt, sq);
    }
    #pragma unroll
    for (int o = 16; o; o >>= 1) {
        sum += __shfl_xor_sync(0xffffffffu, sum, o);
        sq  += __shfl_xor_sync(0xffffffffu, sq,  o);
    }
    if (lane == 0) { sh1[grp][w4] = sum; sh2[grp][w4] = sq; }
    __syncthreads();
    if (t == 0) {
        float a = 0.f, c2 = 0.f;
        #pragma unroll
        for (int i = 0; i < 4; ++i) { a += sh1[grp][i]; c2 += sh2[grp][i]; }
        sh1[grp][0] = a; sh2[grp][0] = c2;
    }
    __syncthreads();
    float mu2 = sh1[grp][0] * (1.f / Dd);
    float rs2 = rsqrtf(sh2[grp][0] * (1.f / Dd) - mu2 * mu2 + 1e-5f);
    #pragma unroll
    for (int i = 0; i < 6; ++i) {
        int c = t + i * 128;
        float o = (v[i] - mu2) * rs2 * g2[c] + b2[c];
        xp[c] = o;
        x16[(size_t)row * Dd + c] = __float2half(o);
    }
}

// ================= flash-attention: base-2 softmax + vote-skip rescale ==========
#define FATT_SMEM 66560
#define QPITCH 208

__global__ void __launch_bounds__(256) attn_flash(
    const __half* __restrict__ qkv, __half* __restrict__ o16)
{
    extern __shared__ char smd[];
    const int bid  = blockIdx.x;
    const int qidx = (Ss/128 - 1) - (bid >> 7);   // longest blocks first
    const int rem  = bid & 127;
    const int h    = rem >> 4;
    const int b    = rem & 15;
    const int qb   = qidx * 128;
    const int tid  = threadIdx.x;
    const int lane = tid & 31;
    const int wid  = tid >> 5;
    const uint32_t sQ  = smem_u32(smd);
    const uint32_t sKV = sQ + 26624;
    // base-2 softmax: pre-fold log2(e) into the score scale
    const float scale2 = rsqrtf((float)DHd) * 1.4426950408889634f;

    #pragma unroll
    for (int i = 0; i < 6; ++i) {
        int c = tid + 256 * i;
        int row = c / 12, dc = c - row * 12;
        cp_async16(sQ + row * QPITCH + dc * 16,
                   qkv + (size_t)(b * Ss + qb + row) * QKVS + h * DHd + dc * 8, 16);
    }
    CP_COMMIT();

    auto load_kv = [&](int jt, int s) {
        #pragma unroll
        for (int i = 0; i < 3; ++i) {
            int c = tid + 256 * i;
            int kv = (c >= 384) ? 1 : 0;
            int cc = c - kv * 384;
            int row = cc / 12, dc = cc - row * 12;
            cp_async16(sKV + s * 13312 + kv * 6656 + row * QPITCH + dc * 16,
                       qkv + (size_t)(b * Ss + jt + row) * QKVS + (1 + kv) * Dd
                           + h * DHd + dc * 8, 16);
        }
        CP_COMMIT();
    };

    const int ntiles  = (qb + 128) / 32;   // >= 4 always
    load_kv(0, 0);
    load_kv(32, 1);
    CP_WAIT(2);
    __syncthreads();

    uint32_t qf[6][4];
    {
        uint32_t base = sQ + (wid * 16 + (lane & 15)) * QPITCH + ((lane >> 4) << 3) * 2;
        #pragma unroll
        for (int ks = 0; ks < 6; ++ks)
            ldm_x4(qf[ks], base + ks * 32);
    }

    float oacc[12][4];
    #pragma unroll
    for (int i = 0; i < 12; ++i)
        #pragma unroll
        for (int r = 0; r < 4; ++r) oacc[i][r] = 0.f;
    float m0 = -1e30f, m1 = -1e30f, l0 = 0.f, l1 = 0.f;

    const int my_last = qb + wid * 16 + 15;
    const int r0g     = qb + wid * 16 + (lane >> 2);

    for (int t = 0; t < ntiles; ++t) {
        const int jt = t * 32;
        if (t + 1 < ntiles) { CP_WAIT(1); } else { CP_WAIT(0); }
        __syncthreads();
        if (t + 2 < ntiles) load_kv((t + 2) * 32, (t + 2) % 3);

        if (jt <= my_last) {
            const uint32_t kb = sKV + (t % 3) * 13312;
            const uint32_t vb = kb + 6656;

            float sacc[4][4];
            #pragma unroll
            for (int i = 0; i < 4; ++i)
                #pragma unroll
                for (int r = 0; r < 4; ++r) sacc[i][r] = 0.f;
            const uint32_t kbase = kb + ((lane & 7) + ((lane >> 4) << 3)) * QPITCH
                                 + (((lane >> 3) & 1) << 4);
            #pragma unroll
            for (int ks = 0; ks < 6; ++ks) {
                uint32_t kf[4], kg[4];
                ldm_x4(kf, kbase + ks * 32);
                ldm_x4(kg, kbase + 16 * QPITCH + ks * 32);
                mma16816(sacc[0], qf[ks], &kf[0]);
                mma16816(sacc[1], qf[ks], &kf[2]);
                mma16816(sacc[2], qf[ks], &kg[0]);
                mma16816(sacc[3], qf[ks], &kg[2]);
            }

            #pragma unroll
            for (int nb = 0; nb < 4; ++nb)
                #pragma unroll
                for (int e = 0; e < 4; ++e) {
                    int j = jt + nb * 8 + (lane & 3) * 2 + (e & 1);
                    int r = r0g + ((e >> 1) << 3);
                    float v = sacc[nb][e] * scale2;
                    sacc[nb][e] = (j <= r) ? v : -1e30f;
                }

            float mx0 = -1e30f, mx1 = -1e30f;
            #pragma unroll
            for (int nb = 0; nb < 4; ++nb) {
                mx0 = fmaxf(mx0, fmaxf(sacc[nb][0], sacc[nb][1]));
                mx1 = fmaxf(mx1, fmaxf(sacc[nb][2], sacc[nb][3]));
            }
            mx0 = fmaxf(mx0, __shfl_xor_sync(0xffffffffu, mx0, 1));
            mx0 = fmaxf(mx0, __shfl_xor_sync(0xffffffffu, mx0, 2));
            mx1 = fmaxf(mx1, __shfl_xor_sync(0xffffffffu, mx1, 1));
            mx1 = fmaxf(mx1, __shfl_xor_sync(0xffffffffu, mx1, 2));
            float mn0 = fmaxf(m0, mx0), mn1 = fmaxf(m1, mx1);

            // rescale only if any lane's running max changed (skip is exact: f==1)
            if (__any_sync(0xffffffffu, (mn0 > m0) || (mn1 > m1))) {
                float f0 = ex2(m0 - mn0), f1 = ex2(m1 - mn1);
                l0 *= f0; l1 *= f1;
                #pragma unroll
                for (int c6 = 0; c6 < 12; ++c6) {
                    oacc[c6][0] *= f0; oacc[c6][1] *= f0;
                    oacc[c6][2] *= f1; oacc[c6][3] *= f1;
                }
            }
            m0 = mn0; m1 = mn1;

            float s0 = 0.f, s1 = 0.f;
            #pragma unroll
            for (int nb = 0; nb < 4; ++nb) {
                float p0 = ex2(sacc[nb][0] - mn0);
                float p1 = ex2(sacc[nb][1] - mn0);
                float p2 = ex2(sacc[nb][2] - mn1);
                float p3 = ex2(sacc[nb][3] - mn1);
                sacc[nb][0] = p0; sacc[nb][1] = p1;
                sacc[nb][2] = p2; sacc[nb][3] = p3;
                s0 += p0 + p1; s1 += p2 + p3;
            }
            s0 += __shfl_xor_sync(0xffffffffu, s0, 1);
            s0 += __shfl_xor_sync(0xffffffffu, s0, 2);
            s1 += __shfl_xor_sync(0xffffffffu, s1, 1);
            s1 += __shfl_xor_sync(0xffffffffu, s1, 2);
            l0 += s0;
            l1 += s1;

            uint32_t pa[2][4];
            #pragma unroll
            for (int kk = 0; kk < 2; ++kk) {
                pa[kk][0] = pack_h2(sacc[kk*2][0],   sacc[kk*2][1]);
                pa[kk][1] = pack_h2(sacc[kk*2][2],   sacc[kk*2][3]);
                pa[kk][2] = pack_h2(sacc[kk*2+1][0], sacc[kk*2+1][1]);
                pa[kk][3] = pack_h2(sacc[kk*2+1][2], sacc[kk*2+1][3]);
            }

            const uint32_t vrow = vb + ((lane & 7) + (((lane >> 3) & 1) << 3)) * QPITCH;
            #pragma unroll
            for (int kk = 0; kk < 2; ++kk) {
                #pragma unroll
                for (int c6 = 0; c6 < 6; ++c6) {
                    uint32_t vf[4];
                    ldm_trans_x4(vf, vrow + kk * 16 * QPITCH
                                     + (c6 * 16 + ((lane >> 4) << 3)) * 2);
                    mma16816(oacc[c6 * 2],     pa[kk], &vf[0]);
                    mma16816(oacc[c6 * 2 + 1], pa[kk], &vf[2]);
                }
            }
        }
    }

    float il0 = 1.f / l0, il1 = 1.f / l1;
    #pragma unroll
    for (int c6 = 0; c6 < 12; ++c6) {
        int col = h * DHd + c6 * 8 + (lane & 3) * 2;
        *(__half2*)(o16 + (size_t)(b * Ss + r0g) * Dd + col) =
            __floats2half2_rn(oacc[c6][0] * il0, oacc[c6][1] * il0);
        *(__half2*)(o16 + (size_t)(b * Ss + r0g + 8) * Dd + col) =
            __floats2half2_rn(oacc[c6][2] * il1, oacc[c6][3] * il1);
    }
}

// ================= launcher =================
extern "C" void kernel_launch(void* const* d_in, const int* in_sizes, int n_in,
                              void* d_out, int out_size)
{
    (void)in_sizes; (void)n_in; (void)out_size;
    const float* latent   = (const float*)d_in[0];
    const int*   target   = (const int*)  d_in[1];
    const float* tok_emb  = (const float*)d_in[2];
    const float* pos_emb  = (const float*)d_in[3];
    const float* sa_w_qkv = (const float*)d_in[4];
    const float* sa_b_qkv = (const float*)d_in[5];
    const float* sa_w_o   = (const float*)d_in[6];
    const float* sa_b_o   = (const float*)d_in[7];
    const float* ca_w_qkv = (const float*)d_in[8];
    const float* ca_b_qkv = (const float*)d_in[9];
    const float* ca_w_o   = (const float*)d_in[10];
    const float* ca_b_o   = (const float*)d_in[11];
    const float* ffn_w1   = (const float*)d_in[12];
    const float* ffn_b1   = (const float*)d_in[13];
    const float* ffn_w2   = (const float*)d_in[14];
    const float* ffn_b2   = (const float*)d_in[15];
    const float* ln1_g    = (const float*)d_in[16];
    const float* ln1_b    = (const float*)d_in[17];
    const float* ln2_g    = (const float*)d_in[18];
    const float* ln2_b    = (const float*)d_in[19];
    const float* ln3_g    = (const float*)d_in[20];
    const float* ln3_b    = (const float*)d_in[21];
    const float* out_w    = (const float*)d_in[22];
    const float* out_b    = (const float*)d_in[23];

    float *x, *cat, *ca;
    __half *x16, *o16, *y16, *h16, *qkv16, *wqkv16, *wo16, *w116, *w216, *wout16;
    cudaGetSymbolAddress((void**)&x,   g_x);
    cudaGetSymbolAddress((void**)&cat, g_cat);
    cudaGetSymbolAddress((void**)&ca,  g_ca);
    cudaGetSymbolAddress((void**)&x16, g_x16);
    cudaGetSymbolAddress((void**)&o16, g_o16);
    cudaGetSymbolAddress((void**)&y16, g_y16);
    cudaGetSymbolAddress((void**)&h16, g_h16);
    cudaGetSymbolAddress((void**)&qkv16, g_qkv16);
    cudaGetSymbolAddress((void**)&wqkv16, g_wqkv16);
    cudaGetSymbolAddress((void**)&wo16,   g_wo16);
    cudaGetSymbolAddress((void**)&w116,   g_w116);
    cudaGetSymbolAddress((void**)&w216,   g_w216);
    cudaGetSymbolAddress((void**)&wout16, g_wout16);

    cudaFuncSetAttribute(gemm_fp16,  cudaFuncAttributeMaxDynamicSharedMemorySize, GEMM_SMEM);
    cudaFuncSetAttribute(attn_flash, cudaFuncAttributeMaxDynamicSharedMemorySize, FATT_SMEM);

    // 0: weight conversions
    const int nb0 = (Ll*3*Dd*Dd) / 1024, nb1 = (Ll*Dd*Dd) / 1024,
              nb2 = (Ll*Ff*Dd) / 1024,   nb3 = (Ll*Dd*Ff) / 1024,
              nb4 = (Vv*Dd) / 1024;
    convert_all<<<nb0 + nb1 + nb2 + nb3 + nb4, 256>>>(
        sa_w_qkv, wqkv16, nb0, sa_w_o, wo16, nb1,
        ffn_w1, w116, nb2, ffn_w2, w216, nb3, out_w, wout16, nb4);

    // 1: embed
    embed_kernel<<<Mm, 256>>>(target, tok_emb, pos_emb, x, x16);

    // 2: batched cross-attn stage-1
    const int SGB = (Ll * Bb * Dd) / 8;
    small_gemm_all<<<SGB, 256>>>(
        latent, 0,
        ca_w_qkv + (size_t)2*Dd*Dd, (size_t)3*Dd*Dd,
        ca_b_qkv + 2*Dd, 3*Dd, cat);

    // 3: QKV gemm (layer 0), 4: attention, 5: O-proj (ncu slot)
    gemm_fp16<<<dim3(18, 64), 128, GEMM_SMEM>>>(
        x16, wqkv16, sa_b_qkv, nullptr, qkv16, Mm, QKVS, Dd, 2);
    attn_flash<<<512, 256, FATT_SMEM>>>(qkv16, o16);
    gemm_fp16<<<dim3(6, 64), 128, GEMM_SMEM>>>(
        o16, wo16, sa_b_o, nullptr, y16, Mm, Dd, Dd, 2);

    // 6: batched cross-attn stage-2
    small_gemm_all<<<SGB, 256>>>(
        cat, Bb*Dd,
        ca_w_o, (size_t)Dd*Dd,
        ca_b_o, Dd, ca);

    for (int l = 0; l < Ll; ++l) {
        if (l > 0) {
            gemm_fp16<<<dim3(18, 64), 128, GEMM_SMEM>>>(
                x16, wqkv16 + (size_t)l*3*Dd*Dd, sa_b_qkv + (size_t)l*3*Dd,
                nullptr, qkv16, Mm, QKVS, Dd, 2);
            attn_flash<<<512, 256, FATT_SMEM>>>(qkv16, o16);
            gemm_fp16<<<dim3(6, 64), 128, GEMM_SMEM>>>(
                o16, wo16 + (size_t)l*Dd*Dd, sa_b_o + (size_t)l*Dd,
                nullptr, y16, Mm, Dd, Dd, 2);
        }
        add_ln2_kernel<<<Mm/2, 256>>>(x, y16, ca + l*Bb*Dd,
                                      ln1_g + (size_t)l*Dd, ln1_b + (size_t)l*Dd,
                                      ln2_g + (size_t)l*Dd, ln2_b + (size_t)l*Dd, x16);
        gemm_fp16<<<dim3(16, 64), 128, GEMM_SMEM>>>(
            x16, w116 + (size_t)l*Ff*Dd, ffn_b1 + (size_t)l*Ff,
            nullptr, h16, Mm, Ff, Dd, 1);
        gemm_fp16<<<dim3(6, 64), 128, GEMM_SMEM>>>(
            h16, w216 + (size_t)l*Dd*Ff, ffn_b2 + (size_t)l*Dd,
            nullptr, y16, Mm, Dd, Ff, 2);
        add_ln_kernel<<<Mm/2, 256>>>(x, y16, ln3_g + (size_t)l*Dd, ln3_b + (size_t)l*Dd,
                                     x16);
    }

    // output projection (fp32 out)
    gemm_fp16<<<dim3(1, 64), 128, GEMM_SMEM>>>(
        x16, wout16, out_b, (float*)d_out, nullptr, Mm, Vv, Dd, 0);
}